// round 1
// baseline (speedup 1.0000x reference)
#include <cuda_runtime.h>
#include <math.h>

#define BATCH 8
#define SEQ 1024
#define DMODEL 768
#define NHEAD 12
#define HDIM 64
#define MROWS (BATCH*SEQ)
#define APAD 68   // padded row stride (floats) for 64-wide attention tiles

// Scratch (allocation-free rule: __device__ globals)
__device__ float g_q[MROWS*DMODEL];     // [B,H,S,DH]
__device__ float g_k[MROWS*DMODEL];     // [B,H,S,DH]
__device__ float g_v[MROWS*DMODEL];     // [B,H,S,DH]
__device__ float g_attn[MROWS*DMODEL];  // [B,S,D]

// ---------------------------------------------------------------------------
// GEMM: C[M,N] = A[M,K] * W[K,N] + bias.  M=8192, N=K=768.
// 128x128 block tile, BK=16, 256 threads, 8x8 per thread.
// MODE 1/2/3: A=x, C=g_q/g_k/g_v written in [B,H,S,DH] layout.
// MODE 4:     A=g_attn, C=out (plain [M,N]).
// ---------------------------------------------------------------------------
template<int MODE>
__global__ void __launch_bounds__(256) gemm_kernel(const float* __restrict__ Ain,
                                                   const float* __restrict__ W,
                                                   const float* __restrict__ bias,
                                                   float* __restrict__ Cout)
{
    constexpr int N = DMODEL, K = DMODEL;
    const float* A = (MODE == 4) ? g_attn : Ain;
    float* C = (MODE == 1) ? g_q : (MODE == 2) ? g_k : (MODE == 3) ? g_v : Cout;

    __shared__ float As[16][136];  // transposed: As[k][m], 136 pad keeps f4 align + low conflicts
    __shared__ float Bs[16][136];  // natural:    Bs[k][n]

    const int bm = blockIdx.x * 128;
    const int bn = blockIdx.y * 128;
    const int t  = threadIdx.x;
    const int tx = t & 15, ty = t >> 4;
    const int a_k4 = t & 3,  a_m = t >> 2;   // A load: 1 float4 along k, rows a_m, a_m+64
    const int b_n4 = t & 31, b_k = t >> 5;   // B load: 1 float4 along n, rows b_k, b_k+8

    float acc[8][8] = {};

    for (int k0 = 0; k0 < K; k0 += 16) {
        #pragma unroll
        for (int i = 0; i < 2; i++) {
            const int m = a_m + 64*i;
            float4 v = *reinterpret_cast<const float4*>(&A[(size_t)(bm + m)*K + k0 + a_k4*4]);
            As[a_k4*4+0][m] = v.x;
            As[a_k4*4+1][m] = v.y;
            As[a_k4*4+2][m] = v.z;
            As[a_k4*4+3][m] = v.w;
        }
        #pragma unroll
        for (int i = 0; i < 2; i++) {
            const int kr = b_k + 8*i;
            *reinterpret_cast<float4*>(&Bs[kr][b_n4*4]) =
                *reinterpret_cast<const float4*>(&W[(size_t)(k0 + kr)*N + bn + b_n4*4]);
        }
        __syncthreads();

        #pragma unroll
        for (int kk = 0; kk < 16; kk++) {
            float a[8], b[8];
            *reinterpret_cast<float4*>(&a[0]) = *reinterpret_cast<const float4*>(&As[kk][ty*4]);
            *reinterpret_cast<float4*>(&a[4]) = *reinterpret_cast<const float4*>(&As[kk][ty*4 + 64]);
            *reinterpret_cast<float4*>(&b[0]) = *reinterpret_cast<const float4*>(&Bs[kk][tx*4]);
            *reinterpret_cast<float4*>(&b[4]) = *reinterpret_cast<const float4*>(&Bs[kk][tx*4 + 64]);
            #pragma unroll
            for (int ii = 0; ii < 8; ii++)
                #pragma unroll
                for (int jj = 0; jj < 8; jj++)
                    acc[ii][jj] = fmaf(a[ii], b[jj], acc[ii][jj]);
        }
        __syncthreads();
    }

    // Epilogue: bias + store (float4)
    #pragma unroll
    for (int ii = 0; ii < 8; ii++) {
        const int m = bm + ((ii < 4) ? 0 : 64) + ty*4 + (ii & 3);
        #pragma unroll
        for (int j4 = 0; j4 < 2; j4++) {
            const int n = bn + j4*64 + tx*4;
            float4 v;
            v.x = acc[ii][j4*4+0] + bias[n+0];
            v.y = acc[ii][j4*4+1] + bias[n+1];
            v.z = acc[ii][j4*4+2] + bias[n+2];
            v.w = acc[ii][j4*4+3] + bias[n+3];
            if (MODE == 0 || MODE == 4) {
                *reinterpret_cast<float4*>(&C[(size_t)m*N + n]) = v;
            } else {
                // [B,S,D] row/col -> [B,H,S,DH]
                const int b_ = m >> 10;          // m / SEQ
                const int s  = m & (SEQ - 1);
                const int h_ = n >> 6;           // n / HDIM  (128-wide tile spans 2 heads)
                *reinterpret_cast<float4*>(
                    &C[(size_t)(((b_*NHEAD) + h_)*SEQ + s)*HDIM + (n & 63)]) = v;
            }
        }
    }
}

// ---------------------------------------------------------------------------
// Flash attention: one block per (64-query tile, b*H+h). 256 threads (16x16),
// 4x4 scores/outputs per thread. Streams 16 key tiles with online softmax.
// All smem tiles [64][APAD] so float4 accesses are conflict-free.
// ---------------------------------------------------------------------------
__global__ void __launch_bounds__(256) attn_kernel()
{
    extern __shared__ float sm[];
    float* Qs   = sm;                 // [64][APAD] pre-scaled Q
    float* Ks   = Qs + 64*APAD;       // [64][APAD]
    float* Vs   = Ks + 64*APAD;       // [64][APAD]
    float* P    = Vs + 64*APAD;       // [64][APAD] scores -> probs
    float* m_s  = P  + 64*APAD;       // [64] running max
    float* l_s  = m_s + 64;           // [64] running denom
    float* corr = l_s + 64;           // [64] per-tile correction

    const int t    = threadIdx.x;
    const int tx   = t & 15, ty = t >> 4;
    const int lane = t & 31, warp = t >> 5;
    const int qt   = blockIdx.x;      // query tile
    const int bh   = blockIdx.y;      // b*NHEAD + h

    const float* Qg = g_q + ((size_t)bh*SEQ + qt*64)*HDIM;
    const float* Kg = g_k + (size_t)bh*SEQ*HDIM;
    const float* Vg = g_v + (size_t)bh*SEQ*HDIM;

    for (int i = t; i < 64*16; i += 256) {
        const int s = i >> 4, d4 = i & 15;
        float4 v = *reinterpret_cast<const float4*>(&Qg[s*HDIM + d4*4]);
        v.x *= 0.125f; v.y *= 0.125f; v.z *= 0.125f; v.w *= 0.125f;  // 1/sqrt(64)
        *reinterpret_cast<float4*>(&Qs[s*APAD + d4*4]) = v;
    }
    if (t < 64) { m_s[t] = -1e30f; l_s[t] = 0.0f; }
    float o[4][4] = {};
    __syncthreads();

    for (int kt = 0; kt < SEQ/64; kt++) {
        const float* Kp = Kg + (size_t)kt*64*HDIM;
        const float* Vp = Vg + (size_t)kt*64*HDIM;
        for (int i = t; i < 64*16; i += 256) {
            const int s = i >> 4, d4 = i & 15;
            *reinterpret_cast<float4*>(&Ks[s*APAD + d4*4]) =
                *reinterpret_cast<const float4*>(&Kp[s*HDIM + d4*4]);
            *reinterpret_cast<float4*>(&Vs[s*APAD + d4*4]) =
                *reinterpret_cast<const float4*>(&Vp[s*HDIM + d4*4]);
        }
        __syncthreads();

        // S = Q * K^T (both row-major, dot along contiguous d, float4 chunks)
        float sacc[4][4] = {};
        #pragma unroll
        for (int d4 = 0; d4 < 16; d4++) {
            float4 q4[4], k4[4];
            #pragma unroll
            for (int i = 0; i < 4; i++)
                q4[i] = *reinterpret_cast<const float4*>(&Qs[(ty*4+i)*APAD + d4*4]);
            #pragma unroll
            for (int j = 0; j < 4; j++)
                k4[j] = *reinterpret_cast<const float4*>(&Ks[(tx*4+j)*APAD + d4*4]);
            #pragma unroll
            for (int i = 0; i < 4; i++)
                #pragma unroll
                for (int j = 0; j < 4; j++)
                    sacc[i][j] += q4[i].x*k4[j].x + q4[i].y*k4[j].y
                                + q4[i].z*k4[j].z + q4[i].w*k4[j].w;
        }
        #pragma unroll
        for (int i = 0; i < 4; i++) {
            float4 v = make_float4(sacc[i][0], sacc[i][1], sacc[i][2], sacc[i][3]);
            *reinterpret_cast<float4*>(&P[(ty*4+i)*APAD + tx*4]) = v;
        }
        __syncthreads();

        // Online softmax: each warp owns 8 rows, lane covers 2 of 64 cols.
        #pragma unroll
        for (int r8 = 0; r8 < 8; r8++) {
            const int r = warp*8 + r8;
            float v0 = P[r*APAD + lane];
            float v1 = P[r*APAD + 32 + lane];
            float mx = fmaxf(v0, v1);
            #pragma unroll
            for (int off = 16; off; off >>= 1)
                mx = fmaxf(mx, __shfl_xor_sync(0xffffffffu, mx, off));
            const float m_old = m_s[r];
            const float m_new = fmaxf(m_old, mx);
            const float p0 = __expf(v0 - m_new);
            const float p1 = __expf(v1 - m_new);
            P[r*APAD + lane]      = p0;
            P[r*APAD + 32 + lane] = p1;
            float sum = p0 + p1;
            #pragma unroll
            for (int off = 16; off; off >>= 1)
                sum += __shfl_xor_sync(0xffffffffu, sum, off);
            if (lane == 0) {
                const float cr = __expf(m_old - m_new);
                l_s[r]  = l_s[r]*cr + sum;
                m_s[r]  = m_new;
                corr[r] = cr;
            }
        }
        __syncthreads();

        // O = O*corr + P @ V
        #pragma unroll
        for (int i = 0; i < 4; i++) {
            const float cr = corr[ty*4+i];
            #pragma unroll
            for (int j = 0; j < 4; j++) o[i][j] *= cr;
        }
        #pragma unroll
        for (int k4 = 0; k4 < 16; k4++) {
            float4 vv[4];
            #pragma unroll
            for (int u = 0; u < 4; u++)
                vv[u] = *reinterpret_cast<const float4*>(&Vs[(k4*4+u)*APAD + tx*4]);
            #pragma unroll
            for (int i = 0; i < 4; i++) {
                float4 p = *reinterpret_cast<const float4*>(&P[(ty*4+i)*APAD + k4*4]);
                o[i][0] += p.x*vv[0].x + p.y*vv[1].x + p.z*vv[2].x + p.w*vv[3].x;
                o[i][1] += p.x*vv[0].y + p.y*vv[1].y + p.z*vv[2].y + p.w*vv[3].y;
                o[i][2] += p.x*vv[0].z + p.y*vv[1].z + p.z*vv[2].z + p.w*vv[3].z;
                o[i][3] += p.x*vv[0].w + p.y*vv[1].w + p.z*vv[2].w + p.w*vv[3].w;
            }
        }
        __syncthreads();
    }

    // Normalize and write merged-head layout [B,S,D]
    const int b_ = bh / NHEAD, h_ = bh % NHEAD;
    #pragma unroll
    for (int i = 0; i < 4; i++) {
        const int r = ty*4 + i;
        const float inv = 1.0f / l_s[r];
        const size_t row = (size_t)b_*SEQ + qt*64 + r;
        float4 v = make_float4(o[i][0]*inv, o[i][1]*inv, o[i][2]*inv, o[i][3]*inv);
        *reinterpret_cast<float4*>(&g_attn[row*DMODEL + h_*HDIM + tx*4]) = v;
    }
}

// ---------------------------------------------------------------------------
extern "C" void kernel_launch(void* const* d_in, const int* in_sizes, int n_in,
                              void* d_out, int out_size)
{
    (void)in_sizes; (void)n_in; (void)out_size;
    const float* x  = (const float*)d_in[0];
    const float* Wq = (const float*)d_in[1];
    const float* bq = (const float*)d_in[2];
    const float* Wk = (const float*)d_in[3];
    const float* bk = (const float*)d_in[4];
    const float* Wv = (const float*)d_in[5];
    const float* bv = (const float*)d_in[6];
    const float* Wo = (const float*)d_in[7];
    const float* bo = (const float*)d_in[8];
    float* out = (float*)d_out;

    dim3 gg(MROWS/128, DMODEL/128);   // (64, 6)
    gemm_kernel<1><<<gg, 256>>>(x, Wq, bq, nullptr);
    gemm_kernel<2><<<gg, 256>>>(x, Wk, bk, nullptr);
    gemm_kernel<3><<<gg, 256>>>(x, Wv, bv, nullptr);

    const int smem_bytes = (4*64*APAD + 192) * (int)sizeof(float);  // 70,400 B
    cudaFuncSetAttribute(attn_kernel, cudaFuncAttributeMaxDynamicSharedMemorySize, smem_bytes);
    attn_kernel<<<dim3(SEQ/64, BATCH*NHEAD), 256, smem_bytes>>>();

    gemm_kernel<4><<<gg, 256>>>(nullptr, Wo, bo, out);
}

// round 2
// speedup vs baseline: 1.1635x; 1.1635x over previous
#include <cuda_runtime.h>
#include <math.h>
#include <stdint.h>

#define BATCH 8
#define SEQ 1024
#define DMODEL 768
#define NHEAD 12
#define HDIM 64
#define MROWS (BATCH*SEQ)

// Scratch (__device__ globals: allocation-free rule)
__device__ float g_q[MROWS*DMODEL];     // [B,H,S,DH]
__device__ float g_k[MROWS*DMODEL];     // [B,H,S,DH]
__device__ float g_v[MROWS*DMODEL];     // [B,H,S,DH]
__device__ float g_attn[MROWS*DMODEL];  // [B,S,D]

// ---------------------------------------------------------------------------
// tf32 helpers
// ---------------------------------------------------------------------------
__device__ __forceinline__ float tf32_rna(float x) {
    float r; asm("cvt.rna.tf32.f32 %0, %1;" : "=f"(r) : "f"(x)); return r;
}
__device__ __forceinline__ void split2(float x, float& h, float& l) {
    h = tf32_rna(x);
    l = tf32_rna(x - h);     // x - h exact in fp32
}
// D += A(16x8,row) * B(8x8,col)  tf32
__device__ __forceinline__ void mma8(float c[4], const float a[4], const float b[2]) {
    asm volatile("mma.sync.aligned.m16n8k8.row.col.f32.tf32.tf32.f32 "
        "{%0,%1,%2,%3}, {%4,%5,%6,%7}, {%8,%9}, {%0,%1,%2,%3};"
        : "+f"(c[0]), "+f"(c[1]), "+f"(c[2]), "+f"(c[3])
        : "r"(__float_as_uint(a[0])), "r"(__float_as_uint(a[1])),
          "r"(__float_as_uint(a[2])), "r"(__float_as_uint(a[3])),
          "r"(__float_as_uint(b[0])), "r"(__float_as_uint(b[1])));
}

// ---------------------------------------------------------------------------
// Split-tf32 GEMM: C[M,N] = A[M,768] * W[768,N] + bias.  128x128 tile, BK=16.
// 8 warps (2m x 4n), each 64x32.  Strides: A-frag idx (lane>>2)*20 -> banks m*4+k
// conflict-free; B-frag (lane&3)*136 -> banks k*8+n conflict-free.
// ---------------------------------------------------------------------------
#define GA_STR 20
#define GB_STR 136

template<int MODE>
__global__ void __launch_bounds__(256, 2) gemm_tc(const float* __restrict__ Ain,
                                                  const float* __restrict__ W,
                                                  const float* __restrict__ bias,
                                                  float* __restrict__ Cout)
{
    extern __shared__ float smg[];
    float* Ah = smg;                    // [128][20]
    float* Al = Ah + 128*GA_STR;
    float* Bh = Al + 128*GA_STR;        // [16][136]
    float* Bl = Bh + 16*GB_STR;

    const float* A = (MODE == 4) ? g_attn : Ain;
    float* C = (MODE == 1) ? g_q : (MODE == 2) ? g_k : (MODE == 3) ? g_v : Cout;

    const int bm = blockIdx.x * 128, bn = blockIdx.y * 128;
    const int t = threadIdx.x, lane = t & 31, w = t >> 5;
    const int wm = (w >> 2) * 64, wn = (w & 3) * 32;

    float acc[4][4][4];
    #pragma unroll
    for (int i = 0; i < 4; i++)
        #pragma unroll
        for (int j = 0; j < 4; j++)
            #pragma unroll
            for (int q = 0; q < 4; q++) acc[i][j][q] = 0.f;

    for (int k0 = 0; k0 < DMODEL; k0 += 16) {
        #pragma unroll
        for (int i = 0; i < 2; i++) {           // A tile: 512 float4
            const int idx = t*2 + i;
            const int m = idx >> 2, k4 = (idx & 3) * 4;
            float4 v = *(const float4*)&A[(size_t)(bm + m)*DMODEL + k0 + k4];
            float4 h, l;
            split2(v.x, h.x, l.x); split2(v.y, h.y, l.y);
            split2(v.z, h.z, l.z); split2(v.w, h.w, l.w);
            *(float4*)&Ah[m*GA_STR + k4] = h;
            *(float4*)&Al[m*GA_STR + k4] = l;
        }
        #pragma unroll
        for (int i = 0; i < 2; i++) {           // B tile: 512 float4
            const int idx = t*2 + i;
            const int kr = idx >> 5, n4 = (idx & 31) * 4;
            float4 v = *(const float4*)&W[(size_t)(k0 + kr)*DMODEL + bn + n4];
            float4 h, l;
            split2(v.x, h.x, l.x); split2(v.y, h.y, l.y);
            split2(v.z, h.z, l.z); split2(v.w, h.w, l.w);
            *(float4*)&Bh[kr*GB_STR + n4] = h;
            *(float4*)&Bl[kr*GB_STR + n4] = l;
        }
        __syncthreads();

        #pragma unroll
        for (int ks = 0; ks < 16; ks += 8) {
            const int kf = ks + (lane & 3);
            float bh_[4][2], bl_[4][2];
            #pragma unroll
            for (int nt = 0; nt < 4; nt++) {
                const int n = wn + nt*8 + (lane >> 2);
                bh_[nt][0] = Bh[kf*GB_STR + n];     bl_[nt][0] = Bl[kf*GB_STR + n];
                bh_[nt][1] = Bh[(kf+4)*GB_STR + n]; bl_[nt][1] = Bl[(kf+4)*GB_STR + n];
            }
            #pragma unroll
            for (int mt = 0; mt < 4; mt++) {
                const int m = wm + mt*16 + (lane >> 2);
                float ah_[4], al_[4];
                ah_[0] = Ah[m*GA_STR + kf];       al_[0] = Al[m*GA_STR + kf];
                ah_[1] = Ah[(m+8)*GA_STR + kf];   al_[1] = Al[(m+8)*GA_STR + kf];
                ah_[2] = Ah[m*GA_STR + kf+4];     al_[2] = Al[m*GA_STR + kf+4];
                ah_[3] = Ah[(m+8)*GA_STR + kf+4]; al_[3] = Al[(m+8)*GA_STR + kf+4];
                #pragma unroll
                for (int nt = 0; nt < 4; nt++) {
                    mma8(acc[mt][nt], ah_, bh_[nt]);
                    mma8(acc[mt][nt], ah_, bl_[nt]);
                    mma8(acc[mt][nt], al_, bh_[nt]);
                }
            }
        }
        __syncthreads();
    }

    // Epilogue
    #pragma unroll
    for (int mt = 0; mt < 4; mt++) {
        #pragma unroll
        for (int nt = 0; nt < 4; nt++) {
            const int r0 = bm + wm + mt*16 + (lane >> 2);
            const int n0 = bn + wn + nt*8 + 2*(lane & 3);
            const float2 bi = *(const float2*)&bias[n0];
            #pragma unroll
            for (int half = 0; half < 2; half++) {
                const int r = r0 + half*8;
                float2 p = make_float2(acc[mt][nt][half*2+0] + bi.x,
                                       acc[mt][nt][half*2+1] + bi.y);
                if (MODE == 4) {
                    *(float2*)&C[(size_t)r*DMODEL + n0] = p;
                } else {
                    const int b_ = r >> 10, s = r & (SEQ-1);
                    const int h_ = n0 >> 6, d = n0 & 63;
                    *(float2*)&C[(size_t)((b_*NHEAD + h_)*SEQ + s)*HDIM + d] = p;
                }
            }
        }
    }
}

// ---------------------------------------------------------------------------
// Flash attention, split-tf32 MMA.  Block = (64 queries, one b*H+h), 8 warps.
// Warp w: m-tile = w&3 (16 q rows), n-range = (w>>2)*32 (keys for S, dims for O).
// Strides: Q/K/P/S 68 (A-frag & K-B-frag conflict-free), V 72 (B-frag k=lane&3
// multiplies stride -> needs stride%32==8).
// ---------------------------------------------------------------------------
#define AT_STR 68
#define VT_STR 72

__global__ void __launch_bounds__(256, 1) attn_tc()
{
    extern __shared__ float sma[];
    float* Qh = sma;
    float* Ql = Qh + 64*AT_STR;
    float* Kh = Ql + 64*AT_STR;
    float* Kl = Kh + 64*AT_STR;
    float* Vh = Kl + 64*AT_STR;
    float* Vl = Vh + 64*VT_STR;
    float* Sb = Vl + 64*VT_STR;
    float* Ph = Sb + 64*AT_STR;
    float* Pl = Ph + 64*AT_STR;
    float* m_s  = Pl + 64*AT_STR;
    float* l_s  = m_s + 64;
    float* corr = l_s + 64;

    const int t = threadIdx.x, lane = t & 31, w = t >> 5;
    const int qt = blockIdx.x, bh = blockIdx.y;
    const int mt = (w & 3) * 16;     // this warp's q-row base
    const int wn = (w >> 2) * 32;    // this warp's n base

    const float* Qg = g_q + ((size_t)bh*SEQ + qt*64)*HDIM;
    const float* Kg = g_k + (size_t)bh*SEQ*HDIM;
    const float* Vg = g_v + (size_t)bh*SEQ*HDIM;

    for (int i = t; i < 64*16; i += 256) {
        const int s = i >> 4, d4 = (i & 15) * 4;
        float4 v = *(const float4*)&Qg[s*HDIM + d4];
        float4 h, l;
        split2(v.x*0.125f, h.x, l.x); split2(v.y*0.125f, h.y, l.y);
        split2(v.z*0.125f, h.z, l.z); split2(v.w*0.125f, h.w, l.w);
        *(float4*)&Qh[s*AT_STR + d4] = h;
        *(float4*)&Ql[s*AT_STR + d4] = l;
    }
    if (t < 64) { m_s[t] = -1e30f; l_s[t] = 0.f; }
    float o[4][4];
    #pragma unroll
    for (int i = 0; i < 4; i++)
        #pragma unroll
        for (int j = 0; j < 4; j++) o[i][j] = 0.f;
    __syncthreads();

    for (int kt = 0; kt < SEQ/64; kt++) {
        const float* Kp = Kg + (size_t)kt*64*HDIM;
        const float* Vp = Vg + (size_t)kt*64*HDIM;
        for (int i = t; i < 64*16; i += 256) {
            const int s = i >> 4, d4 = (i & 15) * 4;
            float4 v = *(const float4*)&Kp[s*HDIM + d4];
            float4 h, l;
            split2(v.x, h.x, l.x); split2(v.y, h.y, l.y);
            split2(v.z, h.z, l.z); split2(v.w, h.w, l.w);
            *(float4*)&Kh[s*AT_STR + d4] = h;
            *(float4*)&Kl[s*AT_STR + d4] = l;
            float4 u = *(const float4*)&Vp[s*HDIM + d4];
            split2(u.x, h.x, l.x); split2(u.y, h.y, l.y);
            split2(u.z, h.z, l.z); split2(u.w, h.w, l.w);
            *(float4*)&Vh[s*VT_STR + d4] = h;
            *(float4*)&Vl[s*VT_STR + d4] = l;
        }
        __syncthreads();

        // ---- S = Q K^T ----
        float sc[4][4];
        #pragma unroll
        for (int i = 0; i < 4; i++)
            #pragma unroll
            for (int j = 0; j < 4; j++) sc[i][j] = 0.f;

        #pragma unroll
        for (int ks = 0; ks < HDIM; ks += 8) {
            const int kf = ks + (lane & 3);
            const int m = mt + (lane >> 2);
            float ah_[4], al_[4];
            ah_[0] = Qh[m*AT_STR + kf];       al_[0] = Ql[m*AT_STR + kf];
            ah_[1] = Qh[(m+8)*AT_STR + kf];   al_[1] = Ql[(m+8)*AT_STR + kf];
            ah_[2] = Qh[m*AT_STR + kf+4];     al_[2] = Ql[m*AT_STR + kf+4];
            ah_[3] = Qh[(m+8)*AT_STR + kf+4]; al_[3] = Ql[(m+8)*AT_STR + kf+4];
            #pragma unroll
            for (int nt = 0; nt < 4; nt++) {
                const int n = wn + nt*8 + (lane >> 2);   // key index
                float bh_[2], bl_[2];
                bh_[0] = Kh[n*AT_STR + kf];   bl_[0] = Kl[n*AT_STR + kf];
                bh_[1] = Kh[n*AT_STR + kf+4]; bl_[1] = Kl[n*AT_STR + kf+4];
                mma8(sc[nt], ah_, bh_);
                mma8(sc[nt], ah_, bl_);
                mma8(sc[nt], al_, bh_);
            }
        }
        #pragma unroll
        for (int nt = 0; nt < 4; nt++) {
            const int r = mt + (lane >> 2);
            const int n0 = wn + nt*8 + 2*(lane & 3);
            *(float2*)&Sb[r*AT_STR + n0]     = make_float2(sc[nt][0], sc[nt][1]);
            *(float2*)&Sb[(r+8)*AT_STR + n0] = make_float2(sc[nt][2], sc[nt][3]);
        }
        __syncthreads();

        // ---- online softmax (warp w owns rows w*8 .. w*8+7) ----
        #pragma unroll
        for (int r8 = 0; r8 < 8; r8++) {
            const int r = w*8 + r8;
            float v0 = Sb[r*AT_STR + lane];
            float v1 = Sb[r*AT_STR + 32 + lane];
            float mx = fmaxf(v0, v1);
            #pragma unroll
            for (int off = 16; off; off >>= 1)
                mx = fmaxf(mx, __shfl_xor_sync(0xffffffffu, mx, off));
            const float m_old = m_s[r];
            const float m_new = fmaxf(m_old, mx);
            const float p0 = __expf(v0 - m_new);
            const float p1 = __expf(v1 - m_new);
            float h, l;
            split2(p0, h, l); Ph[r*AT_STR + lane] = h;      Pl[r*AT_STR + lane] = l;
            split2(p1, h, l); Ph[r*AT_STR + 32 + lane] = h; Pl[r*AT_STR + 32 + lane] = l;
            float sum = p0 + p1;
            #pragma unroll
            for (int off = 16; off; off >>= 1)
                sum += __shfl_xor_sync(0xffffffffu, sum, off);
            if (lane == 0) {
                const float cr = __expf(m_old - m_new);
                l_s[r] = l_s[r]*cr + sum;
                m_s[r] = m_new;
                corr[r] = cr;
            }
        }
        __syncthreads();

        // ---- O = O*corr + P V ----
        {
            const int r = mt + (lane >> 2);
            const float c0 = corr[r], c1 = corr[r + 8];
            #pragma unroll
            for (int nt = 0; nt < 4; nt++) {
                o[nt][0] *= c0; o[nt][1] *= c0;
                o[nt][2] *= c1; o[nt][3] *= c1;
            }
        }
        #pragma unroll
        for (int ks = 0; ks < 64; ks += 8) {
            const int kf = ks + (lane & 3);          // key index
            const int m = mt + (lane >> 2);
            float ah_[4], al_[4];
            ah_[0] = Ph[m*AT_STR + kf];       al_[0] = Pl[m*AT_STR + kf];
            ah_[1] = Ph[(m+8)*AT_STR + kf];   al_[1] = Pl[(m+8)*AT_STR + kf];
            ah_[2] = Ph[m*AT_STR + kf+4];     al_[2] = Pl[m*AT_STR + kf+4];
            ah_[3] = Ph[(m+8)*AT_STR + kf+4]; al_[3] = Pl[(m+8)*AT_STR + kf+4];
            #pragma unroll
            for (int nt = 0; nt < 4; nt++) {
                const int n = wn + nt*8 + (lane >> 2);   // head dim
                float bh_[2], bl_[2];
                bh_[0] = Vh[kf*VT_STR + n];     bl_[0] = Vl[kf*VT_STR + n];
                bh_[1] = Vh[(kf+4)*VT_STR + n]; bl_[1] = Vl[(kf+4)*VT_STR + n];
                mma8(o[nt], ah_, bh_);
                mma8(o[nt], ah_, bl_);
                mma8(o[nt], al_, bh_);
            }
        }
        __syncthreads();
    }

    // ---- normalize + write [B,S,D] ----
    const int b_ = bh / NHEAD, h_ = bh % NHEAD;
    const int r = mt + (lane >> 2);
    const float inv0 = 1.f / l_s[r], inv1 = 1.f / l_s[r + 8];
    #pragma unroll
    for (int nt = 0; nt < 4; nt++) {
        const int n0 = wn + nt*8 + 2*(lane & 3);
        const size_t row0 = (size_t)b_*SEQ + qt*64 + r;
        *(float2*)&g_attn[row0*DMODEL + h_*HDIM + n0] =
            make_float2(o[nt][0]*inv0, o[nt][1]*inv0);
        *(float2*)&g_attn[(row0+8)*DMODEL + h_*HDIM + n0] =
            make_float2(o[nt][2]*inv1, o[nt][3]*inv1);
    }
}

// ---------------------------------------------------------------------------
extern "C" void kernel_launch(void* const* d_in, const int* in_sizes, int n_in,
                              void* d_out, int out_size)
{
    (void)in_sizes; (void)n_in; (void)out_size;
    const float* x  = (const float*)d_in[0];
    const float* Wq = (const float*)d_in[1];
    const float* bq = (const float*)d_in[2];
    const float* Wk = (const float*)d_in[3];
    const float* bk = (const float*)d_in[4];
    const float* Wv = (const float*)d_in[5];
    const float* bv = (const float*)d_in[6];
    const float* Wo = (const float*)d_in[7];
    const float* bo = (const float*)d_in[8];
    float* out = (float*)d_out;

    const int gemm_smem = (2*128*GA_STR + 2*16*GB_STR) * (int)sizeof(float);  // 37,888 B
    dim3 gg(MROWS/128, DMODEL/128);   // (64, 6)
    gemm_tc<1><<<gg, 256, gemm_smem>>>(x, Wq, bq, nullptr);
    gemm_tc<2><<<gg, 256, gemm_smem>>>(x, Wk, bk, nullptr);
    gemm_tc<3><<<gg, 256, gemm_smem>>>(x, Wv, bv, nullptr);

    const int attn_smem = (7*64*AT_STR + 2*64*VT_STR + 192) * (int)sizeof(float); // 159,488 B
    cudaFuncSetAttribute(attn_tc, cudaFuncAttributeMaxDynamicSharedMemorySize, attn_smem);
    attn_tc<<<dim3(SEQ/64, BATCH*NHEAD), 256, attn_smem>>>();

    gemm_tc<4><<<gg, 256, gemm_smem>>>(nullptr, Wo, bo, out);
}

// round 6
// speedup vs baseline: 1.8780x; 1.6142x over previous
#include <cuda_runtime.h>
#include <cuda_bf16.h>
#include <math.h>
#include <stdint.h>

#define BATCH 8
#define SEQ 1024
#define DMODEL 768
#define NHEAD 12
#define HDIM 64
#define MROWS (BATCH*SEQ)

// ------------------------- device scratch (no allocs) -----------------------
__device__ __align__(16) __nv_bfloat16 g_xh[MROWS*DMODEL];      // x split [M][K]
__device__ __align__(16) __nv_bfloat16 g_xl[MROWS*DMODEL];
__device__ __align__(16) __nv_bfloat16 g_wth[4][DMODEL*DMODEL]; // W^T split [N][K]
__device__ __align__(16) __nv_bfloat16 g_wtl[4][DMODEL*DMODEL];
__device__ __align__(16) __nv_bfloat16 g_qh[MROWS*DMODEL];      // Q/8 split [bh][s][d]
__device__ __align__(16) __nv_bfloat16 g_ql[MROWS*DMODEL];
__device__ __align__(16) __nv_bfloat16 g_kh[MROWS*DMODEL];      // K split [bh][s][d]
__device__ __align__(16) __nv_bfloat16 g_kl[MROWS*DMODEL];
__device__ __align__(16) __nv_bfloat16 g_vth[MROWS*DMODEL];     // V split TRANSPOSED [bh][d][s]
__device__ __align__(16) __nv_bfloat16 g_vtl[MROWS*DMODEL];
__device__ __align__(16) __nv_bfloat16 g_ah[MROWS*DMODEL];      // attn out split [M][K]
__device__ __align__(16) __nv_bfloat16 g_al[MROWS*DMODEL];

// ------------------------- helpers ------------------------------------------
__device__ __forceinline__ void bsplit(float x, __nv_bfloat16& h, __nv_bfloat16& l) {
    h = __float2bfloat16_rn(x);
    l = __float2bfloat16_rn(x - __bfloat162float(h));
}
// D += A(16x16 row) * B(16x8 col)  bf16, f32 acc
__device__ __forceinline__ void mma16(float c[4], const uint32_t a[4], const uint32_t b[2]) {
    asm volatile("mma.sync.aligned.m16n8k16.row.col.f32.bf16.bf16.f32 "
        "{%0,%1,%2,%3}, {%4,%5,%6,%7}, {%8,%9}, {%0,%1,%2,%3};"
        : "+f"(c[0]), "+f"(c[1]), "+f"(c[2]), "+f"(c[3])
        : "r"(a[0]), "r"(a[1]), "r"(a[2]), "r"(a[3]), "r"(b[0]), "r"(b[1]));
}

// ------------------------- prep kernels -------------------------------------
__global__ void __launch_bounds__(256) prep_x(const float* __restrict__ x)
{
    const int i = blockIdx.x * 256 + threadIdx.x;   // float4 index
    float4 v = ((const float4*)x)[i];
    union { __nv_bfloat16 b[4]; uint2 u; } H, L;
    bsplit(v.x, H.b[0], L.b[0]); bsplit(v.y, H.b[1], L.b[1]);
    bsplit(v.z, H.b[2], L.b[2]); bsplit(v.w, H.b[3], L.b[3]);
    ((uint2*)g_xh)[i] = H.u;
    ((uint2*)g_xl)[i] = L.u;
}

template<int WID>
__global__ void __launch_bounds__(256) prep_wt(const float* __restrict__ W)
{
    __shared__ float tile[32][33];
    const int n0 = blockIdx.x * 32, k0 = blockIdx.y * 32;
    const int tx = threadIdx.x & 31, ty = threadIdx.x >> 5;  // 32x8
    #pragma unroll
    for (int i = 0; i < 32; i += 8)
        tile[ty + i][tx] = W[(size_t)(k0 + ty + i) * DMODEL + n0 + tx];
    __syncthreads();
    #pragma unroll
    for (int i = 0; i < 32; i += 8) {
        float v = tile[tx][ty + i];
        __nv_bfloat16 h, l; bsplit(v, h, l);
        g_wth[WID][(size_t)(n0 + ty + i) * DMODEL + k0 + tx] = h;
        g_wtl[WID][(size_t)(n0 + ty + i) * DMODEL + k0 + tx] = l;
    }
}

// ------------------------- bf16 split GEMM ----------------------------------
// C[128x128] = A[M,768] * B^T where B^T stored [N][K].  BK=32, 8 warps 2mx4n.
// smem stride 40 elems (80B = 5x16B): conflict-free fragment loads.
// MODE 1: C -> g_qh/g_ql (scaled 1/8)   MODE 2: C -> g_kh/g_kl
// MODE 3: C -> g_vth/g_vtl (transposed) MODE 4: C -> fp32 out
#define GSTR 40

template<int MODE>
__global__ void __launch_bounds__(256, 2) gemm_bf(const float* __restrict__ bias,
                                                  float* __restrict__ Cout)
{
    __shared__ __align__(16) __nv_bfloat16 Ah[128*GSTR], Al[128*GSTR];
    __shared__ __align__(16) __nv_bfloat16 Bh[128*GSTR], Bl[128*GSTR];

    const __nv_bfloat16* gAh = (MODE == 4) ? g_ah : g_xh;
    const __nv_bfloat16* gAl = (MODE == 4) ? g_al : g_xl;
    const __nv_bfloat16* gBh = g_wth[MODE == 4 ? 3 : MODE - 1];
    const __nv_bfloat16* gBl = g_wtl[MODE == 4 ? 3 : MODE - 1];

    const int bm = blockIdx.x * 128, bn = blockIdx.y * 128;
    const int t = threadIdx.x, lane = t & 31, w = t >> 5;
    const int wm = (w >> 2) * 64, wn = (w & 3) * 32;

    float acc[4][4][4];
    #pragma unroll
    for (int i = 0; i < 4; i++)
        #pragma unroll
        for (int j = 0; j < 4; j++)
            #pragma unroll
            for (int q = 0; q < 4; q++) acc[i][j][q] = 0.f;

    for (int kt = 0; kt < 24; kt++) {
        const int k0 = kt * 32;
        #pragma unroll
        for (int i = 0; i < 2; i++) {
            const int idx = t*2 + i;          // 0..511
            const int r = idx >> 2, c = (idx & 3) * 8;
            *(uint4*)&Ah[r*GSTR + c] = *(const uint4*)&gAh[(size_t)(bm + r)*DMODEL + k0 + c];
            *(uint4*)&Al[r*GSTR + c] = *(const uint4*)&gAl[(size_t)(bm + r)*DMODEL + k0 + c];
            *(uint4*)&Bh[r*GSTR + c] = *(const uint4*)&gBh[(size_t)(bn + r)*DMODEL + k0 + c];
            *(uint4*)&Bl[r*GSTR + c] = *(const uint4*)&gBl[(size_t)(bn + r)*DMODEL + k0 + c];
        }
        __syncthreads();

        #pragma unroll
        for (int ks = 0; ks < 32; ks += 16) {
            const int kb = ks + (lane & 3) * 2;
            uint32_t bh_[4][2], bl_[4][2];
            #pragma unroll
            for (int nt = 0; nt < 4; nt++) {
                const int n = wn + nt*8 + (lane >> 2);
                bh_[nt][0] = *(const uint32_t*)&Bh[n*GSTR + kb];
                bh_[nt][1] = *(const uint32_t*)&Bh[n*GSTR + kb + 8];
                bl_[nt][0] = *(const uint32_t*)&Bl[n*GSTR + kb];
                bl_[nt][1] = *(const uint32_t*)&Bl[n*GSTR + kb + 8];
            }
            #pragma unroll
            for (int mt = 0; mt < 4; mt++) {
                const int m = wm + mt*16 + (lane >> 2);
                uint32_t ah_[4], al_[4];
                ah_[0] = *(const uint32_t*)&Ah[m*GSTR + kb];
                ah_[1] = *(const uint32_t*)&Ah[(m+8)*GSTR + kb];
                ah_[2] = *(const uint32_t*)&Ah[m*GSTR + kb + 8];
                ah_[3] = *(const uint32_t*)&Ah[(m+8)*GSTR + kb + 8];
                al_[0] = *(const uint32_t*)&Al[m*GSTR + kb];
                al_[1] = *(const uint32_t*)&Al[(m+8)*GSTR + kb];
                al_[2] = *(const uint32_t*)&Al[m*GSTR + kb + 8];
                al_[3] = *(const uint32_t*)&Al[(m+8)*GSTR + kb + 8];
                #pragma unroll
                for (int nt = 0; nt < 4; nt++) {
                    mma16(acc[mt][nt], ah_, bh_[nt]);
                    mma16(acc[mt][nt], ah_, bl_[nt]);
                    mma16(acc[mt][nt], al_, bh_[nt]);
                }
            }
        }
        __syncthreads();
    }

    // ---- epilogue ----
    #pragma unroll
    for (int mt = 0; mt < 4; mt++) {
        #pragma unroll
        for (int nt = 0; nt < 4; nt++) {
            const int n0 = bn + wn + nt*8 + 2*(lane & 3);
            const float b0 = bias[n0], b1 = bias[n0+1];
            #pragma unroll
            for (int half = 0; half < 2; half++) {
                const int r = bm + wm + mt*16 + (lane >> 2) + half*8;
                float c0 = acc[mt][nt][half*2+0] + b0;
                float c1 = acc[mt][nt][half*2+1] + b1;
                if (MODE == 4) {
                    *(float2*)&Cout[(size_t)r*DMODEL + n0] = make_float2(c0, c1);
                } else {
                    const int b_ = r >> 10, s = r & (SEQ-1);
                    const int h_ = n0 >> 6, d = n0 & 63;
                    const int bh_i = b_ * NHEAD + h_;
                    if (MODE == 1) { c0 *= 0.125f; c1 *= 0.125f; }
                    union { __nv_bfloat16 bb[2]; uint32_t u; } Hu, Lu;
                    bsplit(c0, Hu.bb[0], Lu.bb[0]);
                    bsplit(c1, Hu.bb[1], Lu.bb[1]);
                    if (MODE == 1 || MODE == 2) {
                        __nv_bfloat16* Hd = (MODE == 1) ? g_qh : g_kh;
                        __nv_bfloat16* Ld = (MODE == 1) ? g_ql : g_kl;
                        const size_t o = ((size_t)bh_i*SEQ + s)*HDIM + d;
                        *(uint32_t*)&Hd[o] = Hu.u;
                        *(uint32_t*)&Ld[o] = Lu.u;
                    } else { // MODE 3: transposed [bh][d][s]
                        const size_t o0 = ((size_t)bh_i*HDIM + d)*SEQ + s;
                        const size_t o1 = ((size_t)bh_i*HDIM + d+1)*SEQ + s;
                        g_vth[o0] = Hu.bb[0]; g_vtl[o0] = Lu.bb[0];
                        g_vth[o1] = Hu.bb[1]; g_vtl[o1] = Lu.bb[1];
                    }
                }
            }
        }
    }
}

// ------------------------- flash attention (bf16 mma) ------------------------
// Block: 64 q x one bh, 8 warps (4m x 2n), streams 16 key tiles of 64.
// bf16 tile stride 72 elems (144B = 9x16B); fp32 S stride 68.
// Tail: m_s/l_s/corr = 3*64 floats = 768 B (was the R4/R5 overflow).
#define ASTR 72
#define SSTR 68
#define ATTN_SMEM (8*64*ASTR*2 + 64*SSTR*4 + 768)

__global__ void __launch_bounds__(256) attn_bf()
{
    extern __shared__ __align__(16) char smraw[];
    __nv_bfloat16* Qh = (__nv_bfloat16*)smraw;
    __nv_bfloat16* Ql = Qh + 64*ASTR;
    __nv_bfloat16* Kh = Ql + 64*ASTR;
    __nv_bfloat16* Kl = Kh + 64*ASTR;
    __nv_bfloat16* Vh = Kl + 64*ASTR;   // transposed [d][s]
    __nv_bfloat16* Vl = Vh + 64*ASTR;
    __nv_bfloat16* Ph = Vl + 64*ASTR;
    __nv_bfloat16* Pl = Ph + 64*ASTR;
    float* Sb   = (float*)(Pl + 64*ASTR);       // [64][68]
    float* m_s  = Sb + 64*SSTR;
    float* l_s  = m_s + 64;
    float* corr = l_s + 64;

    const int t = threadIdx.x, lane = t & 31, w = t >> 5;
    const int qt = blockIdx.x, bh = blockIdx.y;
    const int mt = (w & 3) * 16;     // warp's 16 q rows
    const int wn = (w >> 2) * 32;    // warp's 32-col half

    const size_t qoff = ((size_t)bh*SEQ + qt*64)*HDIM;
    const size_t koff = (size_t)bh*SEQ*HDIM;

    // Q tile (pre-scaled, pre-split)
    #pragma unroll
    for (int i = 0; i < 2; i++) {
        const int idx = t*2 + i;             // 0..511
        const int r = idx >> 3, c = (idx & 7) * 8;
        *(uint4*)&Qh[r*ASTR + c] = *(const uint4*)&g_qh[qoff + r*HDIM + c];
        *(uint4*)&Ql[r*ASTR + c] = *(const uint4*)&g_ql[qoff + r*HDIM + c];
    }
    if (t < 64) { m_s[t] = -1e30f; l_s[t] = 0.f; }
    float o[4][4];
    #pragma unroll
    for (int i = 0; i < 4; i++)
        #pragma unroll
        for (int j = 0; j < 4; j++) o[i][j] = 0.f;
    __syncthreads();

    for (int kt = 0; kt < SEQ/64; kt++) {
        // K rows [s][d]; V^T rows [d][s]
        #pragma unroll
        for (int i = 0; i < 2; i++) {
            const int idx = t*2 + i;
            const int r = idx >> 3, c = (idx & 7) * 8;
            *(uint4*)&Kh[r*ASTR + c] = *(const uint4*)&g_kh[koff + (kt*64 + r)*HDIM + c];
            *(uint4*)&Kl[r*ASTR + c] = *(const uint4*)&g_kl[koff + (kt*64 + r)*HDIM + c];
            *(uint4*)&Vh[r*ASTR + c] = *(const uint4*)&g_vth[koff + (size_t)r*SEQ + kt*64 + c];
            *(uint4*)&Vl[r*ASTR + c] = *(const uint4*)&g_vtl[koff + (size_t)r*SEQ + kt*64 + c];
        }
        __syncthreads();

        // ---- S = Q K^T ----
        float sc[4][4];
        #pragma unroll
        for (int i = 0; i < 4; i++)
            #pragma unroll
            for (int j = 0; j < 4; j++) sc[i][j] = 0.f;

        #pragma unroll
        for (int ks = 0; ks < HDIM; ks += 16) {
            const int kb = ks + (lane & 3) * 2;
            const int m = mt + (lane >> 2);
            uint32_t ah_[4], al_[4];
            ah_[0] = *(const uint32_t*)&Qh[m*ASTR + kb];
            ah_[1] = *(const uint32_t*)&Qh[(m+8)*ASTR + kb];
            ah_[2] = *(const uint32_t*)&Qh[m*ASTR + kb + 8];
            ah_[3] = *(const uint32_t*)&Qh[(m+8)*ASTR + kb + 8];
            al_[0] = *(const uint32_t*)&Ql[m*ASTR + kb];
            al_[1] = *(const uint32_t*)&Ql[(m+8)*ASTR + kb];
            al_[2] = *(const uint32_t*)&Ql[m*ASTR + kb + 8];
            al_[3] = *(const uint32_t*)&Ql[(m+8)*ASTR + kb + 8];
            #pragma unroll
            for (int nt = 0; nt < 4; nt++) {
                const int n = wn + nt*8 + (lane >> 2);
                uint32_t bh_[2], bl_[2];
                bh_[0] = *(const uint32_t*)&Kh[n*ASTR + kb];
                bh_[1] = *(const uint32_t*)&Kh[n*ASTR + kb + 8];
                bl_[0] = *(const uint32_t*)&Kl[n*ASTR + kb];
                bl_[1] = *(const uint32_t*)&Kl[n*ASTR + kb + 8];
                mma16(sc[nt], ah_, bh_);
                mma16(sc[nt], ah_, bl_);
                mma16(sc[nt], al_, bh_);
            }
        }
        {
            const int r = mt + (lane >> 2);
            #pragma unroll
            for (int nt = 0; nt < 4; nt++) {
                const int n0 = wn + nt*8 + 2*(lane & 3);
                *(float2*)&Sb[r*SSTR + n0]     = make_float2(sc[nt][0], sc[nt][1]);
                *(float2*)&Sb[(r+8)*SSTR + n0] = make_float2(sc[nt][2], sc[nt][3]);
            }
        }
        __syncthreads();

        // ---- online softmax; warp w owns rows w*8..w*8+7; lane -> cols 2l,2l+1
        #pragma unroll
        for (int r8 = 0; r8 < 8; r8++) {
            const int r = w*8 + r8;
            float2 f = *(const float2*)&Sb[r*SSTR + 2*lane];
            float mx = fmaxf(f.x, f.y);
            #pragma unroll
            for (int off = 16; off; off >>= 1)
                mx = fmaxf(mx, __shfl_xor_sync(0xffffffffu, mx, off));
            const float m_old = m_s[r];
            const float m_new = fmaxf(m_old, mx);
            const float p0 = __expf(f.x - m_new);
            const float p1 = __expf(f.y - m_new);
            union { __nv_bfloat16 bb[2]; uint32_t u; } Hu, Lu;
            bsplit(p0, Hu.bb[0], Lu.bb[0]);
            bsplit(p1, Hu.bb[1], Lu.bb[1]);
            *(uint32_t*)&Ph[r*ASTR + 2*lane] = Hu.u;
            *(uint32_t*)&Pl[r*ASTR + 2*lane] = Lu.u;
            float sum = p0 + p1;
            #pragma unroll
            for (int off = 16; off; off >>= 1)
                sum += __shfl_xor_sync(0xffffffffu, sum, off);
            if (lane == 0) {
                const float cr = __expf(m_old - m_new);
                l_s[r] = l_s[r]*cr + sum;
                m_s[r] = m_new;
                corr[r] = cr;
            }
        }
        __syncthreads();

        // ---- O = O*corr + P V  (B = V^T [d][s]) ----
        {
            const int r = mt + (lane >> 2);
            const float c0 = corr[r], c1 = corr[r + 8];
            #pragma unroll
            for (int nt = 0; nt < 4; nt++) {
                o[nt][0] *= c0; o[nt][1] *= c0;
                o[nt][2] *= c1; o[nt][3] *= c1;
            }
        }
        #pragma unroll
        for (int ks = 0; ks < 64; ks += 16) {
            const int kb = ks + (lane & 3) * 2;
            const int m = mt + (lane >> 2);
            uint32_t ah_[4], al_[4];
            ah_[0] = *(const uint32_t*)&Ph[m*ASTR + kb];
            ah_[1] = *(const uint32_t*)&Ph[(m+8)*ASTR + kb];
            ah_[2] = *(const uint32_t*)&Ph[m*ASTR + kb + 8];
            ah_[3] = *(const uint32_t*)&Ph[(m+8)*ASTR + kb + 8];
            al_[0] = *(const uint32_t*)&Pl[m*ASTR + kb];
            al_[1] = *(const uint32_t*)&Pl[(m+8)*ASTR + kb];
            al_[2] = *(const uint32_t*)&Pl[m*ASTR + kb + 8];
            al_[3] = *(const uint32_t*)&Pl[(m+8)*ASTR + kb + 8];
            #pragma unroll
            for (int nt = 0; nt < 4; nt++) {
                const int n = wn + nt*8 + (lane >> 2);   // head dim
                uint32_t bh_[2], bl_[2];
                bh_[0] = *(const uint32_t*)&Vh[n*ASTR + kb];
                bh_[1] = *(const uint32_t*)&Vh[n*ASTR + kb + 8];
                bl_[0] = *(const uint32_t*)&Vl[n*ASTR + kb];
                bl_[1] = *(const uint32_t*)&Vl[n*ASTR + kb + 8];
                mma16(o[nt], ah_, bh_);
                mma16(o[nt], ah_, bl_);
                mma16(o[nt], al_, bh_);
            }
        }
        __syncthreads();
    }

    // ---- normalize + write split-bf16 [B,S,D] for the O GEMM ----
    const int b_ = bh / NHEAD, h_ = bh % NHEAD;
    const int r = mt + (lane >> 2);
    const float inv0 = 1.f / l_s[r], inv1 = 1.f / l_s[r + 8];
    #pragma unroll
    for (int nt = 0; nt < 4; nt++) {
        const int n0 = wn + nt*8 + 2*(lane & 3);
        const size_t row0 = (size_t)b_*SEQ + qt*64 + r;
        union { __nv_bfloat16 bb[2]; uint32_t u; } Hu, Lu;
        bsplit(o[nt][0]*inv0, Hu.bb[0], Lu.bb[0]);
        bsplit(o[nt][1]*inv0, Hu.bb[1], Lu.bb[1]);
        *(uint32_t*)&g_ah[row0*DMODEL + h_*HDIM + n0] = Hu.u;
        *(uint32_t*)&g_al[row0*DMODEL + h_*HDIM + n0] = Lu.u;
        bsplit(o[nt][2]*inv1, Hu.bb[0], Lu.bb[0]);
        bsplit(o[nt][3]*inv1, Hu.bb[1], Lu.bb[1]);
        *(uint32_t*)&g_ah[(row0+8)*DMODEL + h_*HDIM + n0] = Hu.u;
        *(uint32_t*)&g_al[(row0+8)*DMODEL + h_*HDIM + n0] = Lu.u;
    }
}

// ---------------------------------------------------------------------------
extern "C" void kernel_launch(void* const* d_in, const int* in_sizes, int n_in,
                              void* d_out, int out_size)
{
    (void)in_sizes; (void)n_in; (void)out_size;
    const float* x  = (const float*)d_in[0];
    const float* Wq = (const float*)d_in[1];
    const float* bq = (const float*)d_in[2];
    const float* Wk = (const float*)d_in[3];
    const float* bk = (const float*)d_in[4];
    const float* Wv = (const float*)d_in[5];
    const float* bv = (const float*)d_in[6];
    const float* Wo = (const float*)d_in[7];
    const float* bo = (const float*)d_in[8];
    float* out = (float*)d_out;

    prep_x<<<(MROWS*DMODEL/4)/256, 256>>>(x);
    dim3 wt(DMODEL/32, DMODEL/32);
    prep_wt<0><<<wt, 256>>>(Wq);
    prep_wt<1><<<wt, 256>>>(Wk);
    prep_wt<2><<<wt, 256>>>(Wv);
    prep_wt<3><<<wt, 256>>>(Wo);

    dim3 gg(MROWS/128, DMODEL/128);   // (64, 6)
    gemm_bf<1><<<gg, 256>>>(bq, nullptr);
    gemm_bf<2><<<gg, 256>>>(bk, nullptr);
    gemm_bf<3><<<gg, 256>>>(bv, nullptr);

    cudaFuncSetAttribute(attn_bf, cudaFuncAttributeMaxDynamicSharedMemorySize, ATTN_SMEM);
    attn_bf<<<dim3(SEQ/64, BATCH*NHEAD), 256, ATTN_SMEM>>>();

    gemm_bf<4><<<gg, 256>>>(bo, out);
}

// round 7
// speedup vs baseline: 2.5788x; 1.3732x over previous
#include <cuda_runtime.h>
#include <cuda_bf16.h>
#include <math.h>
#include <stdint.h>

#define BATCH 8
#define SEQ 1024
#define DMODEL 768
#define NHEAD 12
#define HDIM 64
#define MROWS (BATCH*SEQ)

// ------------------------- device scratch (no allocs) -----------------------
__device__ __align__(16) __nv_bfloat16 g_xh[MROWS*DMODEL];      // x split [M][K]
__device__ __align__(16) __nv_bfloat16 g_xl[MROWS*DMODEL];
__device__ __align__(16) __nv_bfloat16 g_wth[4][DMODEL*DMODEL]; // W^T split [N][K]
__device__ __align__(16) __nv_bfloat16 g_wtl[4][DMODEL*DMODEL];
__device__ __align__(16) __nv_bfloat16 g_qh[MROWS*DMODEL];      // Q/8 split [bh][s][d]
__device__ __align__(16) __nv_bfloat16 g_ql[MROWS*DMODEL];
__device__ __align__(16) __nv_bfloat16 g_kh[MROWS*DMODEL];      // K split [bh][s][d]
__device__ __align__(16) __nv_bfloat16 g_kl[MROWS*DMODEL];
__device__ __align__(16) __nv_bfloat16 g_vth[MROWS*DMODEL];     // V split TRANSPOSED [bh][d][s]
__device__ __align__(16) __nv_bfloat16 g_vtl[MROWS*DMODEL];
__device__ __align__(16) __nv_bfloat16 g_ah[MROWS*DMODEL];      // attn out split [M][K]
__device__ __align__(16) __nv_bfloat16 g_al[MROWS*DMODEL];

// ------------------------- helpers ------------------------------------------
__device__ __forceinline__ void bsplit(float x, __nv_bfloat16& h, __nv_bfloat16& l) {
    h = __float2bfloat16_rn(x);
    l = __float2bfloat16_rn(x - __bfloat162float(h));
}
// D += A(16x16 row) * B(16x8 col)  bf16, f32 acc
__device__ __forceinline__ void mma16(float c[4], const uint32_t a[4],
                                      uint32_t b0, uint32_t b1) {
    asm volatile("mma.sync.aligned.m16n8k16.row.col.f32.bf16.bf16.f32 "
        "{%0,%1,%2,%3}, {%4,%5,%6,%7}, {%8,%9}, {%0,%1,%2,%3};"
        : "+f"(c[0]), "+f"(c[1]), "+f"(c[2]), "+f"(c[3])
        : "r"(a[0]), "r"(a[1]), "r"(a[2]), "r"(a[3]), "r"(b0), "r"(b1));
}
__device__ __forceinline__ uint32_t sm_addr(const void* p) {
    return (uint32_t)__cvta_generic_to_shared(p);
}
__device__ __forceinline__ void ldsm_x4(uint32_t& r0, uint32_t& r1, uint32_t& r2,
                                        uint32_t& r3, uint32_t addr) {
    asm volatile("ldmatrix.sync.aligned.m8n8.x4.shared.b16 {%0,%1,%2,%3}, [%4];"
        : "=r"(r0), "=r"(r1), "=r"(r2), "=r"(r3) : "r"(addr));
}
__device__ __forceinline__ void cp16(void* dst, const void* src) {
    asm volatile("cp.async.cg.shared.global [%0], [%1], 16;"
        :: "r"(sm_addr(dst)), "l"(src));
}
#define CP_COMMIT() asm volatile("cp.async.commit_group;" ::: "memory")
#define CP_WAIT(n)  asm volatile("cp.async.wait_group %0;" :: "n"(n) : "memory")

// ------------------------- prep kernels -------------------------------------
__global__ void __launch_bounds__(256) prep_x(const float* __restrict__ x)
{
    const int i = blockIdx.x * 256 + threadIdx.x;   // float4 index
    float4 v = ((const float4*)x)[i];
    union { __nv_bfloat16 b[4]; uint2 u; } H, L;
    bsplit(v.x, H.b[0], L.b[0]); bsplit(v.y, H.b[1], L.b[1]);
    bsplit(v.z, H.b[2], L.b[2]); bsplit(v.w, H.b[3], L.b[3]);
    ((uint2*)g_xh)[i] = H.u;
    ((uint2*)g_xl)[i] = L.u;
}

template<int WID>
__global__ void __launch_bounds__(256) prep_wt(const float* __restrict__ W)
{
    __shared__ float tile[32][33];
    const int n0 = blockIdx.x * 32, k0 = blockIdx.y * 32;
    const int tx = threadIdx.x & 31, ty = threadIdx.x >> 5;  // 32x8
    #pragma unroll
    for (int i = 0; i < 32; i += 8)
        tile[ty + i][tx] = W[(size_t)(k0 + ty + i) * DMODEL + n0 + tx];
    __syncthreads();
    #pragma unroll
    for (int i = 0; i < 32; i += 8) {
        float v = tile[tx][ty + i];
        __nv_bfloat16 h, l; bsplit(v, h, l);
        g_wth[WID][(size_t)(n0 + ty + i) * DMODEL + k0 + tx] = h;
        g_wtl[WID][(size_t)(n0 + ty + i) * DMODEL + k0 + tx] = l;
    }
}

// ------------------------- bf16 split GEMM (ldmatrix + cp.async x2) ---------
// C[128x128] = A[M,768] * B^T ([N][K]).  BK=32, 8 warps 2m x 4n, 2-stage pipe.
#define GSTR 40
#define GTILE (128*GSTR)                      // elems per tile
#define GEMM_SMEM (2*4*GTILE*2)               // 81,920 B

template<int MODE>
__global__ void __launch_bounds__(256, 2) gemm_bf(const float* __restrict__ bias,
                                                  float* __restrict__ Cout)
{
    extern __shared__ __align__(16) char gsm[];
    __nv_bfloat16* Sm = (__nv_bfloat16*)gsm;

    const __nv_bfloat16* gAh = (MODE == 4) ? g_ah : g_xh;
    const __nv_bfloat16* gAl = (MODE == 4) ? g_al : g_xl;
    const __nv_bfloat16* gBh = g_wth[MODE == 4 ? 3 : MODE - 1];
    const __nv_bfloat16* gBl = g_wtl[MODE == 4 ? 3 : MODE - 1];

    const int bm = blockIdx.x * 128, bn = blockIdx.y * 128;
    const int t = threadIdx.x, lane = t & 31, w = t >> 5;
    const int wm = (w >> 2) * 64, wn = (w & 3) * 32;

    float acc[4][4][4];
    #pragma unroll
    for (int i = 0; i < 4; i++)
        #pragma unroll
        for (int j = 0; j < 4; j++)
            #pragma unroll
            for (int q = 0; q < 4; q++) acc[i][j][q] = 0.f;

    // prefetch one kt into stage: 4 tiles x 512 chunks of 16B
    auto prefetch = [&](int kt, int stage) {
        const int k0 = kt * 32;
        __nv_bfloat16* base = Sm + stage * 4 * GTILE;
        #pragma unroll
        for (int i = 0; i < 8; i++) {
            const int c = t + i * 256;          // 0..2047
            const int tile = c >> 9, cc = c & 511;
            const int row = cc >> 2, col = (cc & 3) * 8;
            const __nv_bfloat16* g = (tile == 0) ? gAh : (tile == 1) ? gAl
                                   : (tile == 2) ? gBh : gBl;
            const int gr = ((tile < 2) ? bm : bn) + row;
            cp16(base + tile * GTILE + row * GSTR + col,
                 g + (size_t)gr * DMODEL + k0 + col);
        }
        CP_COMMIT();
    };

    prefetch(0, 0);

    const int laneA = (lane & 15) * GSTR + (lane >> 4) * 8;
    const int laneB = ((lane & 7) + ((lane >> 4) & 1) * 8) * GSTR + ((lane >> 3) & 1) * 8;

    for (int kt = 0; kt < 24; kt++) {
        const int stage = kt & 1;
        if (kt + 1 < 24) { prefetch(kt + 1, stage ^ 1); CP_WAIT(1); }
        else             { CP_WAIT(0); }
        __syncthreads();

        const __nv_bfloat16* Ah = Sm + (stage * 4 + 0) * GTILE;
        const __nv_bfloat16* Al = Sm + (stage * 4 + 1) * GTILE;
        const __nv_bfloat16* Bh = Sm + (stage * 4 + 2) * GTILE;
        const __nv_bfloat16* Bl = Sm + (stage * 4 + 3) * GTILE;

        #pragma unroll
        for (int ks = 0; ks < 32; ks += 16) {
            uint32_t bh_[2][4], bl_[2][4];
            #pragma unroll
            for (int p = 0; p < 2; p++) {
                const int off = (wn + p * 16) * GSTR + ks + laneB;
                ldsm_x4(bh_[p][0], bh_[p][1], bh_[p][2], bh_[p][3], sm_addr(Bh + off));
                ldsm_x4(bl_[p][0], bl_[p][1], bl_[p][2], bl_[p][3], sm_addr(Bl + off));
            }
            #pragma unroll
            for (int mt_ = 0; mt_ < 4; mt_++) {
                const int off = (wm + mt_ * 16) * GSTR + ks + laneA;
                uint32_t ah_[4], al_[4];
                ldsm_x4(ah_[0], ah_[1], ah_[2], ah_[3], sm_addr(Ah + off));
                ldsm_x4(al_[0], al_[1], al_[2], al_[3], sm_addr(Al + off));
                #pragma unroll
                for (int p = 0; p < 2; p++) {
                    mma16(acc[mt_][2*p],   ah_, bh_[p][0], bh_[p][1]);
                    mma16(acc[mt_][2*p],   ah_, bl_[p][0], bl_[p][1]);
                    mma16(acc[mt_][2*p],   al_, bh_[p][0], bh_[p][1]);
                    mma16(acc[mt_][2*p+1], ah_, bh_[p][2], bh_[p][3]);
                    mma16(acc[mt_][2*p+1], ah_, bl_[p][2], bl_[p][3]);
                    mma16(acc[mt_][2*p+1], al_, bh_[p][2], bh_[p][3]);
                }
            }
        }
        __syncthreads();
    }

    // ---- epilogue ----
    #pragma unroll
    for (int mt_ = 0; mt_ < 4; mt_++) {
        #pragma unroll
        for (int nt = 0; nt < 4; nt++) {
            const int n0 = bn + wn + nt*8 + 2*(lane & 3);
            const float b0 = bias[n0], b1 = bias[n0+1];
            #pragma unroll
            for (int half = 0; half < 2; half++) {
                const int r = bm + wm + mt_*16 + (lane >> 2) + half*8;
                float c0 = acc[mt_][nt][half*2+0] + b0;
                float c1 = acc[mt_][nt][half*2+1] + b1;
                if (MODE == 4) {
                    *(float2*)&Cout[(size_t)r*DMODEL + n0] = make_float2(c0, c1);
                } else {
                    const int b_ = r >> 10, s = r & (SEQ-1);
                    const int h_ = n0 >> 6, d = n0 & 63;
                    const int bh_i = b_ * NHEAD + h_;
                    if (MODE == 1) { c0 *= 0.125f; c1 *= 0.125f; }
                    union { __nv_bfloat16 bb[2]; uint32_t u; } Hu, Lu;
                    bsplit(c0, Hu.bb[0], Lu.bb[0]);
                    bsplit(c1, Hu.bb[1], Lu.bb[1]);
                    if (MODE == 1 || MODE == 2) {
                        __nv_bfloat16* Hd = (MODE == 1) ? g_qh : g_kh;
                        __nv_bfloat16* Ld = (MODE == 1) ? g_ql : g_kl;
                        const size_t o = ((size_t)bh_i*SEQ + s)*HDIM + d;
                        *(uint32_t*)&Hd[o] = Hu.u;
                        *(uint32_t*)&Ld[o] = Lu.u;
                    } else { // MODE 3: transposed [bh][d][s]
                        const size_t o0 = ((size_t)bh_i*HDIM + d)*SEQ + s;
                        const size_t o1 = ((size_t)bh_i*HDIM + d+1)*SEQ + s;
                        g_vth[o0] = Hu.bb[0]; g_vtl[o0] = Lu.bb[0];
                        g_vth[o1] = Hu.bb[1]; g_vtl[o1] = Lu.bb[1];
                    }
                }
            }
        }
    }
}

// ------------------------- flash attention (ldmatrix + cp.async) -------------
#define ASTR 72
#define SSTR 68
#define ATTN_SMEM (8*64*ASTR*2 + 64*SSTR*4 + 768)

__global__ void __launch_bounds__(256, 2) attn_bf()
{
    extern __shared__ __align__(16) char smraw[];
    __nv_bfloat16* Qh = (__nv_bfloat16*)smraw;
    __nv_bfloat16* Ql = Qh + 64*ASTR;
    __nv_bfloat16* Kh = Ql + 64*ASTR;
    __nv_bfloat16* Kl = Kh + 64*ASTR;
    __nv_bfloat16* Vh = Kl + 64*ASTR;   // transposed [d][s]
    __nv_bfloat16* Vl = Vh + 64*ASTR;
    __nv_bfloat16* Ph = Vl + 64*ASTR;
    __nv_bfloat16* Pl = Ph + 64*ASTR;
    float* Sb   = (float*)(Pl + 64*ASTR);       // [64][68]
    float* m_s  = Sb + 64*SSTR;
    float* l_s  = m_s + 64;
    float* corr = l_s + 64;

    const int t = threadIdx.x, lane = t & 31, w = t >> 5;
    const int qt = blockIdx.x, bh = blockIdx.y;
    const int mt = (w & 3) * 16;     // warp's 16 q rows
    const int wn = (w >> 2) * 32;    // warp's 32-col half

    const size_t qoff = ((size_t)bh*SEQ + qt*64)*HDIM;
    const size_t koff = (size_t)bh*SEQ*HDIM;

    const int laneA = (lane & 15) * ASTR + (lane >> 4) * 8;
    const int laneB = ((lane & 7) + ((lane >> 4) & 1) * 8) * ASTR + ((lane >> 3) & 1) * 8;

    // Q tile (pre-scaled, pre-split) -> smem -> hoisted register fragments
    #pragma unroll
    for (int i = 0; i < 4; i++) {
        const int c = t + i * 256;             // 0..1023 (2 tiles x 512 chunks)
        const int tile = c >> 9, cc = c & 511;
        const int r = cc >> 3, col = (cc & 7) * 8;
        cp16((tile ? Ql : Qh) + r*ASTR + col,
             (tile ? g_ql : g_qh) + qoff + r*HDIM + col);
    }
    CP_COMMIT(); CP_WAIT(0);
    if (t < 64) { m_s[t] = -1e30f; l_s[t] = 0.f; }
    __syncthreads();

    uint32_t qh_[4][4], ql_[4][4];
    #pragma unroll
    for (int ks4 = 0; ks4 < 4; ks4++) {
        const int off = mt*ASTR + ks4*16 + laneA;
        ldsm_x4(qh_[ks4][0], qh_[ks4][1], qh_[ks4][2], qh_[ks4][3], sm_addr(Qh + off));
        ldsm_x4(ql_[ks4][0], ql_[ks4][1], ql_[ks4][2], ql_[ks4][3], sm_addr(Ql + off));
    }

    float o[4][4];
    #pragma unroll
    for (int i = 0; i < 4; i++)
        #pragma unroll
        for (int j = 0; j < 4; j++) o[i][j] = 0.f;

    for (int kt = 0; kt < SEQ/64; kt++) {
        // K rows [s][d]; V^T rows [d][s]  (4 tiles x 512 chunks, cp.async)
        #pragma unroll
        for (int i = 0; i < 8; i++) {
            const int c = t + i * 256;          // 0..2047
            const int tile = c >> 9, cc = c & 511;
            const int r = cc >> 3, col = (cc & 7) * 8;
            __nv_bfloat16* d = (tile == 0) ? Kh : (tile == 1) ? Kl
                             : (tile == 2) ? Vh : Vl;
            const __nv_bfloat16* g;
            size_t src;
            if (tile < 2) { g = tile ? g_kl : g_kh; src = koff + (size_t)(kt*64 + r)*HDIM + col; }
            else          { g = (tile == 3) ? g_vtl : g_vth; src = koff + (size_t)r*SEQ + kt*64 + col; }
            cp16(d + r*ASTR + col, g + src);
        }
        CP_COMMIT(); CP_WAIT(0);
        __syncthreads();

        // ---- S = Q K^T ----
        float sc[4][4];
        #pragma unroll
        for (int i = 0; i < 4; i++)
            #pragma unroll
            for (int j = 0; j < 4; j++) sc[i][j] = 0.f;

        #pragma unroll
        for (int ks4 = 0; ks4 < 4; ks4++) {
            uint32_t kh_[2][4], kl_[2][4];
            #pragma unroll
            for (int p = 0; p < 2; p++) {
                const int off = (wn + p*16)*ASTR + ks4*16 + laneB;
                ldsm_x4(kh_[p][0], kh_[p][1], kh_[p][2], kh_[p][3], sm_addr(Kh + off));
                ldsm_x4(kl_[p][0], kl_[p][1], kl_[p][2], kl_[p][3], sm_addr(Kl + off));
            }
            #pragma unroll
            for (int p = 0; p < 2; p++) {
                mma16(sc[2*p],   qh_[ks4], kh_[p][0], kh_[p][1]);
                mma16(sc[2*p],   qh_[ks4], kl_[p][0], kl_[p][1]);
                mma16(sc[2*p],   ql_[ks4], kh_[p][0], kh_[p][1]);
                mma16(sc[2*p+1], qh_[ks4], kh_[p][2], kh_[p][3]);
                mma16(sc[2*p+1], qh_[ks4], kl_[p][2], kl_[p][3]);
                mma16(sc[2*p+1], ql_[ks4], kh_[p][2], kh_[p][3]);
            }
        }
        {
            const int r = mt + (lane >> 2);
            #pragma unroll
            for (int nt = 0; nt < 4; nt++) {
                const int n0 = wn + nt*8 + 2*(lane & 3);
                *(float2*)&Sb[r*SSTR + n0]     = make_float2(sc[nt][0], sc[nt][1]);
                *(float2*)&Sb[(r+8)*SSTR + n0] = make_float2(sc[nt][2], sc[nt][3]);
            }
        }
        __syncthreads();

        // ---- online softmax; warp w owns rows w*8..w*8+7
        #pragma unroll
        for (int r8 = 0; r8 < 8; r8++) {
            const int r = w*8 + r8;
            float2 f = *(const float2*)&Sb[r*SSTR + 2*lane];
            float mx = fmaxf(f.x, f.y);
            #pragma unroll
            for (int off = 16; off; off >>= 1)
                mx = fmaxf(mx, __shfl_xor_sync(0xffffffffu, mx, off));
            const float m_old = m_s[r];
            const float m_new = fmaxf(m_old, mx);
            const float p0 = __expf(f.x - m_new);
            const float p1 = __expf(f.y - m_new);
            union { __nv_bfloat16 bb[2]; uint32_t u; } Hu, Lu;
            bsplit(p0, Hu.bb[0], Lu.bb[0]);
            bsplit(p1, Hu.bb[1], Lu.bb[1]);
            *(uint32_t*)&Ph[r*ASTR + 2*lane] = Hu.u;
            *(uint32_t*)&Pl[r*ASTR + 2*lane] = Lu.u;
            float sum = p0 + p1;
            #pragma unroll
            for (int off = 16; off; off >>= 1)
                sum += __shfl_xor_sync(0xffffffffu, sum, off);
            if (lane == 0) {
                const float cr = __expf(m_old - m_new);
                l_s[r] = l_s[r]*cr + sum;
                m_s[r] = m_new;
                corr[r] = cr;
            }
        }
        __syncthreads();

        // ---- O = O*corr + P V  (B = V^T [d][s]) ----
        {
            const int r = mt + (lane >> 2);
            const float c0 = corr[r], c1 = corr[r + 8];
            #pragma unroll
            for (int nt = 0; nt < 4; nt++) {
                o[nt][0] *= c0; o[nt][1] *= c0;
                o[nt][2] *= c1; o[nt][3] *= c1;
            }
        }
        #pragma unroll
        for (int ks4 = 0; ks4 < 4; ks4++) {
            uint32_t ph_[4], pl_[4];
            {
                const int off = mt*ASTR + ks4*16 + laneA;
                ldsm_x4(ph_[0], ph_[1], ph_[2], ph_[3], sm_addr(Ph + off));
                ldsm_x4(pl_[0], pl_[1], pl_[2], pl_[3], sm_addr(Pl + off));
            }
            uint32_t vh_[2][4], vl_[2][4];
            #pragma unroll
            for (int p = 0; p < 2; p++) {
                const int off = (wn + p*16)*ASTR + ks4*16 + laneB;
                ldsm_x4(vh_[p][0], vh_[p][1], vh_[p][2], vh_[p][3], sm_addr(Vh + off));
                ldsm_x4(vl_[p][0], vl_[p][1], vl_[p][2], vl_[p][3], sm_addr(Vl + off));
            }
            #pragma unroll
            for (int p = 0; p < 2; p++) {
                mma16(o[2*p],   ph_, vh_[p][0], vh_[p][1]);
                mma16(o[2*p],   ph_, vl_[p][0], vl_[p][1]);
                mma16(o[2*p],   pl_, vh_[p][0], vh_[p][1]);
                mma16(o[2*p+1], ph_, vh_[p][2], vh_[p][3]);
                mma16(o[2*p+1], ph_, vl_[p][2], vl_[p][3]);
                mma16(o[2*p+1], pl_, vh_[p][2], vh_[p][3]);
            }
        }
        __syncthreads();
    }

    // ---- normalize + write split-bf16 [B,S,D] for the O GEMM ----
    const int b_ = bh / NHEAD, h_ = bh % NHEAD;
    const int r = mt + (lane >> 2);
    const float inv0 = 1.f / l_s[r], inv1 = 1.f / l_s[r + 8];
    #pragma unroll
    for (int nt = 0; nt < 4; nt++) {
        const int n0 = wn + nt*8 + 2*(lane & 3);
        const size_t row0 = (size_t)b_*SEQ + qt*64 + r;
        union { __nv_bfloat16 bb[2]; uint32_t u; } Hu, Lu;
        bsplit(o[nt][0]*inv0, Hu.bb[0], Lu.bb[0]);
        bsplit(o[nt][1]*inv0, Hu.bb[1], Lu.bb[1]);
        *(uint32_t*)&g_ah[row0*DMODEL + h_*HDIM + n0] = Hu.u;
        *(uint32_t*)&g_al[row0*DMODEL + h_*HDIM + n0] = Lu.u;
        bsplit(o[nt][2]*inv1, Hu.bb[0], Lu.bb[0]);
        bsplit(o[nt][3]*inv1, Hu.bb[1], Lu.bb[1]);
        *(uint32_t*)&g_ah[(row0+8)*DMODEL + h_*HDIM + n0] = Hu.u;
        *(uint32_t*)&g_al[(row0+8)*DMODEL + h_*HDIM + n0] = Lu.u;
    }
}

// ---------------------------------------------------------------------------
extern "C" void kernel_launch(void* const* d_in, const int* in_sizes, int n_in,
                              void* d_out, int out_size)
{
    (void)in_sizes; (void)n_in; (void)out_size;
    const float* x  = (const float*)d_in[0];
    const float* Wq = (const float*)d_in[1];
    const float* bq = (const float*)d_in[2];
    const float* Wk = (const float*)d_in[3];
    const float* bk = (const float*)d_in[4];
    const float* Wv = (const float*)d_in[5];
    const float* bv = (const float*)d_in[6];
    const float* Wo = (const float*)d_in[7];
    const float* bo = (const float*)d_in[8];
    float* out = (float*)d_out;

    prep_x<<<(MROWS*DMODEL/4)/256, 256>>>(x);
    dim3 wt(DMODEL/32, DMODEL/32);
    prep_wt<0><<<wt, 256>>>(Wq);
    prep_wt<1><<<wt, 256>>>(Wk);
    prep_wt<2><<<wt, 256>>>(Wv);
    prep_wt<3><<<wt, 256>>>(Wo);

    cudaFuncSetAttribute(gemm_bf<1>, cudaFuncAttributeMaxDynamicSharedMemorySize, GEMM_SMEM);
    cudaFuncSetAttribute(gemm_bf<2>, cudaFuncAttributeMaxDynamicSharedMemorySize, GEMM_SMEM);
    cudaFuncSetAttribute(gemm_bf<3>, cudaFuncAttributeMaxDynamicSharedMemorySize, GEMM_SMEM);
    cudaFuncSetAttribute(gemm_bf<4>, cudaFuncAttributeMaxDynamicSharedMemorySize, GEMM_SMEM);
    cudaFuncSetAttribute(attn_bf, cudaFuncAttributeMaxDynamicSharedMemorySize, ATTN_SMEM);

    dim3 gg(MROWS/128, DMODEL/128);   // (64, 6)
    gemm_bf<1><<<gg, 256, GEMM_SMEM>>>(bq, nullptr);
    gemm_bf<2><<<gg, 256, GEMM_SMEM>>>(bk, nullptr);
    gemm_bf<3><<<gg, 256, GEMM_SMEM>>>(bv, nullptr);

    attn_bf<<<dim3(SEQ/64, BATCH*NHEAD), 256, ATTN_SMEM>>>();

    gemm_bf<4><<<gg, 256, GEMM_SMEM>>>(bo, out);
}

// round 8
// speedup vs baseline: 3.5766x; 1.3869x over previous
#include <cuda_runtime.h>
#include <cuda_bf16.h>
#include <math.h>
#include <stdint.h>

#define BATCH 8
#define SEQ 1024
#define DMODEL 768
#define NHEAD 12
#define HDIM 64
#define MROWS (BATCH*SEQ)

// ------------------------- device scratch (no allocs) -----------------------
__device__ __align__(16) __nv_bfloat16 g_xh[MROWS*DMODEL];      // x split [M][K]
__device__ __align__(16) __nv_bfloat16 g_xl[MROWS*DMODEL];
__device__ __align__(16) __nv_bfloat16 g_wth[4][DMODEL*DMODEL]; // W^T split [N][K]
__device__ __align__(16) __nv_bfloat16 g_wtl[4][DMODEL*DMODEL];
__device__ __align__(16) __nv_bfloat16 g_qh[MROWS*DMODEL];      // Q/8 split [bh][s][d]
__device__ __align__(16) __nv_bfloat16 g_ql[MROWS*DMODEL];
__device__ __align__(16) __nv_bfloat16 g_kh[MROWS*DMODEL];      // K split [bh][s][d]
__device__ __align__(16) __nv_bfloat16 g_kl[MROWS*DMODEL];
__device__ __align__(16) __nv_bfloat16 g_vth[MROWS*DMODEL];     // V split TRANSPOSED [bh][d][s]
__device__ __align__(16) __nv_bfloat16 g_vtl[MROWS*DMODEL];
__device__ __align__(16) __nv_bfloat16 g_ah[MROWS*DMODEL];      // attn out split [M][K]
__device__ __align__(16) __nv_bfloat16 g_al[MROWS*DMODEL];

// ------------------------- helpers ------------------------------------------
__device__ __forceinline__ void bsplit(float x, __nv_bfloat16& h, __nv_bfloat16& l) {
    h = __float2bfloat16_rn(x);
    l = __float2bfloat16_rn(x - __bfloat162float(h));
}
__device__ __forceinline__ void mma16(float c[4], const uint32_t a[4],
                                      uint32_t b0, uint32_t b1) {
    asm volatile("mma.sync.aligned.m16n8k16.row.col.f32.bf16.bf16.f32 "
        "{%0,%1,%2,%3}, {%4,%5,%6,%7}, {%8,%9}, {%0,%1,%2,%3};"
        : "+f"(c[0]), "+f"(c[1]), "+f"(c[2]), "+f"(c[3])
        : "r"(a[0]), "r"(a[1]), "r"(a[2]), "r"(a[3]), "r"(b0), "r"(b1));
}
__device__ __forceinline__ uint32_t sm_addr(const void* p) {
    return (uint32_t)__cvta_generic_to_shared(p);
}
__device__ __forceinline__ void ldsm_x4(uint32_t& r0, uint32_t& r1, uint32_t& r2,
                                        uint32_t& r3, uint32_t addr) {
    asm volatile("ldmatrix.sync.aligned.m8n8.x4.shared.b16 {%0,%1,%2,%3}, [%4];"
        : "=r"(r0), "=r"(r1), "=r"(r2), "=r"(r3) : "r"(addr));
}
__device__ __forceinline__ void cp16(void* dst, const void* src) {
    asm volatile("cp.async.cg.shared.global [%0], [%1], 16;"
        :: "r"(sm_addr(dst)), "l"(src));
}
#define CP_COMMIT() asm volatile("cp.async.commit_group;" ::: "memory")
#define CP_WAIT(n)  asm volatile("cp.async.wait_group %0;" :: "n"(n) : "memory")
// pack two floats' bf16-high / bf16-low parts
__device__ __forceinline__ void packsplit(float x, float y, uint32_t& H, uint32_t& L) {
    union { __nv_bfloat16 bb[2]; uint32_t u; } Hu, Lu;
    bsplit(x, Hu.bb[0], Lu.bb[0]);
    bsplit(y, Hu.bb[1], Lu.bb[1]);
    H = Hu.u; L = Lu.u;
}

// ------------------------- prep kernels -------------------------------------
__global__ void __launch_bounds__(256) prep_x(const float* __restrict__ x)
{
    const int i = blockIdx.x * 256 + threadIdx.x;   // float4 index
    float4 v = ((const float4*)x)[i];
    union { __nv_bfloat16 b[4]; uint2 u; } H, L;
    bsplit(v.x, H.b[0], L.b[0]); bsplit(v.y, H.b[1], L.b[1]);
    bsplit(v.z, H.b[2], L.b[2]); bsplit(v.w, H.b[3], L.b[3]);
    ((uint2*)g_xh)[i] = H.u;
    ((uint2*)g_xl)[i] = L.u;
}

__global__ void __launch_bounds__(256) prep_wt(const float* __restrict__ Wq,
                                               const float* __restrict__ Wk,
                                               const float* __restrict__ Wv,
                                               const float* __restrict__ Wo)
{
    __shared__ float tile[32][33];
    const int wid = blockIdx.z;
    const float* W = (wid == 0) ? Wq : (wid == 1) ? Wk : (wid == 2) ? Wv : Wo;
    const int n0 = blockIdx.x * 32, k0 = blockIdx.y * 32;
    const int tx = threadIdx.x & 31, ty = threadIdx.x >> 5;  // 32x8
    #pragma unroll
    for (int i = 0; i < 32; i += 8)
        tile[ty + i][tx] = W[(size_t)(k0 + ty + i) * DMODEL + n0 + tx];
    __syncthreads();
    #pragma unroll
    for (int i = 0; i < 32; i += 8) {
        float v = tile[tx][ty + i];
        __nv_bfloat16 h, l; bsplit(v, h, l);
        g_wth[wid][(size_t)(n0 + ty + i) * DMODEL + k0 + tx] = h;
        g_wtl[wid][(size_t)(n0 + ty + i) * DMODEL + k0 + tx] = l;
    }
}

// ------------------------- bf16 split GEMM (ldmatrix + cp.async x2) ---------
// MODE 0: fused QKV (blockIdx.z selects W/bias/output)   MODE 4: O proj -> fp32
#define GSTR 40
#define GTILE (128*GSTR)
#define GEMM_SMEM (2*4*GTILE*2)               // 81,920 B

template<int MODE>
__global__ void __launch_bounds__(256, 2) gemm_bf(const float* __restrict__ b0p,
                                                  const float* __restrict__ b1p,
                                                  const float* __restrict__ b2p,
                                                  float* __restrict__ Cout)
{
    extern __shared__ __align__(16) char gsm[];
    __nv_bfloat16* Sm = (__nv_bfloat16*)gsm;

    const int z = (MODE == 0) ? blockIdx.z : 3;
    const __nv_bfloat16* gAh = (MODE == 4) ? g_ah : g_xh;
    const __nv_bfloat16* gAl = (MODE == 4) ? g_al : g_xl;
    const __nv_bfloat16* gBh = g_wth[z];
    const __nv_bfloat16* gBl = g_wtl[z];
    const float* bias = (MODE == 4) ? b0p : (z == 0) ? b0p : (z == 1) ? b1p : b2p;

    const int bm = blockIdx.x * 128, bn = blockIdx.y * 128;
    const int t = threadIdx.x, lane = t & 31, w = t >> 5;
    const int wm = (w >> 2) * 64, wn = (w & 3) * 32;

    float acc[4][4][4];
    #pragma unroll
    for (int i = 0; i < 4; i++)
        #pragma unroll
        for (int j = 0; j < 4; j++)
            #pragma unroll
            for (int q = 0; q < 4; q++) acc[i][j][q] = 0.f;

    auto prefetch = [&](int kt, int stage) {
        const int k0 = kt * 32;
        __nv_bfloat16* base = Sm + stage * 4 * GTILE;
        #pragma unroll
        for (int i = 0; i < 8; i++) {
            const int c = t + i * 256;
            const int tile = c >> 9, cc = c & 511;
            const int row = cc >> 2, col = (cc & 3) * 8;
            const __nv_bfloat16* g = (tile == 0) ? gAh : (tile == 1) ? gAl
                                   : (tile == 2) ? gBh : gBl;
            const int gr = ((tile < 2) ? bm : bn) + row;
            cp16(base + tile * GTILE + row * GSTR + col,
                 g + (size_t)gr * DMODEL + k0 + col);
        }
        CP_COMMIT();
    };

    prefetch(0, 0);

    const int laneA = (lane & 15) * GSTR + (lane >> 4) * 8;
    const int laneB = ((lane & 7) + ((lane >> 4) & 1) * 8) * GSTR + ((lane >> 3) & 1) * 8;

    for (int kt = 0; kt < 24; kt++) {
        const int stage = kt & 1;
        if (kt + 1 < 24) { prefetch(kt + 1, stage ^ 1); CP_WAIT(1); }
        else             { CP_WAIT(0); }
        __syncthreads();

        const __nv_bfloat16* Ah = Sm + (stage * 4 + 0) * GTILE;
        const __nv_bfloat16* Al = Sm + (stage * 4 + 1) * GTILE;
        const __nv_bfloat16* Bh = Sm + (stage * 4 + 2) * GTILE;
        const __nv_bfloat16* Bl = Sm + (stage * 4 + 3) * GTILE;

        #pragma unroll
        for (int ks = 0; ks < 32; ks += 16) {
            uint32_t bh_[2][4], bl_[2][4];
            #pragma unroll
            for (int p = 0; p < 2; p++) {
                const int off = (wn + p * 16) * GSTR + ks + laneB;
                ldsm_x4(bh_[p][0], bh_[p][1], bh_[p][2], bh_[p][3], sm_addr(Bh + off));
                ldsm_x4(bl_[p][0], bl_[p][1], bl_[p][2], bl_[p][3], sm_addr(Bl + off));
            }
            #pragma unroll
            for (int mt_ = 0; mt_ < 4; mt_++) {
                const int off = (wm + mt_ * 16) * GSTR + ks + laneA;
                uint32_t ah_[4], al_[4];
                ldsm_x4(ah_[0], ah_[1], ah_[2], ah_[3], sm_addr(Ah + off));
                ldsm_x4(al_[0], al_[1], al_[2], al_[3], sm_addr(Al + off));
                #pragma unroll
                for (int p = 0; p < 2; p++) {
                    mma16(acc[mt_][2*p],   ah_, bh_[p][0], bh_[p][1]);
                    mma16(acc[mt_][2*p],   ah_, bl_[p][0], bl_[p][1]);
                    mma16(acc[mt_][2*p],   al_, bh_[p][0], bh_[p][1]);
                    mma16(acc[mt_][2*p+1], ah_, bh_[p][2], bh_[p][3]);
                    mma16(acc[mt_][2*p+1], ah_, bl_[p][2], bl_[p][3]);
                    mma16(acc[mt_][2*p+1], al_, bh_[p][2], bh_[p][3]);
                }
            }
        }
        __syncthreads();
    }

    // ---- epilogue ----
    #pragma unroll
    for (int mt_ = 0; mt_ < 4; mt_++) {
        #pragma unroll
        for (int nt = 0; nt < 4; nt++) {
            const int n0 = bn + wn + nt*8 + 2*(lane & 3);
            const float bb0 = bias[n0], bb1 = bias[n0+1];
            #pragma unroll
            for (int half = 0; half < 2; half++) {
                const int r = bm + wm + mt_*16 + (lane >> 2) + half*8;
                float c0 = acc[mt_][nt][half*2+0] + bb0;
                float c1 = acc[mt_][nt][half*2+1] + bb1;
                if (MODE == 4) {
                    *(float2*)&Cout[(size_t)r*DMODEL + n0] = make_float2(c0, c1);
                } else {
                    const int b_ = r >> 10, s = r & (SEQ-1);
                    const int h_ = n0 >> 6, d = n0 & 63;
                    const int bh_i = b_ * NHEAD + h_;
                    if (z == 0) { c0 *= 0.125f; c1 *= 0.125f; }
                    uint32_t Hu, Lu;
                    packsplit(c0, c1, Hu, Lu);
                    if (z == 0 || z == 1) {
                        __nv_bfloat16* Hd = (z == 0) ? g_qh : g_kh;
                        __nv_bfloat16* Ld = (z == 0) ? g_ql : g_kl;
                        const size_t o = ((size_t)bh_i*SEQ + s)*HDIM + d;
                        *(uint32_t*)&Hd[o] = Hu;
                        *(uint32_t*)&Ld[o] = Lu;
                    } else {          // z==2: V transposed [bh][d][s]
                        union { __nv_bfloat16 bb[2]; uint32_t u; } hu, lu;
                        hu.u = Hu; lu.u = Lu;
                        const size_t o0 = ((size_t)bh_i*HDIM + d)*SEQ + s;
                        const size_t o1 = ((size_t)bh_i*HDIM + d+1)*SEQ + s;
                        g_vth[o0] = hu.bb[0]; g_vtl[o0] = lu.bb[0];
                        g_vth[o1] = hu.bb[1]; g_vtl[o1] = lu.bb[1];
                    }
                }
            }
        }
    }
}

// ------------------------- flash attention v3 --------------------------------
// 8 warps: warp w -> q rows mt=(w&3)*16, key-half wg=w>>2 (keys wn=wg*32).
// In-register softmax; P fragments straight from S accumulators; each warp
// accumulates PV partial over its 32 keys x all 64 dims; merge at end.
// K/V double-buffered via cp.async.
#define ASTR 72
#define KVTILE (64*ASTR)
#define OSTR 66
#define ATTN_SMEM ((2*KVTILE + 8*KVTILE)*2 + (2*64 + 2*64 + 64 + 64)*4)  // 93,696 B

__global__ void __launch_bounds__(256, 2) attn_bf()
{
    extern __shared__ __align__(16) char smraw[];
    __nv_bfloat16* Qh = (__nv_bfloat16*)smraw;
    __nv_bfloat16* Ql = Qh + KVTILE;
    __nv_bfloat16* KV = Ql + KVTILE;               // [2 stages][Kh,Kl,Vh,Vl]
    float* pmax = (float*)(KV + 8*KVTILE);         // [2][64]
    float* psum = pmax + 128;                      // [2][64]
    float* m_s  = psum + 128;                      // [64]
    float* l_s  = m_s + 64;                        // [64]
    float* Omrg = (float*)KV;                      // overlay after mainloop

    const int t = threadIdx.x, lane = t & 31, w = t >> 5;
    const int qt = blockIdx.x, bh = blockIdx.y;
    const int mt = (w & 3) * 16;
    const int wg = w >> 2;
    const int wn = wg * 32;

    const size_t qoff = ((size_t)bh*SEQ + qt*64)*HDIM;
    const size_t koff = (size_t)bh*SEQ*HDIM;

    const int laneA = (lane & 15) * ASTR + (lane >> 4) * 8;
    const int laneB = ((lane & 7) + ((lane >> 4) & 1) * 8) * ASTR + ((lane >> 3) & 1) * 8;

    // Q load (group 0)
    #pragma unroll
    for (int i = 0; i < 4; i++) {
        const int c = t + i * 256;
        const int tile = c >> 9, cc = c & 511;
        const int r = cc >> 3, col = (cc & 7) * 8;
        cp16((tile ? Ql : Qh) + r*ASTR + col,
             (tile ? g_ql : g_qh) + qoff + r*HDIM + col);
    }
    CP_COMMIT();

    auto prefetch = [&](int kt, int st) {
        __nv_bfloat16* base = KV + st * 4 * KVTILE;
        #pragma unroll
        for (int i = 0; i < 8; i++) {
            const int c = t + i * 256;
            const int tile = c >> 9, cc = c & 511;
            const int r = cc >> 3, col = (cc & 7) * 8;
            const __nv_bfloat16* g; size_t src;
            if (tile < 2) { g = tile ? g_kl : g_kh; src = koff + (size_t)(kt*64 + r)*HDIM + col; }
            else          { g = (tile == 3) ? g_vtl : g_vth; src = koff + (size_t)r*SEQ + kt*64 + col; }
            cp16(base + tile*KVTILE + r*ASTR + col, g + src);
        }
        CP_COMMIT();
    };

    prefetch(0, 0);
    if (t < 64) { m_s[t] = -1e30f; l_s[t] = 0.f; }
    CP_WAIT(1);            // Q group done
    __syncthreads();

    // hoist Q fragments
    uint32_t qh_[4][4], ql_[4][4];
    #pragma unroll
    for (int ks4 = 0; ks4 < 4; ks4++) {
        const int off = mt*ASTR + ks4*16 + laneA;
        ldsm_x4(qh_[ks4][0], qh_[ks4][1], qh_[ks4][2], qh_[ks4][3], sm_addr(Qh + off));
        ldsm_x4(ql_[ks4][0], ql_[ks4][1], ql_[ks4][2], ql_[ks4][3], sm_addr(Ql + off));
    }

    float o[8][4];
    #pragma unroll
    for (int i = 0; i < 8; i++)
        #pragma unroll
        for (int j = 0; j < 4; j++) o[i][j] = 0.f;

    const int r0 = mt + (lane >> 2);           // this thread's first q row
    const int wrt = ((lane & 3) == 0);         // row-stat writer lanes

    for (int kt = 0; kt < SEQ/64; kt++) {
        const int st = kt & 1;
        if (kt + 1 < SEQ/64) { prefetch(kt + 1, st ^ 1); CP_WAIT(1); }
        else                 { CP_WAIT(0); }
        __syncthreads();                                    // (a) KV ready

        const __nv_bfloat16* Kh = KV + (st*4 + 0)*KVTILE;
        const __nv_bfloat16* Kl = KV + (st*4 + 1)*KVTILE;
        const __nv_bfloat16* Vh = KV + (st*4 + 2)*KVTILE;
        const __nv_bfloat16* Vl = KV + (st*4 + 3)*KVTILE;

        // ---- S = Q K^T (warp's 32 keys) ----
        float sc[4][4];
        #pragma unroll
        for (int i = 0; i < 4; i++)
            #pragma unroll
            for (int j = 0; j < 4; j++) sc[i][j] = 0.f;

        #pragma unroll
        for (int ks4 = 0; ks4 < 4; ks4++) {
            uint32_t kh_[2][4], kl_[2][4];
            #pragma unroll
            for (int p = 0; p < 2; p++) {
                const int off = (wn + p*16)*ASTR + ks4*16 + laneB;
                ldsm_x4(kh_[p][0], kh_[p][1], kh_[p][2], kh_[p][3], sm_addr(Kh + off));
                ldsm_x4(kl_[p][0], kl_[p][1], kl_[p][2], kl_[p][3], sm_addr(Kl + off));
            }
            #pragma unroll
            for (int p = 0; p < 2; p++) {
                mma16(sc[2*p],   qh_[ks4], kh_[p][0], kh_[p][1]);
                mma16(sc[2*p],   qh_[ks4], kl_[p][0], kl_[p][1]);
                mma16(sc[2*p],   ql_[ks4], kh_[p][0], kh_[p][1]);
                mma16(sc[2*p+1], qh_[ks4], kh_[p][2], kh_[p][3]);
                mma16(sc[2*p+1], qh_[ks4], kl_[p][2], kl_[p][3]);
                mma16(sc[2*p+1], ql_[ks4], kh_[p][2], kh_[p][3]);
            }
        }

        // ---- partial row max (this warp's 32 cols) ----
        float mx0 = sc[0][0], mx1 = sc[0][2];
        #pragma unroll
        for (int nt = 0; nt < 4; nt++) {
            mx0 = fmaxf(mx0, fmaxf(sc[nt][0], sc[nt][1]));
            mx1 = fmaxf(mx1, fmaxf(sc[nt][2], sc[nt][3]));
        }
        mx0 = fmaxf(mx0, __shfl_xor_sync(0xffffffffu, mx0, 1));
        mx0 = fmaxf(mx0, __shfl_xor_sync(0xffffffffu, mx0, 2));
        mx1 = fmaxf(mx1, __shfl_xor_sync(0xffffffffu, mx1, 1));
        mx1 = fmaxf(mx1, __shfl_xor_sync(0xffffffffu, mx1, 2));
        if (wrt) { pmax[wg*64 + r0] = mx0; pmax[wg*64 + r0 + 8] = mx1; }
        __syncthreads();                                    // (b)

        const float m_old0 = m_s[r0], m_old1 = m_s[r0 + 8];
        const float m_new0 = fmaxf(m_old0, fmaxf(pmax[r0],     pmax[64 + r0]));
        const float m_new1 = fmaxf(m_old1, fmaxf(pmax[r0 + 8], pmax[64 + r0 + 8]));
        const float cr0 = __expf(m_old0 - m_new0);
        const float cr1 = __expf(m_old1 - m_new1);

        // exp + partial row sums
        float s0 = 0.f, s1 = 0.f;
        #pragma unroll
        for (int nt = 0; nt < 4; nt++) {
            sc[nt][0] = __expf(sc[nt][0] - m_new0);
            sc[nt][1] = __expf(sc[nt][1] - m_new0);
            sc[nt][2] = __expf(sc[nt][2] - m_new1);
            sc[nt][3] = __expf(sc[nt][3] - m_new1);
            s0 += sc[nt][0] + sc[nt][1];
            s1 += sc[nt][2] + sc[nt][3];
        }
        s0 += __shfl_xor_sync(0xffffffffu, s0, 1);
        s0 += __shfl_xor_sync(0xffffffffu, s0, 2);
        s1 += __shfl_xor_sync(0xffffffffu, s1, 1);
        s1 += __shfl_xor_sync(0xffffffffu, s1, 2);
        if (wrt) { psum[wg*64 + r0] = s0; psum[wg*64 + r0 + 8] = s1; }

        // rescale O partials
        #pragma unroll
        for (int nt = 0; nt < 8; nt++) {
            o[nt][0] *= cr0; o[nt][1] *= cr0;
            o[nt][2] *= cr1; o[nt][3] *= cr1;
        }
        __syncthreads();                                    // (c)

        if (wg == 0 && wrt) {
            l_s[r0]     = l_s[r0]*cr0     + psum[r0]     + psum[64 + r0];
            l_s[r0 + 8] = l_s[r0 + 8]*cr1 + psum[r0 + 8] + psum[64 + r0 + 8];
            m_s[r0] = m_new0; m_s[r0 + 8] = m_new1;
        }

        // ---- P fragments straight from accumulators ----
        uint32_t ph_[2][4], pl_[2][4];
        #pragma unroll
        for (int c = 0; c < 2; c++) {
            packsplit(sc[2*c][0],   sc[2*c][1],   ph_[c][0], pl_[c][0]);
            packsplit(sc[2*c][2],   sc[2*c][3],   ph_[c][1], pl_[c][1]);
            packsplit(sc[2*c+1][0], sc[2*c+1][1], ph_[c][2], pl_[c][2]);
            packsplit(sc[2*c+1][2], sc[2*c+1][3], ph_[c][3], pl_[c][3]);
        }

        // ---- O += P V over this warp's 32 keys, all 64 dims ----
        #pragma unroll
        for (int c = 0; c < 2; c++) {
            #pragma unroll
            for (int p = 0; p < 4; p++) {
                uint32_t vh_[4], vl_[4];
                const int off = (p*16)*ASTR + wn + c*16 + laneB;
                ldsm_x4(vh_[0], vh_[1], vh_[2], vh_[3], sm_addr(Vh + off));
                ldsm_x4(vl_[0], vl_[1], vl_[2], vl_[3], sm_addr(Vl + off));
                mma16(o[2*p],   ph_[c], vh_[0], vh_[1]);
                mma16(o[2*p],   ph_[c], vl_[0], vl_[1]);
                mma16(o[2*p],   pl_[c], vh_[0], vh_[1]);
                mma16(o[2*p+1], ph_[c], vh_[2], vh_[3]);
                mma16(o[2*p+1], ph_[c], vl_[2], vl_[3]);
                mma16(o[2*p+1], pl_[c], vh_[2], vh_[3]);
            }
        }
        __syncthreads();                                    // (d)
    }

    // ---- merge the two key-half partials, normalize, store split-bf16 ----
    if (wg == 1) {
        #pragma unroll
        for (int nt = 0; nt < 8; nt++) {
            const int cc = nt*8 + 2*(lane & 3);
            *(float2*)&Omrg[r0*OSTR + cc]       = make_float2(o[nt][0], o[nt][1]);
            *(float2*)&Omrg[(r0 + 8)*OSTR + cc] = make_float2(o[nt][2], o[nt][3]);
        }
    }
    __syncthreads();
    if (wg == 0) {
        const int b_ = bh / NHEAD, h_ = bh % NHEAD;
        const float inv0 = 1.f / l_s[r0], inv1 = 1.f / l_s[r0 + 8];
        const size_t row0 = (size_t)b_*SEQ + qt*64 + r0;
        #pragma unroll
        for (int nt = 0; nt < 8; nt++) {
            const int cc = nt*8 + 2*(lane & 3);
            float2 a0 = *(const float2*)&Omrg[r0*OSTR + cc];
            float2 a1 = *(const float2*)&Omrg[(r0 + 8)*OSTR + cc];
            uint32_t Hu, Lu;
            packsplit((o[nt][0] + a0.x)*inv0, (o[nt][1] + a0.y)*inv0, Hu, Lu);
            *(uint32_t*)&g_ah[row0*DMODEL + h_*HDIM + cc] = Hu;
            *(uint32_t*)&g_al[row0*DMODEL + h_*HDIM + cc] = Lu;
            packsplit((o[nt][2] + a1.x)*inv1, (o[nt][3] + a1.y)*inv1, Hu, Lu);
            *(uint32_t*)&g_ah[(row0 + 8)*DMODEL + h_*HDIM + cc] = Hu;
            *(uint32_t*)&g_al[(row0 + 8)*DMODEL + h_*HDIM + cc] = Lu;
        }
    }
}

// ---------------------------------------------------------------------------
extern "C" void kernel_launch(void* const* d_in, const int* in_sizes, int n_in,
                              void* d_out, int out_size)
{
    (void)in_sizes; (void)n_in; (void)out_size;
    const float* x  = (const float*)d_in[0];
    const float* Wq = (const float*)d_in[1];
    const float* bq = (const float*)d_in[2];
    const float* Wk = (const float*)d_in[3];
    const float* bk = (const float*)d_in[4];
    const float* Wv = (const float*)d_in[5];
    const float* bv = (const float*)d_in[6];
    const float* Wo = (const float*)d_in[7];
    const float* bo = (const float*)d_in[8];
    float* out = (float*)d_out;

    prep_x<<<(MROWS*DMODEL/4)/256, 256>>>(x);
    prep_wt<<<dim3(DMODEL/32, DMODEL/32, 4), 256>>>(Wq, Wk, Wv, Wo);

    cudaFuncSetAttribute(gemm_bf<0>, cudaFuncAttributeMaxDynamicSharedMemorySize, GEMM_SMEM);
    cudaFuncSetAttribute(gemm_bf<4>, cudaFuncAttributeMaxDynamicSharedMemorySize, GEMM_SMEM);
    cudaFuncSetAttribute(attn_bf, cudaFuncAttributeMaxDynamicSharedMemorySize, ATTN_SMEM);

    dim3 gq(MROWS/128, DMODEL/128, 3);   // fused QKV
    gemm_bf<0><<<gq, 256, GEMM_SMEM>>>(bq, bk, bv, nullptr);

    attn_bf<<<dim3(SEQ/64, BATCH*NHEAD), 256, ATTN_SMEM>>>();

    dim3 gg(MROWS/128, DMODEL/128);
    gemm_bf<4><<<gg, 256, GEMM_SMEM>>>(bo, nullptr, nullptr, out);
}

// round 9
// speedup vs baseline: 3.7580x; 1.0507x over previous
#include <cuda_runtime.h>
#include <cuda_bf16.h>
#include <math.h>
#include <stdint.h>

#define BATCH 8
#define SEQ 1024
#define DMODEL 768
#define NHEAD 12
#define HDIM 64
#define MROWS (BATCH*SEQ)

// ------------------------- device scratch (no allocs) -----------------------
__device__ __align__(16) __nv_bfloat16 g_xh[MROWS*DMODEL];      // x split [M][K]
__device__ __align__(16) __nv_bfloat16 g_xl[MROWS*DMODEL];
__device__ __align__(16) __nv_bfloat16 g_wth[4][DMODEL*DMODEL]; // W^T split [N][K]
__device__ __align__(16) __nv_bfloat16 g_wtl[4][DMODEL*DMODEL];
__device__ __align__(16) __nv_bfloat16 g_qh[MROWS*DMODEL];      // Q/8 split [bh][s][d]
__device__ __align__(16) __nv_bfloat16 g_ql[MROWS*DMODEL];
__device__ __align__(16) __nv_bfloat16 g_kh[MROWS*DMODEL];      // K split [bh][s][d]
__device__ __align__(16) __nv_bfloat16 g_kl[MROWS*DMODEL];
__device__ __align__(16) __nv_bfloat16 g_vth[MROWS*DMODEL];     // V split TRANSPOSED [bh][d][s]
__device__ __align__(16) __nv_bfloat16 g_vtl[MROWS*DMODEL];
__device__ __align__(16) __nv_bfloat16 g_ah[MROWS*DMODEL];      // attn out split [M][K]
__device__ __align__(16) __nv_bfloat16 g_al[MROWS*DMODEL];

// ------------------------- helpers ------------------------------------------
__device__ __forceinline__ void bsplit(float x, __nv_bfloat16& h, __nv_bfloat16& l) {
    h = __float2bfloat16_rn(x);
    l = __float2bfloat16_rn(x - __bfloat162float(h));
}
__device__ __forceinline__ void mma16(float c[4], const uint32_t a[4],
                                      uint32_t b0, uint32_t b1) {
    asm volatile("mma.sync.aligned.m16n8k16.row.col.f32.bf16.bf16.f32 "
        "{%0,%1,%2,%3}, {%4,%5,%6,%7}, {%8,%9}, {%0,%1,%2,%3};"
        : "+f"(c[0]), "+f"(c[1]), "+f"(c[2]), "+f"(c[3])
        : "r"(a[0]), "r"(a[1]), "r"(a[2]), "r"(a[3]), "r"(b0), "r"(b1));
}
__device__ __forceinline__ uint32_t sm_addr(const void* p) {
    return (uint32_t)__cvta_generic_to_shared(p);
}
__device__ __forceinline__ void ldsm_x4(uint32_t& r0, uint32_t& r1, uint32_t& r2,
                                        uint32_t& r3, uint32_t addr) {
    asm volatile("ldmatrix.sync.aligned.m8n8.x4.shared.b16 {%0,%1,%2,%3}, [%4];"
        : "=r"(r0), "=r"(r1), "=r"(r2), "=r"(r3) : "r"(addr));
}
__device__ __forceinline__ void cp16(void* dst, const void* src) {
    asm volatile("cp.async.cg.shared.global [%0], [%1], 16;"
        :: "r"(sm_addr(dst)), "l"(src));
}
#define CP_COMMIT() asm volatile("cp.async.commit_group;" ::: "memory")
#define CP_WAIT(n)  asm volatile("cp.async.wait_group %0;" :: "n"(n) : "memory")
__device__ __forceinline__ void packsplit(float x, float y, uint32_t& H, uint32_t& L) {
    union { __nv_bfloat16 bb[2]; uint32_t u; } Hu, Lu;
    bsplit(x, Hu.bb[0], Lu.bb[0]);
    bsplit(y, Hu.bb[1], Lu.bb[1]);
    H = Hu.u; L = Lu.u;
}

// ------------------------- prep kernels -------------------------------------
__global__ void __launch_bounds__(256) prep_x(const float* __restrict__ x)
{
    const int i = blockIdx.x * 256 + threadIdx.x;
    float4 v = ((const float4*)x)[i];
    union { __nv_bfloat16 b[4]; uint2 u; } H, L;
    bsplit(v.x, H.b[0], L.b[0]); bsplit(v.y, H.b[1], L.b[1]);
    bsplit(v.z, H.b[2], L.b[2]); bsplit(v.w, H.b[3], L.b[3]);
    ((uint2*)g_xh)[i] = H.u;
    ((uint2*)g_xl)[i] = L.u;
}

__global__ void __launch_bounds__(256) prep_wt(const float* __restrict__ Wq,
                                               const float* __restrict__ Wk,
                                               const float* __restrict__ Wv,
                                               const float* __restrict__ Wo)
{
    __shared__ float tile[32][33];
    const int wid = blockIdx.z;
    const float* W = (wid == 0) ? Wq : (wid == 1) ? Wk : (wid == 2) ? Wv : Wo;
    const int n0 = blockIdx.x * 32, k0 = blockIdx.y * 32;
    const int tx = threadIdx.x & 31, ty = threadIdx.x >> 5;
    #pragma unroll
    for (int i = 0; i < 32; i += 8)
        tile[ty + i][tx] = W[(size_t)(k0 + ty + i) * DMODEL + n0 + tx];
    __syncthreads();
    #pragma unroll
    for (int i = 0; i < 32; i += 8) {
        float v = tile[tx][ty + i];
        __nv_bfloat16 h, l; bsplit(v, h, l);
        g_wth[wid][(size_t)(n0 + ty + i) * DMODEL + k0 + tx] = h;
        g_wtl[wid][(size_t)(n0 + ty + i) * DMODEL + k0 + tx] = l;
    }
}

// ------------------------- bf16 split GEMM (unchanged from R8) ---------------
#define GSTR 40
#define GTILE (128*GSTR)
#define GEMM_SMEM (2*4*GTILE*2)               // 81,920 B

template<int MODE>
__global__ void __launch_bounds__(256, 2) gemm_bf(const float* __restrict__ b0p,
                                                  const float* __restrict__ b1p,
                                                  const float* __restrict__ b2p,
                                                  float* __restrict__ Cout)
{
    extern __shared__ __align__(16) char gsm[];
    __nv_bfloat16* Sm = (__nv_bfloat16*)gsm;

    const int z = (MODE == 0) ? blockIdx.z : 3;
    const __nv_bfloat16* gAh = (MODE == 4) ? g_ah : g_xh;
    const __nv_bfloat16* gAl = (MODE == 4) ? g_al : g_xl;
    const __nv_bfloat16* gBh = g_wth[z];
    const __nv_bfloat16* gBl = g_wtl[z];
    const float* bias = (MODE == 4) ? b0p : (z == 0) ? b0p : (z == 1) ? b1p : b2p;

    const int bm = blockIdx.x * 128, bn = blockIdx.y * 128;
    const int t = threadIdx.x, lane = t & 31, w = t >> 5;
    const int wm = (w >> 2) * 64, wn = (w & 3) * 32;

    float acc[4][4][4];
    #pragma unroll
    for (int i = 0; i < 4; i++)
        #pragma unroll
        for (int j = 0; j < 4; j++)
            #pragma unroll
            for (int q = 0; q < 4; q++) acc[i][j][q] = 0.f;

    auto prefetch = [&](int kt, int stage) {
        const int k0 = kt * 32;
        __nv_bfloat16* base = Sm + stage * 4 * GTILE;
        #pragma unroll
        for (int i = 0; i < 8; i++) {
            const int c = t + i * 256;
            const int tile = c >> 9, cc = c & 511;
            const int row = cc >> 2, col = (cc & 3) * 8;
            const __nv_bfloat16* g = (tile == 0) ? gAh : (tile == 1) ? gAl
                                   : (tile == 2) ? gBh : gBl;
            const int gr = ((tile < 2) ? bm : bn) + row;
            cp16(base + tile * GTILE + row * GSTR + col,
                 g + (size_t)gr * DMODEL + k0 + col);
        }
        CP_COMMIT();
    };

    prefetch(0, 0);

    const int laneA = (lane & 15) * GSTR + (lane >> 4) * 8;
    const int laneB = ((lane & 7) + ((lane >> 4) & 1) * 8) * GSTR + ((lane >> 3) & 1) * 8;

    for (int kt = 0; kt < 24; kt++) {
        const int stage = kt & 1;
        if (kt + 1 < 24) { prefetch(kt + 1, stage ^ 1); CP_WAIT(1); }
        else             { CP_WAIT(0); }
        __syncthreads();

        const __nv_bfloat16* Ah = Sm + (stage * 4 + 0) * GTILE;
        const __nv_bfloat16* Al = Sm + (stage * 4 + 1) * GTILE;
        const __nv_bfloat16* Bh = Sm + (stage * 4 + 2) * GTILE;
        const __nv_bfloat16* Bl = Sm + (stage * 4 + 3) * GTILE;

        #pragma unroll
        for (int ks = 0; ks < 32; ks += 16) {
            uint32_t bh_[2][4], bl_[2][4];
            #pragma unroll
            for (int p = 0; p < 2; p++) {
                const int off = (wn + p * 16) * GSTR + ks + laneB;
                ldsm_x4(bh_[p][0], bh_[p][1], bh_[p][2], bh_[p][3], sm_addr(Bh + off));
                ldsm_x4(bl_[p][0], bl_[p][1], bl_[p][2], bl_[p][3], sm_addr(Bl + off));
            }
            #pragma unroll
            for (int mt_ = 0; mt_ < 4; mt_++) {
                const int off = (wm + mt_ * 16) * GSTR + ks + laneA;
                uint32_t ah_[4], al_[4];
                ldsm_x4(ah_[0], ah_[1], ah_[2], ah_[3], sm_addr(Ah + off));
                ldsm_x4(al_[0], al_[1], al_[2], al_[3], sm_addr(Al + off));
                #pragma unroll
                for (int p = 0; p < 2; p++) {
                    mma16(acc[mt_][2*p],   ah_, bh_[p][0], bh_[p][1]);
                    mma16(acc[mt_][2*p],   ah_, bl_[p][0], bl_[p][1]);
                    mma16(acc[mt_][2*p],   al_, bh_[p][0], bh_[p][1]);
                    mma16(acc[mt_][2*p+1], ah_, bh_[p][2], bh_[p][3]);
                    mma16(acc[mt_][2*p+1], ah_, bl_[p][2], bl_[p][3]);
                    mma16(acc[mt_][2*p+1], al_, bh_[p][2], bh_[p][3]);
                }
            }
        }
        __syncthreads();
    }

    #pragma unroll
    for (int mt_ = 0; mt_ < 4; mt_++) {
        #pragma unroll
        for (int nt = 0; nt < 4; nt++) {
            const int n0 = bn + wn + nt*8 + 2*(lane & 3);
            const float bb0 = bias[n0], bb1 = bias[n0+1];
            #pragma unroll
            for (int half = 0; half < 2; half++) {
                const int r = bm + wm + mt_*16 + (lane >> 2) + half*8;
                float c0 = acc[mt_][nt][half*2+0] + bb0;
                float c1 = acc[mt_][nt][half*2+1] + bb1;
                if (MODE == 4) {
                    *(float2*)&Cout[(size_t)r*DMODEL + n0] = make_float2(c0, c1);
                } else {
                    const int b_ = r >> 10, s = r & (SEQ-1);
                    const int h_ = n0 >> 6, d = n0 & 63;
                    const int bh_i = b_ * NHEAD + h_;
                    if (z == 0) { c0 *= 0.125f; c1 *= 0.125f; }
                    uint32_t Hu, Lu;
                    packsplit(c0, c1, Hu, Lu);
                    if (z == 0 || z == 1) {
                        __nv_bfloat16* Hd = (z == 0) ? g_qh : g_kh;
                        __nv_bfloat16* Ld = (z == 0) ? g_ql : g_kl;
                        const size_t o = ((size_t)bh_i*SEQ + s)*HDIM + d;
                        *(uint32_t*)&Hd[o] = Hu;
                        *(uint32_t*)&Ld[o] = Lu;
                    } else {
                        union { __nv_bfloat16 bb[2]; uint32_t u; } hu, lu;
                        hu.u = Hu; lu.u = Lu;
                        const size_t o0 = ((size_t)bh_i*HDIM + d)*SEQ + s;
                        const size_t o1 = ((size_t)bh_i*HDIM + d+1)*SEQ + s;
                        g_vth[o0] = hu.bb[0]; g_vtl[o0] = lu.bb[0];
                        g_vth[o1] = hu.bb[1]; g_vtl[o1] = lu.bb[1];
                    }
                }
            }
        }
    }
}

// ------------------------- flash attention v4 --------------------------------
// 128-q tile, 8 warps; warp w owns q rows [w*16, w*16+16) over ALL 64 keys.
// Softmax fully warp-local (quad shuffles, m/l in regs). P fragments straight
// from S accumulators. 2 syncs per key tile. K/V double-buffered cp.async.
#define ASTR 72
#define KVTILE (64*ASTR)
#define QTILE (128*ASTR)
#define ATTN_SMEM ((2*QTILE + 8*KVTILE)*2)    // 110,592 B

__global__ void __launch_bounds__(256, 2) attn_bf()
{
    extern __shared__ __align__(16) char smraw[];
    __nv_bfloat16* Qh = (__nv_bfloat16*)smraw;
    __nv_bfloat16* Ql = Qh + QTILE;
    __nv_bfloat16* KV = Ql + QTILE;            // [2 stages][Kh,Kl,Vh,Vl]

    const int t = threadIdx.x, lane = t & 31, w = t >> 5;
    const int qt = blockIdx.x, bh = blockIdx.y;
    const int mt = w * 16;

    const size_t qoff = ((size_t)bh*SEQ + qt*128)*HDIM;
    const size_t koff = (size_t)bh*SEQ*HDIM;

    const int laneA = (lane & 15) * ASTR + (lane >> 4) * 8;
    const int laneB = ((lane & 7) + ((lane >> 4) & 1) * 8) * ASTR + ((lane >> 3) & 1) * 8;

    // Q load: 2048 chunks (2 bufs x 128 rows x 8)
    #pragma unroll
    for (int i = 0; i < 8; i++) {
        const int c = t + i * 256;
        const int tile = c >> 10, cc = c & 1023;
        const int r = cc >> 3, col = (cc & 7) * 8;
        cp16((tile ? Ql : Qh) + r*ASTR + col,
             (tile ? g_ql : g_qh) + qoff + r*HDIM + col);
    }
    CP_COMMIT();

    auto prefetch = [&](int kt, int st) {
        __nv_bfloat16* base = KV + st * 4 * KVTILE;
        #pragma unroll
        for (int i = 0; i < 8; i++) {
            const int c = t + i * 256;
            const int tile = c >> 9, cc = c & 511;
            const int r = cc >> 3, col = (cc & 7) * 8;
            const __nv_bfloat16* g; size_t src;
            if (tile < 2) { g = tile ? g_kl : g_kh; src = koff + (size_t)(kt*64 + r)*HDIM + col; }
            else          { g = (tile == 3) ? g_vtl : g_vth; src = koff + (size_t)r*SEQ + kt*64 + col; }
            cp16(base + tile*KVTILE + r*ASTR + col, g + src);
        }
        CP_COMMIT();
    };

    prefetch(0, 0);
    CP_WAIT(0);
    __syncthreads();

    float m0 = -1e30f, m1 = -1e30f, l0 = 0.f, l1 = 0.f;
    float o[8][4];
    #pragma unroll
    for (int i = 0; i < 8; i++)
        #pragma unroll
        for (int j = 0; j < 4; j++) o[i][j] = 0.f;

    for (int kt = 0; kt < SEQ/64; kt++) {
        const int st = kt & 1;
        if (kt + 1 < SEQ/64) { prefetch(kt + 1, st ^ 1); CP_WAIT(1); }
        else                 { CP_WAIT(0); }
        __syncthreads();                                   // KV(st) ready

        const __nv_bfloat16* Kh = KV + (st*4 + 0)*KVTILE;
        const __nv_bfloat16* Kl = KV + (st*4 + 1)*KVTILE;
        const __nv_bfloat16* Vh = KV + (st*4 + 2)*KVTILE;
        const __nv_bfloat16* Vl = KV + (st*4 + 3)*KVTILE;

        // ---- S[16 x 64] = Q K^T ----
        float sc[8][4];
        #pragma unroll
        for (int i = 0; i < 8; i++)
            #pragma unroll
            for (int j = 0; j < 4; j++) sc[i][j] = 0.f;

        #pragma unroll
        for (int ks4 = 0; ks4 < 4; ks4++) {
            uint32_t qh_[4], ql_[4];
            const int qo = mt*ASTR + ks4*16 + laneA;
            ldsm_x4(qh_[0], qh_[1], qh_[2], qh_[3], sm_addr(Qh + qo));
            ldsm_x4(ql_[0], ql_[1], ql_[2], ql_[3], sm_addr(Ql + qo));
            #pragma unroll
            for (int p = 0; p < 4; p++) {
                uint32_t kh_[4], kl_[4];
                const int off = (p*16)*ASTR + ks4*16 + laneB;
                ldsm_x4(kh_[0], kh_[1], kh_[2], kh_[3], sm_addr(Kh + off));
                ldsm_x4(kl_[0], kl_[1], kl_[2], kl_[3], sm_addr(Kl + off));
                mma16(sc[2*p],   qh_, kh_[0], kh_[1]);
                mma16(sc[2*p],   qh_, kl_[0], kl_[1]);
                mma16(sc[2*p],   ql_, kh_[0], kh_[1]);
                mma16(sc[2*p+1], qh_, kh_[2], kh_[3]);
                mma16(sc[2*p+1], qh_, kl_[2], kl_[3]);
                mma16(sc[2*p+1], ql_, kh_[2], kh_[3]);
            }
        }

        // ---- warp-local online softmax (rows r0, r0+8) ----
        float mx0 = sc[0][0], mx1 = sc[0][2];
        #pragma unroll
        for (int nt = 0; nt < 8; nt++) {
            mx0 = fmaxf(mx0, fmaxf(sc[nt][0], sc[nt][1]));
            mx1 = fmaxf(mx1, fmaxf(sc[nt][2], sc[nt][3]));
        }
        mx0 = fmaxf(mx0, __shfl_xor_sync(0xffffffffu, mx0, 1));
        mx0 = fmaxf(mx0, __shfl_xor_sync(0xffffffffu, mx0, 2));
        mx1 = fmaxf(mx1, __shfl_xor_sync(0xffffffffu, mx1, 1));
        mx1 = fmaxf(mx1, __shfl_xor_sync(0xffffffffu, mx1, 2));
        const float mn0 = fmaxf(m0, mx0), mn1 = fmaxf(m1, mx1);
        const float cr0 = __expf(m0 - mn0), cr1 = __expf(m1 - mn1);
        m0 = mn0; m1 = mn1;

        float s0 = 0.f, s1 = 0.f;
        #pragma unroll
        for (int nt = 0; nt < 8; nt++) {
            sc[nt][0] = __expf(sc[nt][0] - mn0);
            sc[nt][1] = __expf(sc[nt][1] - mn0);
            sc[nt][2] = __expf(sc[nt][2] - mn1);
            sc[nt][3] = __expf(sc[nt][3] - mn1);
            s0 += sc[nt][0] + sc[nt][1];
            s1 += sc[nt][2] + sc[nt][3];
        }
        s0 += __shfl_xor_sync(0xffffffffu, s0, 1);
        s0 += __shfl_xor_sync(0xffffffffu, s0, 2);
        s1 += __shfl_xor_sync(0xffffffffu, s1, 1);
        s1 += __shfl_xor_sync(0xffffffffu, s1, 2);
        l0 = l0*cr0 + s0;
        l1 = l1*cr1 + s1;

        #pragma unroll
        for (int nt = 0; nt < 8; nt++) {
            o[nt][0] *= cr0; o[nt][1] *= cr0;
            o[nt][2] *= cr1; o[nt][3] *= cr1;
        }

        // ---- O += P V (all 64 keys, all 64 dims) ----
        #pragma unroll
        for (int c = 0; c < 4; c++) {
            uint32_t ph_[4], pl_[4];
            packsplit(sc[2*c][0],   sc[2*c][1],   ph_[0], pl_[0]);
            packsplit(sc[2*c][2],   sc[2*c][3],   ph_[1], pl_[1]);
            packsplit(sc[2*c+1][0], sc[2*c+1][1], ph_[2], pl_[2]);
            packsplit(sc[2*c+1][2], sc[2*c+1][3], ph_[3], pl_[3]);
            #pragma unroll
            for (int p = 0; p < 4; p++) {
                uint32_t vh_[4], vl_[4];
                const int off = (p*16)*ASTR + c*16 + laneB;
                ldsm_x4(vh_[0], vh_[1], vh_[2], vh_[3], sm_addr(Vh + off));
                ldsm_x4(vl_[0], vl_[1], vl_[2], vl_[3], sm_addr(Vl + off));
                mma16(o[2*p],   ph_, vh_[0], vh_[1]);
                mma16(o[2*p],   ph_, vl_[0], vl_[1]);
                mma16(o[2*p],   pl_, vh_[0], vh_[1]);
                mma16(o[2*p+1], ph_, vh_[2], vh_[3]);
                mma16(o[2*p+1], ph_, vl_[2], vl_[3]);
                mma16(o[2*p+1], pl_, vh_[2], vh_[3]);
            }
        }
        __syncthreads();                                   // done reading st
    }

    // ---- normalize + write split-bf16 [B,S,D] ----
    const int b_ = bh / NHEAD, h_ = bh % NHEAD;
    const int r0 = mt + (lane >> 2);
    const float inv0 = 1.f / l0, inv1 = 1.f / l1;
    const size_t row0 = (size_t)b_*SEQ + qt*128 + r0;
    #pragma unroll
    for (int nt = 0; nt < 8; nt++) {
        const int cc = nt*8 + 2*(lane & 3);
        uint32_t Hu, Lu;
        packsplit(o[nt][0]*inv0, o[nt][1]*inv0, Hu, Lu);
        *(uint32_t*)&g_ah[row0*DMODEL + h_*HDIM + cc] = Hu;
        *(uint32_t*)&g_al[row0*DMODEL + h_*HDIM + cc] = Lu;
        packsplit(o[nt][2]*inv1, o[nt][3]*inv1, Hu, Lu);
        *(uint32_t*)&g_ah[(row0 + 8)*DMODEL + h_*HDIM + cc] = Hu;
        *(uint32_t*)&g_al[(row0 + 8)*DMODEL + h_*HDIM + cc] = Lu;
    }
}

// ---------------------------------------------------------------------------
extern "C" void kernel_launch(void* const* d_in, const int* in_sizes, int n_in,
                              void* d_out, int out_size)
{
    (void)in_sizes; (void)n_in; (void)out_size;
    const float* x  = (const float*)d_in[0];
    const float* Wq = (const float*)d_in[1];
    const float* bq = (const float*)d_in[2];
    const float* Wk = (const float*)d_in[3];
    const float* bk = (const float*)d_in[4];
    const float* Wv = (const float*)d_in[5];
    const float* bv = (const float*)d_in[6];
    const float* Wo = (const float*)d_in[7];
    const float* bo = (const float*)d_in[8];
    float* out = (float*)d_out;

    prep_x<<<(MROWS*DMODEL/4)/256, 256>>>(x);
    prep_wt<<<dim3(DMODEL/32, DMODEL/32, 4), 256>>>(Wq, Wk, Wv, Wo);

    cudaFuncSetAttribute(gemm_bf<0>, cudaFuncAttributeMaxDynamicSharedMemorySize, GEMM_SMEM);
    cudaFuncSetAttribute(gemm_bf<4>, cudaFuncAttributeMaxDynamicSharedMemorySize, GEMM_SMEM);
    cudaFuncSetAttribute(attn_bf, cudaFuncAttributeMaxDynamicSharedMemorySize, ATTN_SMEM);

    dim3 gq(MROWS/128, DMODEL/128, 3);   // fused QKV
    gemm_bf<0><<<gq, 256, GEMM_SMEM>>>(bq, bk, bv, nullptr);

    attn_bf<<<dim3(SEQ/128, BATCH*NHEAD), 256, ATTN_SMEM>>>();

    dim3 gg(MROWS/128, DMODEL/128);
    gemm_bf<4><<<gg, 256, GEMM_SMEM>>>(bo, nullptr, nullptr, out);
}

// round 10
// speedup vs baseline: 3.8148x; 1.0151x over previous
#include <cuda_runtime.h>
#include <cuda_bf16.h>
#include <math.h>
#include <stdint.h>

#define BATCH 8
#define SEQ 1024
#define DMODEL 768
#define NHEAD 12
#define HDIM 64
#define MROWS (BATCH*SEQ)

// Q prescale: 1/sqrt(64) * log2(e)  (scores land in log2 domain)
#define QSCALE 0.1803368801111204f

// ------------------------- device scratch (no allocs) -----------------------
__device__ __align__(16) __nv_bfloat16 g_xh[MROWS*DMODEL];      // x split [M][K]
__device__ __align__(16) __nv_bfloat16 g_xl[MROWS*DMODEL];
__device__ __align__(16) __nv_bfloat16 g_wth[4][DMODEL*DMODEL]; // W^T split [N][K]
__device__ __align__(16) __nv_bfloat16 g_wtl[4][DMODEL*DMODEL];
__device__ __align__(16) __nv_bfloat16 g_qh[MROWS*DMODEL];      // Q*QSCALE split [bh][s][d]
__device__ __align__(16) __nv_bfloat16 g_ql[MROWS*DMODEL];
__device__ __align__(16) __nv_bfloat16 g_kh[MROWS*DMODEL];      // K split [bh][s][d]
__device__ __align__(16) __nv_bfloat16 g_kl[MROWS*DMODEL];
__device__ __align__(16) __nv_bfloat16 g_vh[MROWS*DMODEL];      // V split [bh][s][d]
__device__ __align__(16) __nv_bfloat16 g_vl[MROWS*DMODEL];
__device__ __align__(16) __nv_bfloat16 g_ah[MROWS*DMODEL];      // attn out split [M][K]
__device__ __align__(16) __nv_bfloat16 g_al[MROWS*DMODEL];

// ------------------------- helpers ------------------------------------------
__device__ __forceinline__ void bsplit(float x, __nv_bfloat16& h, __nv_bfloat16& l) {
    h = __float2bfloat16_rn(x);
    l = __float2bfloat16_rn(x - __bfloat162float(h));
}
__device__ __forceinline__ void mma16(float c[4], const uint32_t a[4],
                                      uint32_t b0, uint32_t b1) {
    asm volatile("mma.sync.aligned.m16n8k16.row.col.f32.bf16.bf16.f32 "
        "{%0,%1,%2,%3}, {%4,%5,%6,%7}, {%8,%9}, {%0,%1,%2,%3};"
        : "+f"(c[0]), "+f"(c[1]), "+f"(c[2]), "+f"(c[3])
        : "r"(a[0]), "r"(a[1]), "r"(a[2]), "r"(a[3]), "r"(b0), "r"(b1));
}
__device__ __forceinline__ uint32_t sm_addr(const void* p) {
    return (uint32_t)__cvta_generic_to_shared(p);
}
__device__ __forceinline__ void ldsm_x4(uint32_t& r0, uint32_t& r1, uint32_t& r2,
                                        uint32_t& r3, uint32_t addr) {
    asm volatile("ldmatrix.sync.aligned.m8n8.x4.shared.b16 {%0,%1,%2,%3}, [%4];"
        : "=r"(r0), "=r"(r1), "=r"(r2), "=r"(r3) : "r"(addr));
}
__device__ __forceinline__ void ldsm_x4_t(uint32_t& r0, uint32_t& r1, uint32_t& r2,
                                          uint32_t& r3, uint32_t addr) {
    asm volatile("ldmatrix.sync.aligned.m8n8.x4.trans.shared.b16 {%0,%1,%2,%3}, [%4];"
        : "=r"(r0), "=r"(r1), "=r"(r2), "=r"(r3) : "r"(addr));
}
__device__ __forceinline__ void cp16(void* dst, const void* src) {
    asm volatile("cp.async.cg.shared.global [%0], [%1], 16;"
        :: "r"(sm_addr(dst)), "l"(src));
}
#define CP_COMMIT() asm volatile("cp.async.commit_group;" ::: "memory")
#define CP_WAIT(n)  asm volatile("cp.async.wait_group %0;" :: "n"(n) : "memory")
__device__ __forceinline__ float ex2(float x) {
    float r; asm("ex2.approx.ftz.f32 %0, %1;" : "=f"(r) : "f"(x)); return r;
}
// truncation-based split of two floats into packed bf16 high/low words
__device__ __forceinline__ void packsplit(float x, float y, uint32_t& H, uint32_t& L) {
    const uint32_t xb = __float_as_uint(x), yb = __float_as_uint(y);
    const uint32_t xh = xb & 0xFFFF0000u,  yh = yb & 0xFFFF0000u;
    H = __byte_perm(xh, yh, 0x7632);
    __nv_bfloat162 p = __floats2bfloat162_rn(x - __uint_as_float(xh),
                                             y - __uint_as_float(yh));
    L = *reinterpret_cast<uint32_t*>(&p);
}

// ------------------------- prep kernels -------------------------------------
__global__ void __launch_bounds__(256) prep_x(const float* __restrict__ x)
{
    const int i = blockIdx.x * 256 + threadIdx.x;
    float4 v = ((const float4*)x)[i];
    union { __nv_bfloat16 b[4]; uint2 u; } H, L;
    bsplit(v.x, H.b[0], L.b[0]); bsplit(v.y, H.b[1], L.b[1]);
    bsplit(v.z, H.b[2], L.b[2]); bsplit(v.w, H.b[3], L.b[3]);
    ((uint2*)g_xh)[i] = H.u;
    ((uint2*)g_xl)[i] = L.u;
}

__global__ void __launch_bounds__(256) prep_wt(const float* __restrict__ Wq,
                                               const float* __restrict__ Wk,
                                               const float* __restrict__ Wv,
                                               const float* __restrict__ Wo)
{
    __shared__ float tile[32][33];
    const int wid = blockIdx.z;
    const float* W = (wid == 0) ? Wq : (wid == 1) ? Wk : (wid == 2) ? Wv : Wo;
    const int n0 = blockIdx.x * 32, k0 = blockIdx.y * 32;
    const int tx = threadIdx.x & 31, ty = threadIdx.x >> 5;
    #pragma unroll
    for (int i = 0; i < 32; i += 8)
        tile[ty + i][tx] = W[(size_t)(k0 + ty + i) * DMODEL + n0 + tx];
    __syncthreads();
    #pragma unroll
    for (int i = 0; i < 32; i += 8) {
        float v = tile[tx][ty + i];
        __nv_bfloat16 h, l; bsplit(v, h, l);
        g_wth[wid][(size_t)(n0 + ty + i) * DMODEL + k0 + tx] = h;
        g_wtl[wid][(size_t)(n0 + ty + i) * DMODEL + k0 + tx] = l;
    }
}

// ------------------------- bf16 split GEMM (ldmatrix + cp.async x2) ----------
// MODE 0: fused QKV (blockIdx.z)   MODE 4: O proj -> fp32 out
#define GSTR 40
#define GTILE (128*GSTR)
#define GEMM_SMEM (2*4*GTILE*2)               // 81,920 B

template<int MODE>
__global__ void __launch_bounds__(256, 2) gemm_bf(const float* __restrict__ b0p,
                                                  const float* __restrict__ b1p,
                                                  const float* __restrict__ b2p,
                                                  float* __restrict__ Cout)
{
    extern __shared__ __align__(16) char gsm[];
    __nv_bfloat16* Sm = (__nv_bfloat16*)gsm;

    const int z = (MODE == 0) ? blockIdx.z : 3;
    const __nv_bfloat16* gAh = (MODE == 4) ? g_ah : g_xh;
    const __nv_bfloat16* gAl = (MODE == 4) ? g_al : g_xl;
    const __nv_bfloat16* gBh = g_wth[z];
    const __nv_bfloat16* gBl = g_wtl[z];
    const float* bias = (MODE == 4) ? b0p : (z == 0) ? b0p : (z == 1) ? b1p : b2p;

    const int bm = blockIdx.x * 128, bn = blockIdx.y * 128;
    const int t = threadIdx.x, lane = t & 31, w = t >> 5;
    const int wm = (w >> 2) * 64, wn = (w & 3) * 32;

    float acc[4][4][4];
    #pragma unroll
    for (int i = 0; i < 4; i++)
        #pragma unroll
        for (int j = 0; j < 4; j++)
            #pragma unroll
            for (int q = 0; q < 4; q++) acc[i][j][q] = 0.f;

    auto prefetch = [&](int kt, int stage) {
        const int k0 = kt * 32;
        __nv_bfloat16* base = Sm + stage * 4 * GTILE;
        #pragma unroll
        for (int i = 0; i < 8; i++) {
            const int c = t + i * 256;
            const int tile = c >> 9, cc = c & 511;
            const int row = cc >> 2, col = (cc & 3) * 8;
            const __nv_bfloat16* g = (tile == 0) ? gAh : (tile == 1) ? gAl
                                   : (tile == 2) ? gBh : gBl;
            const int gr = ((tile < 2) ? bm : bn) + row;
            cp16(base + tile * GTILE + row * GSTR + col,
                 g + (size_t)gr * DMODEL + k0 + col);
        }
        CP_COMMIT();
    };

    prefetch(0, 0);

    const int laneA = (lane & 15) * GSTR + (lane >> 4) * 8;
    const int laneB = ((lane & 7) + ((lane >> 4) & 1) * 8) * GSTR + ((lane >> 3) & 1) * 8;

    for (int kt = 0; kt < 24; kt++) {
        const int stage = kt & 1;
        if (kt + 1 < 24) { prefetch(kt + 1, stage ^ 1); CP_WAIT(1); }
        else             { CP_WAIT(0); }
        __syncthreads();

        const __nv_bfloat16* Ah = Sm + (stage * 4 + 0) * GTILE;
        const __nv_bfloat16* Al = Sm + (stage * 4 + 1) * GTILE;
        const __nv_bfloat16* Bh = Sm + (stage * 4 + 2) * GTILE;
        const __nv_bfloat16* Bl = Sm + (stage * 4 + 3) * GTILE;

        #pragma unroll
        for (int ks = 0; ks < 32; ks += 16) {
            uint32_t bh_[2][4], bl_[2][4];
            #pragma unroll
            for (int p = 0; p < 2; p++) {
                const int off = (wn + p * 16) * GSTR + ks + laneB;
                ldsm_x4(bh_[p][0], bh_[p][1], bh_[p][2], bh_[p][3], sm_addr(Bh + off));
                ldsm_x4(bl_[p][0], bl_[p][1], bl_[p][2], bl_[p][3], sm_addr(Bl + off));
            }
            #pragma unroll
            for (int mt_ = 0; mt_ < 4; mt_++) {
                const int off = (wm + mt_ * 16) * GSTR + ks + laneA;
                uint32_t ah_[4], al_[4];
                ldsm_x4(ah_[0], ah_[1], ah_[2], ah_[3], sm_addr(Ah + off));
                ldsm_x4(al_[0], al_[1], al_[2], al_[3], sm_addr(Al + off));
                #pragma unroll
                for (int p = 0; p < 2; p++) {
                    mma16(acc[mt_][2*p],   ah_, bh_[p][0], bh_[p][1]);
                    mma16(acc[mt_][2*p],   ah_, bl_[p][0], bl_[p][1]);
                    mma16(acc[mt_][2*p],   al_, bh_[p][0], bh_[p][1]);
                    mma16(acc[mt_][2*p+1], ah_, bh_[p][2], bh_[p][3]);
                    mma16(acc[mt_][2*p+1], ah_, bl_[p][2], bl_[p][3]);
                    mma16(acc[mt_][2*p+1], al_, bh_[p][2], bh_[p][3]);
                }
            }
        }
        __syncthreads();
    }

    // ---- epilogue ----
    #pragma unroll
    for (int mt_ = 0; mt_ < 4; mt_++) {
        #pragma unroll
        for (int nt = 0; nt < 4; nt++) {
            const int n0 = bn + wn + nt*8 + 2*(lane & 3);
            const float bb0 = bias[n0], bb1 = bias[n0+1];
            #pragma unroll
            for (int half = 0; half < 2; half++) {
                const int r = bm + wm + mt_*16 + (lane >> 2) + half*8;
                float c0 = acc[mt_][nt][half*2+0] + bb0;
                float c1 = acc[mt_][nt][half*2+1] + bb1;
                if (MODE == 4) {
                    *(float2*)&Cout[(size_t)r*DMODEL + n0] = make_float2(c0, c1);
                } else {
                    const int b_ = r >> 10, s = r & (SEQ-1);
                    const int h_ = n0 >> 6, d = n0 & 63;
                    const int bh_i = b_ * NHEAD + h_;
                    if (z == 0) { c0 *= QSCALE; c1 *= QSCALE; }
                    uint32_t Hu, Lu;
                    packsplit(c0, c1, Hu, Lu);
                    __nv_bfloat16* Hd = (z == 0) ? g_qh : (z == 1) ? g_kh : g_vh;
                    __nv_bfloat16* Ld = (z == 0) ? g_ql : (z == 1) ? g_kl : g_vl;
                    const size_t o = ((size_t)bh_i*SEQ + s)*HDIM + d;
                    *(uint32_t*)&Hd[o] = Hu;
                    *(uint32_t*)&Ld[o] = Lu;
                }
            }
        }
    }
}

// ------------------------- flash attention v5 --------------------------------
// 128-q tile, 8 warps; warp w owns q rows [w*16, w*16+16) over ALL 64 keys.
// Warp-local log2-domain softmax (ex2). V loaded via ldmatrix.trans from
// [s][d] layout (no transposed global V). K/V double-buffered cp.async.
#define ASTR 72
#define KVTILE (64*ASTR)
#define QTILE (128*ASTR)
#define ATTN_SMEM ((2*QTILE + 8*KVTILE)*2)    // 110,592 B

__global__ void __launch_bounds__(256, 2) attn_bf()
{
    extern __shared__ __align__(16) char smraw[];
    __nv_bfloat16* Qh = (__nv_bfloat16*)smraw;
    __nv_bfloat16* Ql = Qh + QTILE;
    __nv_bfloat16* KV = Ql + QTILE;            // [2 stages][Kh,Kl,Vh,Vl]

    const int t = threadIdx.x, lane = t & 31, w = t >> 5;
    const int qt = blockIdx.x, bh = blockIdx.y;
    const int mt = w * 16;

    const size_t qoff = ((size_t)bh*SEQ + qt*128)*HDIM;
    const size_t koff = (size_t)bh*SEQ*HDIM;

    const int laneA = (lane & 15) * ASTR + (lane >> 4) * 8;
    const int laneB = ((lane & 7) + ((lane >> 4) & 1) * 8) * ASTR + ((lane >> 3) & 1) * 8;
    const int laneV = (lane & 15) * ASTR + (lane >> 4) * 8;   // trans: rows=keys

    // Q load
    #pragma unroll
    for (int i = 0; i < 8; i++) {
        const int c = t + i * 256;
        const int tile = c >> 10, cc = c & 1023;
        const int r = cc >> 3, col = (cc & 7) * 8;
        cp16((tile ? Ql : Qh) + r*ASTR + col,
             (tile ? g_ql : g_qh) + qoff + r*HDIM + col);
    }
    CP_COMMIT();

    auto prefetch = [&](int kt, int st) {
        __nv_bfloat16* base = KV + st * 4 * KVTILE;
        #pragma unroll
        for (int i = 0; i < 8; i++) {
            const int c = t + i * 256;
            const int tile = c >> 9, cc = c & 511;
            const int r = cc >> 3, col = (cc & 7) * 8;
            const __nv_bfloat16* g = (tile == 0) ? g_kh : (tile == 1) ? g_kl
                                   : (tile == 2) ? g_vh : g_vl;
            cp16(base + tile*KVTILE + r*ASTR + col,
                 g + koff + (size_t)(kt*64 + r)*HDIM + col);
        }
        CP_COMMIT();
    };

    prefetch(0, 0);
    CP_WAIT(0);
    __syncthreads();

    float m0 = -1e30f, m1 = -1e30f, l0 = 0.f, l1 = 0.f;
    float o[8][4];
    #pragma unroll
    for (int i = 0; i < 8; i++)
        #pragma unroll
        for (int j = 0; j < 4; j++) o[i][j] = 0.f;

    for (int kt = 0; kt < SEQ/64; kt++) {
        const int st = kt & 1;
        if (kt + 1 < SEQ/64) { prefetch(kt + 1, st ^ 1); CP_WAIT(1); }
        else                 { CP_WAIT(0); }
        __syncthreads();                                   // KV(st) ready

        const __nv_bfloat16* Kh = KV + (st*4 + 0)*KVTILE;
        const __nv_bfloat16* Kl = KV + (st*4 + 1)*KVTILE;
        const __nv_bfloat16* Vh = KV + (st*4 + 2)*KVTILE;
        const __nv_bfloat16* Vl = KV + (st*4 + 3)*KVTILE;

        // ---- S[16 x 64] = Q K^T  (log2 units) ----
        float sc[8][4];
        #pragma unroll
        for (int i = 0; i < 8; i++)
            #pragma unroll
            for (int j = 0; j < 4; j++) sc[i][j] = 0.f;

        #pragma unroll
        for (int ks4 = 0; ks4 < 4; ks4++) {
            uint32_t qh_[4], ql_[4];
            const int qo = mt*ASTR + ks4*16 + laneA;
            ldsm_x4(qh_[0], qh_[1], qh_[2], qh_[3], sm_addr(Qh + qo));
            ldsm_x4(ql_[0], ql_[1], ql_[2], ql_[3], sm_addr(Ql + qo));
            #pragma unroll
            for (int p = 0; p < 4; p++) {
                uint32_t kh_[4], kl_[4];
                const int off = (p*16)*ASTR + ks4*16 + laneB;
                ldsm_x4(kh_[0], kh_[1], kh_[2], kh_[3], sm_addr(Kh + off));
                ldsm_x4(kl_[0], kl_[1], kl_[2], kl_[3], sm_addr(Kl + off));
                mma16(sc[2*p],   qh_, kh_[0], kh_[1]);
                mma16(sc[2*p],   qh_, kl_[0], kl_[1]);
                mma16(sc[2*p],   ql_, kh_[0], kh_[1]);
                mma16(sc[2*p+1], qh_, kh_[2], kh_[3]);
                mma16(sc[2*p+1], qh_, kl_[2], kl_[3]);
                mma16(sc[2*p+1], ql_, kh_[2], kh_[3]);
            }
        }

        // ---- warp-local online softmax (base-2) ----
        float mx0 = sc[0][0], mx1 = sc[0][2];
        #pragma unroll
        for (int nt = 0; nt < 8; nt++) {
            mx0 = fmaxf(mx0, fmaxf(sc[nt][0], sc[nt][1]));
            mx1 = fmaxf(mx1, fmaxf(sc[nt][2], sc[nt][3]));
        }
        mx0 = fmaxf(mx0, __shfl_xor_sync(0xffffffffu, mx0, 1));
        mx0 = fmaxf(mx0, __shfl_xor_sync(0xffffffffu, mx0, 2));
        mx1 = fmaxf(mx1, __shfl_xor_sync(0xffffffffu, mx1, 1));
        mx1 = fmaxf(mx1, __shfl_xor_sync(0xffffffffu, mx1, 2));
        const float mn0 = fmaxf(m0, mx0), mn1 = fmaxf(m1, mx1);
        const float cr0 = ex2(m0 - mn0), cr1 = ex2(m1 - mn1);
        m0 = mn0; m1 = mn1;

        float s0 = 0.f, s1 = 0.f;
        #pragma unroll
        for (int nt = 0; nt < 8; nt++) {
            sc[nt][0] = ex2(sc[nt][0] - mn0);
            sc[nt][1] = ex2(sc[nt][1] - mn0);
            sc[nt][2] = ex2(sc[nt][2] - mn1);
            sc[nt][3] = ex2(sc[nt][3] - mn1);
            s0 += sc[nt][0] + sc[nt][1];
            s1 += sc[nt][2] + sc[nt][3];
        }
        s0 += __shfl_xor_sync(0xffffffffu, s0, 1);
        s0 += __shfl_xor_sync(0xffffffffu, s0, 2);
        s1 += __shfl_xor_sync(0xffffffffu, s1, 1);
        s1 += __shfl_xor_sync(0xffffffffu, s1, 2);
        l0 = l0*cr0 + s0;
        l1 = l1*cr1 + s1;

        #pragma unroll
        for (int nt = 0; nt < 8; nt++) {
            o[nt][0] *= cr0; o[nt][1] *= cr0;
            o[nt][2] *= cr1; o[nt][3] *= cr1;
        }

        // ---- O += P V (V via trans LDSM from [s][d]) ----
        #pragma unroll
        for (int c = 0; c < 4; c++) {
            uint32_t ph_[4], pl_[4];
            packsplit(sc[2*c][0],   sc[2*c][1],   ph_[0], pl_[0]);
            packsplit(sc[2*c][2],   sc[2*c][3],   ph_[1], pl_[1]);
            packsplit(sc[2*c+1][0], sc[2*c+1][1], ph_[2], pl_[2]);
            packsplit(sc[2*c+1][2], sc[2*c+1][3], ph_[3], pl_[3]);
            #pragma unroll
            for (int p = 0; p < 4; p++) {
                uint32_t vh_[4], vl_[4];
                const int off = (c*16)*ASTR + p*16 + laneV;
                ldsm_x4_t(vh_[0], vh_[1], vh_[2], vh_[3], sm_addr(Vh + off));
                ldsm_x4_t(vl_[0], vl_[1], vl_[2], vl_[3], sm_addr(Vl + off));
                mma16(o[2*p],   ph_, vh_[0], vh_[1]);
                mma16(o[2*p],   ph_, vl_[0], vl_[1]);
                mma16(o[2*p],   pl_, vh_[0], vh_[1]);
                mma16(o[2*p+1], ph_, vh_[2], vh_[3]);
                mma16(o[2*p+1], ph_, vl_[2], vl_[3]);
                mma16(o[2*p+1], pl_, vh_[2], vh_[3]);
            }
        }
        __syncthreads();                                   // done reading st
    }

    // ---- normalize + write split-bf16 [B,S,D] ----
    const int b_ = bh / NHEAD, h_ = bh % NHEAD;
    const int r0 = mt + (lane >> 2);
    const float inv0 = 1.f / l0, inv1 = 1.f / l1;
    const size_t row0 = (size_t)b_*SEQ + qt*128 + r0;
    #pragma unroll
    for (int nt = 0; nt < 8; nt++) {
        const int cc = nt*8 + 2*(lane & 3);
        uint32_t Hu, Lu;
        packsplit(o[nt][0]*inv0, o[nt][1]*inv0, Hu, Lu);
        *(uint32_t*)&g_ah[row0*DMODEL + h_*HDIM + cc] = Hu;
        *(uint32_t*)&g_al[row0*DMODEL + h_*HDIM + cc] = Lu;
        packsplit(o[nt][2]*inv1, o[nt][3]*inv1, Hu, Lu);
        *(uint32_t*)&g_ah[(row0 + 8)*DMODEL + h_*HDIM + cc] = Hu;
        *(uint32_t*)&g_al[(row0 + 8)*DMODEL + h_*HDIM + cc] = Lu;
    }
}

// ---------------------------------------------------------------------------
extern "C" void kernel_launch(void* const* d_in, const int* in_sizes, int n_in,
                              void* d_out, int out_size)
{
    (void)in_sizes; (void)n_in; (void)out_size;
    const float* x  = (const float*)d_in[0];
    const float* Wq = (const float*)d_in[1];
    const float* bq = (const float*)d_in[2];
    const float* Wk = (const float*)d_in[3];
    const float* bk = (const float*)d_in[4];
    const float* Wv = (const float*)d_in[5];
    const float* bv = (const float*)d_in[6];
    const float* Wo = (const float*)d_in[7];
    const float* bo = (const float*)d_in[8];
    float* out = (float*)d_out;

    prep_x<<<(MROWS*DMODEL/4)/256, 256>>>(x);
    prep_wt<<<dim3(DMODEL/32, DMODEL/32, 4), 256>>>(Wq, Wk, Wv, Wo);

    cudaFuncSetAttribute(gemm_bf<0>, cudaFuncAttributeMaxDynamicSharedMemorySize, GEMM_SMEM);
    cudaFuncSetAttribute(gemm_bf<4>, cudaFuncAttributeMaxDynamicSharedMemorySize, GEMM_SMEM);
    cudaFuncSetAttribute(attn_bf, cudaFuncAttributeMaxDynamicSharedMemorySize, ATTN_SMEM);

    dim3 gq(MROWS/128, DMODEL/128, 3);   // fused QKV
    gemm_bf<0><<<gq, 256, GEMM_SMEM>>>(bq, bk, bv, nullptr);

    attn_bf<<<dim3(SEQ/128, BATCH*NHEAD), 256, ATTN_SMEM>>>();

    dim3 gg(MROWS/128, DMODEL/128);
    gemm_bf<4><<<gg, 256, GEMM_SMEM>>>(bo, nullptr, nullptr, out);
}

// round 11
// speedup vs baseline: 3.8569x; 1.0110x over previous
#include <cuda_runtime.h>
#include <cuda_bf16.h>
#include <math.h>
#include <stdint.h>

#define BATCH 8
#define SEQ 1024
#define DMODEL 768
#define NHEAD 12
#define HDIM 64
#define MROWS (BATCH*SEQ)

// Q prescale: 1/sqrt(64) * log2(e)  (scores land in log2 domain)
#define QSCALE 0.1803368801111204f

// ------------------------- device scratch (no allocs) -----------------------
__device__ __align__(16) __nv_bfloat16 g_xh[MROWS*DMODEL];      // x split [M][K]
__device__ __align__(16) __nv_bfloat16 g_xl[MROWS*DMODEL];
__device__ __align__(16) __nv_bfloat16 g_wth[4][DMODEL*DMODEL]; // W^T split [N][K]
__device__ __align__(16) __nv_bfloat16 g_wtl[4][DMODEL*DMODEL];
__device__ __align__(16) __nv_bfloat16 g_qh[MROWS*DMODEL];      // Q*QSCALE split [bh][s][d]
__device__ __align__(16) __nv_bfloat16 g_ql[MROWS*DMODEL];
__device__ __align__(16) __nv_bfloat16 g_kh[MROWS*DMODEL];      // K split [bh][s][d]
__device__ __align__(16) __nv_bfloat16 g_kl[MROWS*DMODEL];
__device__ __align__(16) __nv_bfloat16 g_vh[MROWS*DMODEL];      // V split [bh][s][d]
__device__ __align__(16) __nv_bfloat16 g_vl[MROWS*DMODEL];
__device__ __align__(16) __nv_bfloat16 g_ah[MROWS*DMODEL];      // attn out split [M][K]
__device__ __align__(16) __nv_bfloat16 g_al[MROWS*DMODEL];

// ------------------------- helpers ------------------------------------------
__device__ __forceinline__ void bsplit(float x, __nv_bfloat16& h, __nv_bfloat16& l) {
    h = __float2bfloat16_rn(x);
    l = __float2bfloat16_rn(x - __bfloat162float(h));
}
__device__ __forceinline__ void mma16(float c[4], const uint32_t a[4],
                                      uint32_t b0, uint32_t b1) {
    asm volatile("mma.sync.aligned.m16n8k16.row.col.f32.bf16.bf16.f32 "
        "{%0,%1,%2,%3}, {%4,%5,%6,%7}, {%8,%9}, {%0,%1,%2,%3};"
        : "+f"(c[0]), "+f"(c[1]), "+f"(c[2]), "+f"(c[3])
        : "r"(a[0]), "r"(a[1]), "r"(a[2]), "r"(a[3]), "r"(b0), "r"(b1));
}
__device__ __forceinline__ uint32_t sm_addr(const void* p) {
    return (uint32_t)__cvta_generic_to_shared(p);
}
__device__ __forceinline__ void ldsm_x4(uint32_t& r0, uint32_t& r1, uint32_t& r2,
                                        uint32_t& r3, uint32_t addr) {
    asm volatile("ldmatrix.sync.aligned.m8n8.x4.shared.b16 {%0,%1,%2,%3}, [%4];"
        : "=r"(r0), "=r"(r1), "=r"(r2), "=r"(r3) : "r"(addr));
}
__device__ __forceinline__ void ldsm_x4_t(uint32_t& r0, uint32_t& r1, uint32_t& r2,
                                          uint32_t& r3, uint32_t addr) {
    asm volatile("ldmatrix.sync.aligned.m8n8.x4.trans.shared.b16 {%0,%1,%2,%3}, [%4];"
        : "=r"(r0), "=r"(r1), "=r"(r2), "=r"(r3) : "r"(addr));
}
__device__ __forceinline__ void cp16(void* dst, const void* src) {
    asm volatile("cp.async.cg.shared.global [%0], [%1], 16;"
        :: "r"(sm_addr(dst)), "l"(src));
}
#define CP_COMMIT() asm volatile("cp.async.commit_group;" ::: "memory")
#define CP_WAIT(n)  asm volatile("cp.async.wait_group %0;" :: "n"(n) : "memory")
__device__ __forceinline__ float ex2(float x) {
    float r; asm("ex2.approx.ftz.f32 %0, %1;" : "=f"(r) : "f"(x)); return r;
}
// truncation-based split of two floats into packed bf16 high/low words
__device__ __forceinline__ void packsplit(float x, float y, uint32_t& H, uint32_t& L) {
    const uint32_t xb = __float_as_uint(x), yb = __float_as_uint(y);
    const uint32_t xh = xb & 0xFFFF0000u,  yh = yb & 0xFFFF0000u;
    H = __byte_perm(xh, yh, 0x7632);
    __nv_bfloat162 p = __floats2bfloat162_rn(x - __uint_as_float(xh),
                                             y - __uint_as_float(yh));
    L = *reinterpret_cast<uint32_t*>(&p);
}

// ------------------------- prep kernels -------------------------------------
__global__ void __launch_bounds__(256) prep_x(const float* __restrict__ x)
{
    const int i = blockIdx.x * 256 + threadIdx.x;
    float4 v = ((const float4*)x)[i];
    union { __nv_bfloat16 b[4]; uint2 u; } H, L;
    bsplit(v.x, H.b[0], L.b[0]); bsplit(v.y, H.b[1], L.b[1]);
    bsplit(v.z, H.b[2], L.b[2]); bsplit(v.w, H.b[3], L.b[3]);
    ((uint2*)g_xh)[i] = H.u;
    ((uint2*)g_xl)[i] = L.u;
}

__global__ void __launch_bounds__(256) prep_wt(const float* __restrict__ Wq,
                                               const float* __restrict__ Wk,
                                               const float* __restrict__ Wv,
                                               const float* __restrict__ Wo)
{
    __shared__ float tile[32][33];
    const int wid = blockIdx.z;
    const float* W = (wid == 0) ? Wq : (wid == 1) ? Wk : (wid == 2) ? Wv : Wo;
    const int n0 = blockIdx.x * 32, k0 = blockIdx.y * 32;
    const int tx = threadIdx.x & 31, ty = threadIdx.x >> 5;
    #pragma unroll
    for (int i = 0; i < 32; i += 8)
        tile[ty + i][tx] = W[(size_t)(k0 + ty + i) * DMODEL + n0 + tx];
    __syncthreads();
    #pragma unroll
    for (int i = 0; i < 32; i += 8) {
        float v = tile[tx][ty + i];
        __nv_bfloat16 h, l; bsplit(v, h, l);
        g_wth[wid][(size_t)(n0 + ty + i) * DMODEL + k0 + tx] = h;
        g_wtl[wid][(size_t)(n0 + ty + i) * DMODEL + k0 + tx] = l;
    }
}

// ------------------------- bf16 split GEMM (single-sync pipeline) ------------
// MODE 0: fused QKV (blockIdx.z)   MODE 4: O proj -> fp32 out
#define GSTR 40
#define GTILE (128*GSTR)
#define GEMM_SMEM (2*4*GTILE*2)               // 81,920 B

template<int MODE>
__global__ void __launch_bounds__(256, 2) gemm_bf(const float* __restrict__ b0p,
                                                  const float* __restrict__ b1p,
                                                  const float* __restrict__ b2p,
                                                  float* __restrict__ Cout)
{
    extern __shared__ __align__(16) char gsm[];
    __nv_bfloat16* Sm = (__nv_bfloat16*)gsm;

    const int z = (MODE == 0) ? blockIdx.z : 3;
    const __nv_bfloat16* gAh = (MODE == 4) ? g_ah : g_xh;
    const __nv_bfloat16* gAl = (MODE == 4) ? g_al : g_xl;
    const __nv_bfloat16* gBh = g_wth[z];
    const __nv_bfloat16* gBl = g_wtl[z];
    const float* bias = (MODE == 4) ? b0p : (z == 0) ? b0p : (z == 1) ? b1p : b2p;

    const int bm = blockIdx.x * 128, bn = blockIdx.y * 128;
    const int t = threadIdx.x, lane = t & 31, w = t >> 5;
    const int wm = (w >> 2) * 64, wn = (w & 3) * 32;

    float acc[4][4][4];
    #pragma unroll
    for (int i = 0; i < 4; i++)
        #pragma unroll
        for (int j = 0; j < 4; j++)
            #pragma unroll
            for (int q = 0; q < 4; q++) acc[i][j][q] = 0.f;

    auto prefetch = [&](int kt, int stage) {
        const int k0 = kt * 32;
        __nv_bfloat16* base = Sm + stage * 4 * GTILE;
        #pragma unroll
        for (int i = 0; i < 8; i++) {
            const int c = t + i * 256;
            const int tile = c >> 9, cc = c & 511;
            const int row = cc >> 2, col = (cc & 3) * 8;
            const __nv_bfloat16* g = (tile == 0) ? gAh : (tile == 1) ? gAl
                                   : (tile == 2) ? gBh : gBl;
            const int gr = ((tile < 2) ? bm : bn) + row;
            cp16(base + tile * GTILE + row * GSTR + col,
                 g + (size_t)gr * DMODEL + k0 + col);
        }
        CP_COMMIT();
    };

    prefetch(0, 0);

    const int laneA = (lane & 15) * GSTR + (lane >> 4) * 8;
    const int laneB = ((lane & 7) + ((lane >> 4) & 1) * 8) * GSTR + ((lane >> 3) & 1) * 8;

    for (int kt = 0; kt < 24; kt++) {
        const int stage = kt & 1;
        // single-sync pipeline: wait my inbound group, converge, then issue
        // next prefetch into the stage everyone provably finished at kt-1.
        CP_WAIT(0);
        __syncthreads();
        if (kt + 1 < 24) prefetch(kt + 1, stage ^ 1);

        const __nv_bfloat16* Ah = Sm + (stage * 4 + 0) * GTILE;
        const __nv_bfloat16* Al = Sm + (stage * 4 + 1) * GTILE;
        const __nv_bfloat16* Bh = Sm + (stage * 4 + 2) * GTILE;
        const __nv_bfloat16* Bl = Sm + (stage * 4 + 3) * GTILE;

        #pragma unroll
        for (int ks = 0; ks < 32; ks += 16) {
            uint32_t bh_[2][4], bl_[2][4];
            #pragma unroll
            for (int p = 0; p < 2; p++) {
                const int off = (wn + p * 16) * GSTR + ks + laneB;
                ldsm_x4(bh_[p][0], bh_[p][1], bh_[p][2], bh_[p][3], sm_addr(Bh + off));
                ldsm_x4(bl_[p][0], bl_[p][1], bl_[p][2], bl_[p][3], sm_addr(Bl + off));
            }
            #pragma unroll
            for (int mt_ = 0; mt_ < 4; mt_++) {
                const int off = (wm + mt_ * 16) * GSTR + ks + laneA;
                uint32_t ah_[4], al_[4];
                ldsm_x4(ah_[0], ah_[1], ah_[2], ah_[3], sm_addr(Ah + off));
                ldsm_x4(al_[0], al_[1], al_[2], al_[3], sm_addr(Al + off));
                #pragma unroll
                for (int p = 0; p < 2; p++) {
                    mma16(acc[mt_][2*p],   ah_, bh_[p][0], bh_[p][1]);
                    mma16(acc[mt_][2*p],   ah_, bl_[p][0], bl_[p][1]);
                    mma16(acc[mt_][2*p],   al_, bh_[p][0], bh_[p][1]);
                    mma16(acc[mt_][2*p+1], ah_, bh_[p][2], bh_[p][3]);
                    mma16(acc[mt_][2*p+1], ah_, bl_[p][2], bl_[p][3]);
                    mma16(acc[mt_][2*p+1], al_, bh_[p][2], bh_[p][3]);
                }
            }
        }
    }

    // ---- epilogue ----
    #pragma unroll
    for (int mt_ = 0; mt_ < 4; mt_++) {
        #pragma unroll
        for (int nt = 0; nt < 4; nt++) {
            const int n0 = bn + wn + nt*8 + 2*(lane & 3);
            const float bb0 = bias[n0], bb1 = bias[n0+1];
            #pragma unroll
            for (int half = 0; half < 2; half++) {
                const int r = bm + wm + mt_*16 + (lane >> 2) + half*8;
                float c0 = acc[mt_][nt][half*2+0] + bb0;
                float c1 = acc[mt_][nt][half*2+1] + bb1;
                if (MODE == 4) {
                    *(float2*)&Cout[(size_t)r*DMODEL + n0] = make_float2(c0, c1);
                } else {
                    const int b_ = r >> 10, s = r & (SEQ-1);
                    const int h_ = n0 >> 6, d = n0 & 63;
                    const int bh_i = b_ * NHEAD + h_;
                    if (z == 0) { c0 *= QSCALE; c1 *= QSCALE; }
                    uint32_t Hu, Lu;
                    packsplit(c0, c1, Hu, Lu);
                    __nv_bfloat16* Hd = (z == 0) ? g_qh : (z == 1) ? g_kh : g_vh;
                    __nv_bfloat16* Ld = (z == 0) ? g_ql : (z == 1) ? g_kl : g_vl;
                    const size_t o = ((size_t)bh_i*SEQ + s)*HDIM + d;
                    *(uint32_t*)&Hd[o] = Hu;
                    *(uint32_t*)&Ld[o] = Lu;
                }
            }
        }
    }
}

// ------------------------- flash attention v6 (single-sync) ------------------
// 128-q tile, 8 warps; warp w owns q rows [w*16, w*16+16) over ALL 64 keys.
// Warp-local log2-domain softmax (ex2). V via ldmatrix.trans. K/V double-
// buffered cp.async with ONE barrier per key tile.
#define ASTR 72
#define KVTILE (64*ASTR)
#define QTILE (128*ASTR)
#define ATTN_SMEM ((2*QTILE + 8*KVTILE)*2)    // 110,592 B

__global__ void __launch_bounds__(256, 2) attn_bf()
{
    extern __shared__ __align__(16) char smraw[];
    __nv_bfloat16* Qh = (__nv_bfloat16*)smraw;
    __nv_bfloat16* Ql = Qh + QTILE;
    __nv_bfloat16* KV = Ql + QTILE;            // [2 stages][Kh,Kl,Vh,Vl]

    const int t = threadIdx.x, lane = t & 31, w = t >> 5;
    const int qt = blockIdx.x, bh = blockIdx.y;
    const int mt = w * 16;

    const size_t qoff = ((size_t)bh*SEQ + qt*128)*HDIM;
    const size_t koff = (size_t)bh*SEQ*HDIM;

    const int laneA = (lane & 15) * ASTR + (lane >> 4) * 8;
    const int laneB = ((lane & 7) + ((lane >> 4) & 1) * 8) * ASTR + ((lane >> 3) & 1) * 8;
    const int laneV = (lane & 15) * ASTR + (lane >> 4) * 8;   // trans: rows=keys

    // Q load (group 1 of 2; merged into iter-0 CP_WAIT(0))
    #pragma unroll
    for (int i = 0; i < 8; i++) {
        const int c = t + i * 256;
        const int tile = c >> 10, cc = c & 1023;
        const int r = cc >> 3, col = (cc & 7) * 8;
        cp16((tile ? Ql : Qh) + r*ASTR + col,
             (tile ? g_ql : g_qh) + qoff + r*HDIM + col);
    }
    CP_COMMIT();

    auto prefetch = [&](int kt, int st) {
        __nv_bfloat16* base = KV + st * 4 * KVTILE;
        #pragma unroll
        for (int i = 0; i < 8; i++) {
            const int c = t + i * 256;
            const int tile = c >> 9, cc = c & 511;
            const int r = cc >> 3, col = (cc & 7) * 8;
            const __nv_bfloat16* g = (tile == 0) ? g_kh : (tile == 1) ? g_kl
                                   : (tile == 2) ? g_vh : g_vl;
            cp16(base + tile*KVTILE + r*ASTR + col,
                 g + koff + (size_t)(kt*64 + r)*HDIM + col);
        }
        CP_COMMIT();
    };

    prefetch(0, 0);

    float m0 = -1e30f, m1 = -1e30f, l0 = 0.f, l1 = 0.f;
    float o[8][4];
    #pragma unroll
    for (int i = 0; i < 8; i++)
        #pragma unroll
        for (int j = 0; j < 4; j++) o[i][j] = 0.f;

    for (int kt = 0; kt < SEQ/64; kt++) {
        const int st = kt & 1;
        CP_WAIT(0);
        __syncthreads();                       // all warps done with st^1 reads
        if (kt + 1 < SEQ/64) prefetch(kt + 1, st ^ 1);

        const __nv_bfloat16* Kh = KV + (st*4 + 0)*KVTILE;
        const __nv_bfloat16* Kl = KV + (st*4 + 1)*KVTILE;
        const __nv_bfloat16* Vh = KV + (st*4 + 2)*KVTILE;
        const __nv_bfloat16* Vl = KV + (st*4 + 3)*KVTILE;

        // ---- S[16 x 64] = Q K^T  (log2 units) ----
        float sc[8][4];
        #pragma unroll
        for (int i = 0; i < 8; i++)
            #pragma unroll
            for (int j = 0; j < 4; j++) sc[i][j] = 0.f;

        #pragma unroll
        for (int ks4 = 0; ks4 < 4; ks4++) {
            uint32_t qh_[4], ql_[4];
            const int qo = mt*ASTR + ks4*16 + laneA;
            ldsm_x4(qh_[0], qh_[1], qh_[2], qh_[3], sm_addr(Qh + qo));
            ldsm_x4(ql_[0], ql_[1], ql_[2], ql_[3], sm_addr(Ql + qo));
            #pragma unroll
            for (int p = 0; p < 4; p++) {
                uint32_t kh_[4], kl_[4];
                const int off = (p*16)*ASTR + ks4*16 + laneB;
                ldsm_x4(kh_[0], kh_[1], kh_[2], kh_[3], sm_addr(Kh + off));
                ldsm_x4(kl_[0], kl_[1], kl_[2], kl_[3], sm_addr(Kl + off));
                mma16(sc[2*p],   qh_, kh_[0], kh_[1]);
                mma16(sc[2*p],   qh_, kl_[0], kl_[1]);
                mma16(sc[2*p],   ql_, kh_[0], kh_[1]);
                mma16(sc[2*p+1], qh_, kh_[2], kh_[3]);
                mma16(sc[2*p+1], qh_, kl_[2], kl_[3]);
                mma16(sc[2*p+1], ql_, kh_[2], kh_[3]);
            }
        }

        // ---- warp-local online softmax (base-2) ----
        float mx0 = sc[0][0], mx1 = sc[0][2];
        #pragma unroll
        for (int nt = 0; nt < 8; nt++) {
            mx0 = fmaxf(mx0, fmaxf(sc[nt][0], sc[nt][1]));
            mx1 = fmaxf(mx1, fmaxf(sc[nt][2], sc[nt][3]));
        }
        mx0 = fmaxf(mx0, __shfl_xor_sync(0xffffffffu, mx0, 1));
        mx0 = fmaxf(mx0, __shfl_xor_sync(0xffffffffu, mx0, 2));
        mx1 = fmaxf(mx1, __shfl_xor_sync(0xffffffffu, mx1, 1));
        mx1 = fmaxf(mx1, __shfl_xor_sync(0xffffffffu, mx1, 2));
        const float mn0 = fmaxf(m0, mx0), mn1 = fmaxf(m1, mx1);
        const float cr0 = ex2(m0 - mn0), cr1 = ex2(m1 - mn1);
        m0 = mn0; m1 = mn1;

        float s0 = 0.f, s1 = 0.f;
        #pragma unroll
        for (int nt = 0; nt < 8; nt++) {
            sc[nt][0] = ex2(sc[nt][0] - mn0);
            sc[nt][1] = ex2(sc[nt][1] - mn0);
            sc[nt][2] = ex2(sc[nt][2] - mn1);
            sc[nt][3] = ex2(sc[nt][3] - mn1);
            s0 += sc[nt][0] + sc[nt][1];
            s1 += sc[nt][2] + sc[nt][3];
        }
        s0 += __shfl_xor_sync(0xffffffffu, s0, 1);
        s0 += __shfl_xor_sync(0xffffffffu, s0, 2);
        s1 += __shfl_xor_sync(0xffffffffu, s1, 1);
        s1 += __shfl_xor_sync(0xffffffffu, s1, 2);
        l0 = l0*cr0 + s0;
        l1 = l1*cr1 + s1;

        #pragma unroll
        for (int nt = 0; nt < 8; nt++) {
            o[nt][0] *= cr0; o[nt][1] *= cr0;
            o[nt][2] *= cr1; o[nt][3] *= cr1;
        }

        // ---- O += P V (V via trans LDSM from [s][d]) ----
        #pragma unroll
        for (int c = 0; c < 4; c++) {
            uint32_t ph_[4], pl_[4];
            packsplit(sc[2*c][0],   sc[2*c][1],   ph_[0], pl_[0]);
            packsplit(sc[2*c][2],   sc[2*c][3],   ph_[1], pl_[1]);
            packsplit(sc[2*c+1][0], sc[2*c+1][1], ph_[2], pl_[2]);
            packsplit(sc[2*c+1][2], sc[2*c+1][3], ph_[3], pl_[3]);
            #pragma unroll
            for (int p = 0; p < 4; p++) {
                uint32_t vh_[4], vl_[4];
                const int off = (c*16)*ASTR + p*16 + laneV;
                ldsm_x4_t(vh_[0], vh_[1], vh_[2], vh_[3], sm_addr(Vh + off));
                ldsm_x4_t(vl_[0], vl_[1], vl_[2], vl_[3], sm_addr(Vl + off));
                mma16(o[2*p],   ph_, vh_[0], vh_[1]);
                mma16(o[2*p],   ph_, vl_[0], vl_[1]);
                mma16(o[2*p],   pl_, vh_[0], vh_[1]);
                mma16(o[2*p+1], ph_, vh_[2], vh_[3]);
                mma16(o[2*p+1], ph_, vl_[2], vl_[3]);
                mma16(o[2*p+1], pl_, vh_[2], vh_[3]);
            }
        }
    }

    // ---- normalize + write split-bf16 [B,S,D] ----
    const int b_ = bh / NHEAD, h_ = bh % NHEAD;
    const int r0 = mt + (lane >> 2);
    const float inv0 = 1.f / l0, inv1 = 1.f / l1;
    const size_t row0 = (size_t)b_*SEQ + qt*128 + r0;
    #pragma unroll
    for (int nt = 0; nt < 8; nt++) {
        const int cc = nt*8 + 2*(lane & 3);
        uint32_t Hu, Lu;
        packsplit(o[nt][0]*inv0, o[nt][1]*inv0, Hu, Lu);
        *(uint32_t*)&g_ah[row0*DMODEL + h_*HDIM + cc] = Hu;
        *(uint32_t*)&g_al[row0*DMODEL + h_*HDIM + cc] = Lu;
        packsplit(o[nt][2]*inv1, o[nt][3]*inv1, Hu, Lu);
        *(uint32_t*)&g_ah[(row0 + 8)*DMODEL + h_*HDIM + cc] = Hu;
        *(uint32_t*)&g_al[(row0 + 8)*DMODEL + h_*HDIM + cc] = Lu;
    }
}

// ---------------------------------------------------------------------------
extern "C" void kernel_launch(void* const* d_in, const int* in_sizes, int n_in,
                              void* d_out, int out_size)
{
    (void)in_sizes; (void)n_in; (void)out_size;
    const float* x  = (const float*)d_in[0];
    const float* Wq = (const float*)d_in[1];
    const float* bq = (const float*)d_in[2];
    const float* Wk = (const float*)d_in[3];
    const float* bk = (const float*)d_in[4];
    const float* Wv = (const float*)d_in[5];
    const float* bv = (const float*)d_in[6];
    const float* Wo = (const float*)d_in[7];
    const float* bo = (const float*)d_in[8];
    float* out = (float*)d_out;

    prep_x<<<(MROWS*DMODEL/4)/256, 256>>>(x);
    prep_wt<<<dim3(DMODEL/32, DMODEL/32, 4), 256>>>(Wq, Wk, Wv, Wo);

    cudaFuncSetAttribute(gemm_bf<0>, cudaFuncAttributeMaxDynamicSharedMemorySize, GEMM_SMEM);
    cudaFuncSetAttribute(gemm_bf<4>, cudaFuncAttributeMaxDynamicSharedMemorySize, GEMM_SMEM);
    cudaFuncSetAttribute(attn_bf, cudaFuncAttributeMaxDynamicSharedMemorySize, ATTN_SMEM);

    dim3 gq(MROWS/128, DMODEL/128, 3);   // fused QKV
    gemm_bf<0><<<gq, 256, GEMM_SMEM>>>(bq, bk, bv, nullptr);

    attn_bf<<<dim3(SEQ/128, BATCH*NHEAD), 256, ATTN_SMEM>>>();

    dim3 gg(MROWS/128, DMODEL/128);
    gemm_bf<4><<<gg, 256, GEMM_SMEM>>>(bo, nullptr, nullptr, out);
}

// round 12
// speedup vs baseline: 4.0619x; 1.0532x over previous
#include <cuda_runtime.h>
#include <cuda_bf16.h>
#include <cuda_fp16.h>
#include <math.h>
#include <stdint.h>

#define BATCH 8
#define SEQ 1024
#define DMODEL 768
#define NHEAD 12
#define HDIM 64
#define MROWS (BATCH*SEQ)

// Q prescale: 1/sqrt(64) * log2(e)  (scores land in log2 domain)
#define QSCALE 0.1803368801111204f

// ------------------------- device scratch (no allocs) -----------------------
__device__ __align__(16) __nv_bfloat16 g_xh[MROWS*DMODEL];      // x split [M][K]
__device__ __align__(16) __nv_bfloat16 g_xl[MROWS*DMODEL];
__device__ __align__(16) __nv_bfloat16 g_wth[4][DMODEL*DMODEL]; // W^T split [N][K]
__device__ __align__(16) __nv_bfloat16 g_wtl[4][DMODEL*DMODEL];
__device__ __align__(16) __nv_bfloat16 g_qh[MROWS*DMODEL];      // Q*QSCALE split [bh][s][d]
__device__ __align__(16) __nv_bfloat16 g_ql[MROWS*DMODEL];
__device__ __align__(16) __nv_bfloat16 g_kh[MROWS*DMODEL];      // K split [bh][s][d]
__device__ __align__(16) __nv_bfloat16 g_kl[MROWS*DMODEL];
__device__ __align__(16) __half       g_vh[MROWS*DMODEL];       // V fp16 split [bh][s][d]
__device__ __align__(16) __half       g_vl[MROWS*DMODEL];
__device__ __align__(16) __nv_bfloat16 g_ah[MROWS*DMODEL];      // attn out split [M][K]
__device__ __align__(16) __nv_bfloat16 g_al[MROWS*DMODEL];

// ------------------------- helpers ------------------------------------------
__device__ __forceinline__ void bsplit(float x, __nv_bfloat16& h, __nv_bfloat16& l) {
    h = __float2bfloat16_rn(x);
    l = __float2bfloat16_rn(x - __bfloat162float(h));
}
__device__ __forceinline__ void mma16(float c[4], const uint32_t a[4],
                                      uint32_t b0, uint32_t b1) {
    asm volatile("mma.sync.aligned.m16n8k16.row.col.f32.bf16.bf16.f32 "
        "{%0,%1,%2,%3}, {%4,%5,%6,%7}, {%8,%9}, {%0,%1,%2,%3};"
        : "+f"(c[0]), "+f"(c[1]), "+f"(c[2]), "+f"(c[3])
        : "r"(a[0]), "r"(a[1]), "r"(a[2]), "r"(a[3]), "r"(b0), "r"(b1));
}
__device__ __forceinline__ void mma16h(float c[4], const uint32_t a[4],
                                       uint32_t b0, uint32_t b1) {
    asm volatile("mma.sync.aligned.m16n8k16.row.col.f32.f16.f16.f32 "
        "{%0,%1,%2,%3}, {%4,%5,%6,%7}, {%8,%9}, {%0,%1,%2,%3};"
        : "+f"(c[0]), "+f"(c[1]), "+f"(c[2]), "+f"(c[3])
        : "r"(a[0]), "r"(a[1]), "r"(a[2]), "r"(a[3]), "r"(b0), "r"(b1));
}
__device__ __forceinline__ uint32_t sm_addr(const void* p) {
    return (uint32_t)__cvta_generic_to_shared(p);
}
__device__ __forceinline__ void ldsm_x4(uint32_t& r0, uint32_t& r1, uint32_t& r2,
                                        uint32_t& r3, uint32_t addr) {
    asm volatile("ldmatrix.sync.aligned.m8n8.x4.shared.b16 {%0,%1,%2,%3}, [%4];"
        : "=r"(r0), "=r"(r1), "=r"(r2), "=r"(r3) : "r"(addr));
}
__device__ __forceinline__ void ldsm_x4_t(uint32_t& r0, uint32_t& r1, uint32_t& r2,
                                          uint32_t& r3, uint32_t addr) {
    asm volatile("ldmatrix.sync.aligned.m8n8.x4.trans.shared.b16 {%0,%1,%2,%3}, [%4];"
        : "=r"(r0), "=r"(r1), "=r"(r2), "=r"(r3) : "r"(addr));
}
__device__ __forceinline__ void cp16(void* dst, const void* src) {
    asm volatile("cp.async.cg.shared.global [%0], [%1], 16;"
        :: "r"(sm_addr(dst)), "l"(src));
}
#define CP_COMMIT() asm volatile("cp.async.commit_group;" ::: "memory")
#define CP_WAIT(n)  asm volatile("cp.async.wait_group %0;" :: "n"(n) : "memory")
__device__ __forceinline__ float ex2(float x) {
    float r; asm("ex2.approx.ftz.f32 %0, %1;" : "=f"(r) : "f"(x)); return r;
}
// truncation-based split of two floats into packed bf16 high/low words
__device__ __forceinline__ void packsplit(float x, float y, uint32_t& H, uint32_t& L) {
    const uint32_t xb = __float_as_uint(x), yb = __float_as_uint(y);
    const uint32_t xh = xb & 0xFFFF0000u,  yh = yb & 0xFFFF0000u;
    H = __byte_perm(xh, yh, 0x7632);
    __nv_bfloat162 p = __floats2bfloat162_rn(x - __uint_as_float(xh),
                                             y - __uint_as_float(yh));
    L = *reinterpret_cast<uint32_t*>(&p);
}
// fp16 round-split of two floats (for V)
__device__ __forceinline__ void packsplit_h(float x, float y, uint32_t& H, uint32_t& L) {
    __half2 h = __floats2half2_rn(x, y);
    float2 hf = __half22float2(h);
    __half2 l = __floats2half2_rn(x - hf.x, y - hf.y);
    H = *reinterpret_cast<uint32_t*>(&h);
    L = *reinterpret_cast<uint32_t*>(&l);
}

// ------------------------- prep kernels -------------------------------------
__global__ void __launch_bounds__(256) prep_x(const float* __restrict__ x)
{
    const int i = blockIdx.x * 256 + threadIdx.x;
    float4 v = ((const float4*)x)[i];
    union { __nv_bfloat16 b[4]; uint2 u; } H, L;
    bsplit(v.x, H.b[0], L.b[0]); bsplit(v.y, H.b[1], L.b[1]);
    bsplit(v.z, H.b[2], L.b[2]); bsplit(v.w, H.b[3], L.b[3]);
    ((uint2*)g_xh)[i] = H.u;
    ((uint2*)g_xl)[i] = L.u;
}

__global__ void __launch_bounds__(256) prep_wt(const float* __restrict__ Wq,
                                               const float* __restrict__ Wk,
                                               const float* __restrict__ Wv,
                                               const float* __restrict__ Wo)
{
    __shared__ float tile[32][33];
    const int wid = blockIdx.z;
    const float* W = (wid == 0) ? Wq : (wid == 1) ? Wk : (wid == 2) ? Wv : Wo;
    const int n0 = blockIdx.x * 32, k0 = blockIdx.y * 32;
    const int tx = threadIdx.x & 31, ty = threadIdx.x >> 5;
    #pragma unroll
    for (int i = 0; i < 32; i += 8)
        tile[ty + i][tx] = W[(size_t)(k0 + ty + i) * DMODEL + n0 + tx];
    __syncthreads();
    #pragma unroll
    for (int i = 0; i < 32; i += 8) {
        float v = tile[tx][ty + i];
        __nv_bfloat16 h, l; bsplit(v, h, l);
        g_wth[wid][(size_t)(n0 + ty + i) * DMODEL + k0 + tx] = h;
        g_wtl[wid][(size_t)(n0 + ty + i) * DMODEL + k0 + tx] = l;
    }
}

// ------------------------- bf16 split GEMM (single-sync pipeline) ------------
// MODE 0: fused QKV (blockIdx.z)   MODE 4: O proj -> fp32 out
#define GSTR 40
#define GTILE (128*GSTR)
#define GEMM_SMEM (2*4*GTILE*2)               // 81,920 B

template<int MODE>
__global__ void __launch_bounds__(256, 2) gemm_bf(const float* __restrict__ b0p,
                                                  const float* __restrict__ b1p,
                                                  const float* __restrict__ b2p,
                                                  float* __restrict__ Cout)
{
    extern __shared__ __align__(16) char gsm[];
    __nv_bfloat16* Sm = (__nv_bfloat16*)gsm;

    const int z = (MODE == 0) ? blockIdx.z : 3;
    const __nv_bfloat16* gAh = (MODE == 4) ? g_ah : g_xh;
    const __nv_bfloat16* gAl = (MODE == 4) ? g_al : g_xl;
    const __nv_bfloat16* gBh = g_wth[z];
    const __nv_bfloat16* gBl = g_wtl[z];
    const float* bias = (MODE == 4) ? b0p : (z == 0) ? b0p : (z == 1) ? b1p : b2p;

    const int bm = blockIdx.x * 128, bn = blockIdx.y * 128;
    const int t = threadIdx.x, lane = t & 31, w = t >> 5;
    const int wm = (w >> 2) * 64, wn = (w & 3) * 32;

    float acc[4][4][4];
    #pragma unroll
    for (int i = 0; i < 4; i++)
        #pragma unroll
        for (int j = 0; j < 4; j++)
            #pragma unroll
            for (int q = 0; q < 4; q++) acc[i][j][q] = 0.f;

    auto prefetch = [&](int kt, int stage) {
        const int k0 = kt * 32;
        __nv_bfloat16* base = Sm + stage * 4 * GTILE;
        #pragma unroll
        for (int i = 0; i < 8; i++) {
            const int c = t + i * 256;
            const int tile = c >> 9, cc = c & 511;
            const int row = cc >> 2, col = (cc & 3) * 8;
            const __nv_bfloat16* g = (tile == 0) ? gAh : (tile == 1) ? gAl
                                   : (tile == 2) ? gBh : gBl;
            const int gr = ((tile < 2) ? bm : bn) + row;
            cp16(base + tile * GTILE + row * GSTR + col,
                 g + (size_t)gr * DMODEL + k0 + col);
        }
        CP_COMMIT();
    };

    prefetch(0, 0);

    const int laneA = (lane & 15) * GSTR + (lane >> 4) * 8;
    const int laneB = ((lane & 7) + ((lane >> 4) & 1) * 8) * GSTR + ((lane >> 3) & 1) * 8;

    for (int kt = 0; kt < 24; kt++) {
        const int stage = kt & 1;
        CP_WAIT(0);
        __syncthreads();
        if (kt + 1 < 24) prefetch(kt + 1, stage ^ 1);

        const __nv_bfloat16* Ah = Sm + (stage * 4 + 0) * GTILE;
        const __nv_bfloat16* Al = Sm + (stage * 4 + 1) * GTILE;
        const __nv_bfloat16* Bh = Sm + (stage * 4 + 2) * GTILE;
        const __nv_bfloat16* Bl = Sm + (stage * 4 + 3) * GTILE;

        #pragma unroll
        for (int ks = 0; ks < 32; ks += 16) {
            uint32_t bh_[2][4], bl_[2][4];
            #pragma unroll
            for (int p = 0; p < 2; p++) {
                const int off = (wn + p * 16) * GSTR + ks + laneB;
                ldsm_x4(bh_[p][0], bh_[p][1], bh_[p][2], bh_[p][3], sm_addr(Bh + off));
                ldsm_x4(bl_[p][0], bl_[p][1], bl_[p][2], bl_[p][3], sm_addr(Bl + off));
            }
            #pragma unroll
            for (int mt_ = 0; mt_ < 4; mt_++) {
                const int off = (wm + mt_ * 16) * GSTR + ks + laneA;
                uint32_t ah_[4], al_[4];
                ldsm_x4(ah_[0], ah_[1], ah_[2], ah_[3], sm_addr(Ah + off));
                ldsm_x4(al_[0], al_[1], al_[2], al_[3], sm_addr(Al + off));
                #pragma unroll
                for (int p = 0; p < 2; p++) {
                    mma16(acc[mt_][2*p],   ah_, bh_[p][0], bh_[p][1]);
                    mma16(acc[mt_][2*p],   ah_, bl_[p][0], bl_[p][1]);
                    mma16(acc[mt_][2*p],   al_, bh_[p][0], bh_[p][1]);
                    mma16(acc[mt_][2*p+1], ah_, bh_[p][2], bh_[p][3]);
                    mma16(acc[mt_][2*p+1], ah_, bl_[p][2], bl_[p][3]);
                    mma16(acc[mt_][2*p+1], al_, bh_[p][2], bh_[p][3]);
                }
            }
        }
    }

    // ---- epilogue ----
    #pragma unroll
    for (int mt_ = 0; mt_ < 4; mt_++) {
        #pragma unroll
        for (int nt = 0; nt < 4; nt++) {
            const int n0 = bn + wn + nt*8 + 2*(lane & 3);
            const float bb0 = bias[n0], bb1 = bias[n0+1];
            #pragma unroll
            for (int half_ = 0; half_ < 2; half_++) {
                const int r = bm + wm + mt_*16 + (lane >> 2) + half_*8;
                float c0 = acc[mt_][nt][half_*2+0] + bb0;
                float c1 = acc[mt_][nt][half_*2+1] + bb1;
                if (MODE == 4) {
                    *(float2*)&Cout[(size_t)r*DMODEL + n0] = make_float2(c0, c1);
                } else {
                    const int b_ = r >> 10, s = r & (SEQ-1);
                    const int h_ = n0 >> 6, d = n0 & 63;
                    const int bh_i = b_ * NHEAD + h_;
                    const size_t o = ((size_t)bh_i*SEQ + s)*HDIM + d;
                    if (z == 2) {
                        uint32_t Hu, Lu;
                        packsplit_h(c0, c1, Hu, Lu);
                        *(uint32_t*)&g_vh[o] = Hu;
                        *(uint32_t*)&g_vl[o] = Lu;
                    } else {
                        if (z == 0) { c0 *= QSCALE; c1 *= QSCALE; }
                        uint32_t Hu, Lu;
                        packsplit(c0, c1, Hu, Lu);
                        __nv_bfloat16* Hd = (z == 0) ? g_qh : g_kh;
                        __nv_bfloat16* Ld = (z == 0) ? g_ql : g_kl;
                        *(uint32_t*)&Hd[o] = Hu;
                        *(uint32_t*)&Ld[o] = Lu;
                    }
                }
            }
        }
    }
}

// ------------------------- flash attention v7 --------------------------------
// 128-q tile, 8 warps; warp w owns q rows [w*16, w*16+16) over ALL 64 keys.
// S: bf16 3-term. Softmax: paired h2exp2 -> P is EXACT fp16 (A-fragments
// directly, no split). PV: fp16 MMA, P * (Vh + Vl), 2 terms.
#define ASTR 72
#define KVTILE (64*ASTR)
#define QTILE (128*ASTR)
#define ATTN_SMEM ((2*QTILE + 8*KVTILE)*2)    // 110,592 B

__global__ void __launch_bounds__(256, 2) attn_bf()
{
    extern __shared__ __align__(16) char smraw[];
    __nv_bfloat16* Qh = (__nv_bfloat16*)smraw;
    __nv_bfloat16* Ql = Qh + QTILE;
    __nv_bfloat16* KV = Ql + QTILE;            // [2 stages][Kh,Kl,Vh,Vl]

    const int t = threadIdx.x, lane = t & 31, w = t >> 5;
    const int qt = blockIdx.x, bh = blockIdx.y;
    const int mt = w * 16;

    const size_t qoff = ((size_t)bh*SEQ + qt*128)*HDIM;
    const size_t koff = (size_t)bh*SEQ*HDIM;

    const int laneA = (lane & 15) * ASTR + (lane >> 4) * 8;
    const int laneB = ((lane & 7) + ((lane >> 4) & 1) * 8) * ASTR + ((lane >> 3) & 1) * 8;
    const int laneV = (lane & 15) * ASTR + (lane >> 4) * 8;   // trans: rows=keys

    // Q load
    #pragma unroll
    for (int i = 0; i < 8; i++) {
        const int c = t + i * 256;
        const int tile = c >> 10, cc = c & 1023;
        const int r = cc >> 3, col = (cc & 7) * 8;
        cp16((tile ? Ql : Qh) + r*ASTR + col,
             (tile ? g_ql : g_qh) + qoff + r*HDIM + col);
    }
    CP_COMMIT();

    auto prefetch = [&](int kt, int st) {
        __nv_bfloat16* base = KV + st * 4 * KVTILE;
        #pragma unroll
        for (int i = 0; i < 8; i++) {
            const int c = t + i * 256;
            const int tile = c >> 9, cc = c & 511;
            const int r = cc >> 3, col = (cc & 7) * 8;
            const void* g;
            if      (tile == 0) g = g_kh + koff + (size_t)(kt*64 + r)*HDIM + col;
            else if (tile == 1) g = g_kl + koff + (size_t)(kt*64 + r)*HDIM + col;
            else if (tile == 2) g = g_vh + koff + (size_t)(kt*64 + r)*HDIM + col;
            else                g = g_vl + koff + (size_t)(kt*64 + r)*HDIM + col;
            cp16(base + tile*KVTILE + r*ASTR + col, g);
        }
        CP_COMMIT();
    };

    prefetch(0, 0);

    float m0 = -1e30f, m1 = -1e30f, l0 = 0.f, l1 = 0.f;
    float o[8][4];
    #pragma unroll
    for (int i = 0; i < 8; i++)
        #pragma unroll
        for (int j = 0; j < 4; j++) o[i][j] = 0.f;

    for (int kt = 0; kt < SEQ/64; kt++) {
        const int st = kt & 1;
        CP_WAIT(0);
        __syncthreads();
        if (kt + 1 < SEQ/64) prefetch(kt + 1, st ^ 1);

        const __nv_bfloat16* Kh = KV + (st*4 + 0)*KVTILE;
        const __nv_bfloat16* Kl = KV + (st*4 + 1)*KVTILE;
        const __nv_bfloat16* Vh = KV + (st*4 + 2)*KVTILE;   // fp16 data
        const __nv_bfloat16* Vl = KV + (st*4 + 3)*KVTILE;   // fp16 data

        // ---- S[16 x 64] = Q K^T  (log2 units) ----
        float sc[8][4];
        #pragma unroll
        for (int i = 0; i < 8; i++)
            #pragma unroll
            for (int j = 0; j < 4; j++) sc[i][j] = 0.f;

        #pragma unroll
        for (int ks4 = 0; ks4 < 4; ks4++) {
            uint32_t qh_[4], ql_[4];
            const int qo = mt*ASTR + ks4*16 + laneA;
            ldsm_x4(qh_[0], qh_[1], qh_[2], qh_[3], sm_addr(Qh + qo));
            ldsm_x4(ql_[0], ql_[1], ql_[2], ql_[3], sm_addr(Ql + qo));
            #pragma unroll
            for (int p = 0; p < 4; p++) {
                uint32_t kh_[4], kl_[4];
                const int off = (p*16)*ASTR + ks4*16 + laneB;
                ldsm_x4(kh_[0], kh_[1], kh_[2], kh_[3], sm_addr(Kh + off));
                ldsm_x4(kl_[0], kl_[1], kl_[2], kl_[3], sm_addr(Kl + off));
                mma16(sc[2*p],   qh_, kh_[0], kh_[1]);
                mma16(sc[2*p],   qh_, kl_[0], kl_[1]);
                mma16(sc[2*p],   ql_, kh_[0], kh_[1]);
                mma16(sc[2*p+1], qh_, kh_[2], kh_[3]);
                mma16(sc[2*p+1], qh_, kl_[2], kl_[3]);
                mma16(sc[2*p+1], ql_, kh_[2], kh_[3]);
            }
        }

        // ---- warp-local online softmax (base-2, fp16 P via h2exp2) ----
        float mx0 = sc[0][0], mx1 = sc[0][2];
        #pragma unroll
        for (int nt = 0; nt < 8; nt++) {
            mx0 = fmaxf(mx0, fmaxf(sc[nt][0], sc[nt][1]));
            mx1 = fmaxf(mx1, fmaxf(sc[nt][2], sc[nt][3]));
        }
        mx0 = fmaxf(mx0, __shfl_xor_sync(0xffffffffu, mx0, 1));
        mx0 = fmaxf(mx0, __shfl_xor_sync(0xffffffffu, mx0, 2));
        mx1 = fmaxf(mx1, __shfl_xor_sync(0xffffffffu, mx1, 1));
        mx1 = fmaxf(mx1, __shfl_xor_sync(0xffffffffu, mx1, 2));
        const float mn0 = fmaxf(m0, mx0), mn1 = fmaxf(m1, mx1);
        const float cr0 = ex2(m0 - mn0), cr1 = ex2(m1 - mn1);
        m0 = mn0; m1 = mn1;

        uint32_t pa[8], pb[8];
        float s0 = 0.f, s1 = 0.f;
        #pragma unroll
        for (int nt = 0; nt < 8; nt++) {
            __half2 e0 = h2exp2(__floats2half2_rn(sc[nt][0] - mn0, sc[nt][1] - mn0));
            __half2 e1 = h2exp2(__floats2half2_rn(sc[nt][2] - mn1, sc[nt][3] - mn1));
            pa[nt] = *reinterpret_cast<uint32_t*>(&e0);
            pb[nt] = *reinterpret_cast<uint32_t*>(&e1);
            float2 f0 = __half22float2(e0), f1 = __half22float2(e1);
            s0 += f0.x + f0.y;
            s1 += f1.x + f1.y;
        }
        s0 += __shfl_xor_sync(0xffffffffu, s0, 1);
        s0 += __shfl_xor_sync(0xffffffffu, s0, 2);
        s1 += __shfl_xor_sync(0xffffffffu, s1, 1);
        s1 += __shfl_xor_sync(0xffffffffu, s1, 2);
        l0 = l0*cr0 + s0;
        l1 = l1*cr1 + s1;

        #pragma unroll
        for (int nt = 0; nt < 8; nt++) {
            o[nt][0] *= cr0; o[nt][1] *= cr0;
            o[nt][2] *= cr1; o[nt][3] *= cr1;
        }

        // ---- O += P V (fp16: P exact, V 2-term) ----
        #pragma unroll
        for (int c = 0; c < 4; c++) {
            const uint32_t ph_[4] = { pa[2*c], pb[2*c], pa[2*c+1], pb[2*c+1] };
            #pragma unroll
            for (int p = 0; p < 4; p++) {
                uint32_t vh_[4], vl_[4];
                const int off = (c*16)*ASTR + p*16 + laneV;
                ldsm_x4_t(vh_[0], vh_[1], vh_[2], vh_[3], sm_addr(Vh + off));
                ldsm_x4_t(vl_[0], vl_[1], vl_[2], vl_[3], sm_addr(Vl + off));
                mma16h(o[2*p],   ph_, vh_[0], vh_[1]);
                mma16h(o[2*p],   ph_, vl_[0], vl_[1]);
                mma16h(o[2*p+1], ph_, vh_[2], vh_[3]);
                mma16h(o[2*p+1], ph_, vl_[2], vl_[3]);
            }
        }
    }

    // ---- normalize + write split-bf16 [B,S,D] ----
    const int b_ = bh / NHEAD, h_ = bh % NHEAD;
    const int r0 = mt + (lane >> 2);
    const float inv0 = 1.f / l0, inv1 = 1.f / l1;
    const size_t row0 = (size_t)b_*SEQ + qt*128 + r0;
    #pragma unroll
    for (int nt = 0; nt < 8; nt++) {
        const int cc = nt*8 + 2*(lane & 3);
        uint32_t Hu, Lu;
        packsplit(o[nt][0]*inv0, o[nt][1]*inv0, Hu, Lu);
        *(uint32_t*)&g_ah[row0*DMODEL + h_*HDIM + cc] = Hu;
        *(uint32_t*)&g_al[row0*DMODEL + h_*HDIM + cc] = Lu;
        packsplit(o[nt][2]*inv1, o[nt][3]*inv1, Hu, Lu);
        *(uint32_t*)&g_ah[(row0 + 8)*DMODEL + h_*HDIM + cc] = Hu;
        *(uint32_t*)&g_al[(row0 + 8)*DMODEL + h_*HDIM + cc] = Lu;
    }
}

// ---------------------------------------------------------------------------
extern "C" void kernel_launch(void* const* d_in, const int* in_sizes, int n_in,
                              void* d_out, int out_size)
{
    (void)in_sizes; (void)n_in; (void)out_size;
    const float* x  = (const float*)d_in[0];
    const float* Wq = (const float*)d_in[1];
    const float* bq = (const float*)d_in[2];
    const float* Wk = (const float*)d_in[3];
    const float* bk = (const float*)d_in[4];
    const float* Wv = (const float*)d_in[5];
    const float* bv = (const float*)d_in[6];
    const float* Wo = (const float*)d_in[7];
    const float* bo = (const float*)d_in[8];
    float* out = (float*)d_out;

    prep_x<<<(MROWS*DMODEL/4)/256, 256>>>(x);
    prep_wt<<<dim3(DMODEL/32, DMODEL/32, 4), 256>>>(Wq, Wk, Wv, Wo);

    cudaFuncSetAttribute(gemm_bf<0>, cudaFuncAttributeMaxDynamicSharedMemorySize, GEMM_SMEM);
    cudaFuncSetAttribute(gemm_bf<4>, cudaFuncAttributeMaxDynamicSharedMemorySize, GEMM_SMEM);
    cudaFuncSetAttribute(attn_bf, cudaFuncAttributeMaxDynamicSharedMemorySize, ATTN_SMEM);

    dim3 gq(MROWS/128, DMODEL/128, 3);   // fused QKV
    gemm_bf<0><<<gq, 256, GEMM_SMEM>>>(bq, bk, bv, nullptr);

    attn_bf<<<dim3(SEQ/128, BATCH*NHEAD), 256, ATTN_SMEM>>>();

    dim3 gg(MROWS/128, DMODEL/128);
    gemm_bf<4><<<gg, 256, GEMM_SMEM>>>(bo, nullptr, nullptr, out);
}

// round 13
// speedup vs baseline: 4.3319x; 1.0665x over previous
#include <cuda_runtime.h>
#include <cuda_bf16.h>
#include <cuda_fp16.h>
#include <math.h>
#include <stdint.h>

#define BATCH 8
#define SEQ 1024
#define DMODEL 768
#define NHEAD 12
#define HDIM 64
#define MROWS (BATCH*SEQ)

// sqrt(1/sqrt(64) * log2(e)) — applied to BOTH Q and K so S lands in log2 domain
#define QSC2 0.42466089981329596f

// ------------------------- device scratch (no allocs) -----------------------
__device__ __align__(16) __nv_bfloat16 g_xh[MROWS*DMODEL];      // x split [M][K]
__device__ __align__(16) __nv_bfloat16 g_xl[MROWS*DMODEL];
__device__ __align__(16) __nv_bfloat16 g_wth[4][DMODEL*DMODEL]; // W^T split [N][K]
__device__ __align__(16) __nv_bfloat16 g_wtl[4][DMODEL*DMODEL];
__device__ __align__(16) __half       g_qh[MROWS*DMODEL];       // Q*QSC2 fp16 split
__device__ __align__(16) __half       g_ql[MROWS*DMODEL];
__device__ __align__(16) __half       g_kh[MROWS*DMODEL];       // K*QSC2 fp16 SINGLE
__device__ __align__(16) __half       g_vh[MROWS*DMODEL];       // V fp16 split [bh][s][d]
__device__ __align__(16) __half       g_vl[MROWS*DMODEL];
__device__ __align__(16) __nv_bfloat16 g_ah[MROWS*DMODEL];      // attn out split [M][K]
__device__ __align__(16) __nv_bfloat16 g_al[MROWS*DMODEL];

// ------------------------- helpers ------------------------------------------
__device__ __forceinline__ void bsplit(float x, __nv_bfloat16& h, __nv_bfloat16& l) {
    h = __float2bfloat16_rn(x);
    l = __float2bfloat16_rn(x - __bfloat162float(h));
}
__device__ __forceinline__ void mma16(float c[4], const uint32_t a[4],
                                      uint32_t b0, uint32_t b1) {
    asm volatile("mma.sync.aligned.m16n8k16.row.col.f32.bf16.bf16.f32 "
        "{%0,%1,%2,%3}, {%4,%5,%6,%7}, {%8,%9}, {%0,%1,%2,%3};"
        : "+f"(c[0]), "+f"(c[1]), "+f"(c[2]), "+f"(c[3])
        : "r"(a[0]), "r"(a[1]), "r"(a[2]), "r"(a[3]), "r"(b0), "r"(b1));
}
__device__ __forceinline__ void mma16h(float c[4], const uint32_t a[4],
                                       uint32_t b0, uint32_t b1) {
    asm volatile("mma.sync.aligned.m16n8k16.row.col.f32.f16.f16.f32 "
        "{%0,%1,%2,%3}, {%4,%5,%6,%7}, {%8,%9}, {%0,%1,%2,%3};"
        : "+f"(c[0]), "+f"(c[1]), "+f"(c[2]), "+f"(c[3])
        : "r"(a[0]), "r"(a[1]), "r"(a[2]), "r"(a[3]), "r"(b0), "r"(b1));
}
__device__ __forceinline__ uint32_t sm_addr(const void* p) {
    return (uint32_t)__cvta_generic_to_shared(p);
}
__device__ __forceinline__ void ldsm_x4(uint32_t& r0, uint32_t& r1, uint32_t& r2,
                                        uint32_t& r3, uint32_t addr) {
    asm volatile("ldmatrix.sync.aligned.m8n8.x4.shared.b16 {%0,%1,%2,%3}, [%4];"
        : "=r"(r0), "=r"(r1), "=r"(r2), "=r"(r3) : "r"(addr));
}
__device__ __forceinline__ void ldsm_x4_t(uint32_t& r0, uint32_t& r1, uint32_t& r2,
                                          uint32_t& r3, uint32_t addr) {
    asm volatile("ldmatrix.sync.aligned.m8n8.x4.trans.shared.b16 {%0,%1,%2,%3}, [%4];"
        : "=r"(r0), "=r"(r1), "=r"(r2), "=r"(r3) : "r"(addr));
}
__device__ __forceinline__ void cp16(void* dst, const void* src) {
    asm volatile("cp.async.cg.shared.global [%0], [%1], 16;"
        :: "r"(sm_addr(dst)), "l"(src));
}
#define CP_COMMIT() asm volatile("cp.async.commit_group;" ::: "memory")
#define CP_WAIT(n)  asm volatile("cp.async.wait_group %0;" :: "n"(n) : "memory")
__device__ __forceinline__ float ex2(float x) {
    float r; asm("ex2.approx.ftz.f32 %0, %1;" : "=f"(r) : "f"(x)); return r;
}
// truncation-based split of two floats into packed bf16 high/low words
__device__ __forceinline__ void packsplit(float x, float y, uint32_t& H, uint32_t& L) {
    const uint32_t xb = __float_as_uint(x), yb = __float_as_uint(y);
    const uint32_t xh = xb & 0xFFFF0000u,  yh = yb & 0xFFFF0000u;
    H = __byte_perm(xh, yh, 0x7632);
    __nv_bfloat162 p = __floats2bfloat162_rn(x - __uint_as_float(xh),
                                             y - __uint_as_float(yh));
    L = *reinterpret_cast<uint32_t*>(&p);
}
// fp16 round-split of two floats
__device__ __forceinline__ void packsplit_h(float x, float y, uint32_t& H, uint32_t& L) {
    __half2 h = __floats2half2_rn(x, y);
    float2 hf = __half22float2(h);
    __half2 l = __floats2half2_rn(x - hf.x, y - hf.y);
    H = *reinterpret_cast<uint32_t*>(&h);
    L = *reinterpret_cast<uint32_t*>(&l);
}

// ------------------------- prep kernels -------------------------------------
__global__ void __launch_bounds__(256) prep_x(const float* __restrict__ x)
{
    const int i = blockIdx.x * 256 + threadIdx.x;
    float4 v = ((const float4*)x)[i];
    union { __nv_bfloat16 b[4]; uint2 u; } H, L;
    bsplit(v.x, H.b[0], L.b[0]); bsplit(v.y, H.b[1], L.b[1]);
    bsplit(v.z, H.b[2], L.b[2]); bsplit(v.w, H.b[3], L.b[3]);
    ((uint2*)g_xh)[i] = H.u;
    ((uint2*)g_xl)[i] = L.u;
}

__global__ void __launch_bounds__(256) prep_wt(const float* __restrict__ Wq,
                                               const float* __restrict__ Wk,
                                               const float* __restrict__ Wv,
                                               const float* __restrict__ Wo)
{
    __shared__ float tile[32][33];
    const int wid = blockIdx.z;
    const float* W = (wid == 0) ? Wq : (wid == 1) ? Wk : (wid == 2) ? Wv : Wo;
    const int n0 = blockIdx.x * 32, k0 = blockIdx.y * 32;
    const int tx = threadIdx.x & 31, ty = threadIdx.x >> 5;
    #pragma unroll
    for (int i = 0; i < 32; i += 8)
        tile[ty + i][tx] = W[(size_t)(k0 + ty + i) * DMODEL + n0 + tx];
    __syncthreads();
    #pragma unroll
    for (int i = 0; i < 32; i += 8) {
        float v = tile[tx][ty + i];
        __nv_bfloat16 h, l; bsplit(v, h, l);
        g_wth[wid][(size_t)(n0 + ty + i) * DMODEL + k0 + tx] = h;
        g_wtl[wid][(size_t)(n0 + ty + i) * DMODEL + k0 + tx] = l;
    }
}

// ------------------------- bf16 split GEMM (single-sync pipeline) ------------
// MODE 0: fused QKV (blockIdx.z)   MODE 4: O proj -> fp32 out
#define GSTR 40
#define GTILE (128*GSTR)
#define GEMM_SMEM (2*4*GTILE*2)               // 81,920 B

template<int MODE>
__global__ void __launch_bounds__(256, 2) gemm_bf(const float* __restrict__ b0p,
                                                  const float* __restrict__ b1p,
                                                  const float* __restrict__ b2p,
                                                  float* __restrict__ Cout)
{
    extern __shared__ __align__(16) char gsm[];
    __nv_bfloat16* Sm = (__nv_bfloat16*)gsm;

    const int z = (MODE == 0) ? blockIdx.z : 3;
    const __nv_bfloat16* gAh = (MODE == 4) ? g_ah : g_xh;
    const __nv_bfloat16* gAl = (MODE == 4) ? g_al : g_xl;
    const __nv_bfloat16* gBh = g_wth[z];
    const __nv_bfloat16* gBl = g_wtl[z];
    const float* bias = (MODE == 4) ? b0p : (z == 0) ? b0p : (z == 1) ? b1p : b2p;

    const int bm = blockIdx.x * 128, bn = blockIdx.y * 128;
    const int t = threadIdx.x, lane = t & 31, w = t >> 5;
    const int wm = (w >> 2) * 64, wn = (w & 3) * 32;

    float acc[4][4][4];
    #pragma unroll
    for (int i = 0; i < 4; i++)
        #pragma unroll
        for (int j = 0; j < 4; j++)
            #pragma unroll
            for (int q = 0; q < 4; q++) acc[i][j][q] = 0.f;

    auto prefetch = [&](int kt, int stage) {
        const int k0 = kt * 32;
        __nv_bfloat16* base = Sm + stage * 4 * GTILE;
        #pragma unroll
        for (int i = 0; i < 8; i++) {
            const int c = t + i * 256;
            const int tile = c >> 9, cc = c & 511;
            const int row = cc >> 2, col = (cc & 3) * 8;
            const __nv_bfloat16* g = (tile == 0) ? gAh : (tile == 1) ? gAl
                                   : (tile == 2) ? gBh : gBl;
            const int gr = ((tile < 2) ? bm : bn) + row;
            cp16(base + tile * GTILE + row * GSTR + col,
                 g + (size_t)gr * DMODEL + k0 + col);
        }
        CP_COMMIT();
    };

    prefetch(0, 0);

    const int laneA = (lane & 15) * GSTR + (lane >> 4) * 8;
    const int laneB = ((lane & 7) + ((lane >> 4) & 1) * 8) * GSTR + ((lane >> 3) & 1) * 8;

    for (int kt = 0; kt < 24; kt++) {
        const int stage = kt & 1;
        CP_WAIT(0);
        __syncthreads();
        if (kt + 1 < 24) prefetch(kt + 1, stage ^ 1);

        const __nv_bfloat16* Ah = Sm + (stage * 4 + 0) * GTILE;
        const __nv_bfloat16* Al = Sm + (stage * 4 + 1) * GTILE;
        const __nv_bfloat16* Bh = Sm + (stage * 4 + 2) * GTILE;
        const __nv_bfloat16* Bl = Sm + (stage * 4 + 3) * GTILE;

        #pragma unroll
        for (int ks = 0; ks < 32; ks += 16) {
            uint32_t bh_[2][4], bl_[2][4];
            #pragma unroll
            for (int p = 0; p < 2; p++) {
                const int off = (wn + p * 16) * GSTR + ks + laneB;
                ldsm_x4(bh_[p][0], bh_[p][1], bh_[p][2], bh_[p][3], sm_addr(Bh + off));
                ldsm_x4(bl_[p][0], bl_[p][1], bl_[p][2], bl_[p][3], sm_addr(Bl + off));
            }
            #pragma unroll
            for (int mt_ = 0; mt_ < 4; mt_++) {
                const int off = (wm + mt_ * 16) * GSTR + ks + laneA;
                uint32_t ah_[4], al_[4];
                ldsm_x4(ah_[0], ah_[1], ah_[2], ah_[3], sm_addr(Ah + off));
                ldsm_x4(al_[0], al_[1], al_[2], al_[3], sm_addr(Al + off));
                #pragma unroll
                for (int p = 0; p < 2; p++) {
                    mma16(acc[mt_][2*p],   ah_, bh_[p][0], bh_[p][1]);
                    mma16(acc[mt_][2*p],   ah_, bl_[p][0], bl_[p][1]);
                    mma16(acc[mt_][2*p],   al_, bh_[p][0], bh_[p][1]);
                    mma16(acc[mt_][2*p+1], ah_, bh_[p][2], bh_[p][3]);
                    mma16(acc[mt_][2*p+1], ah_, bl_[p][2], bl_[p][3]);
                    mma16(acc[mt_][2*p+1], al_, bh_[p][2], bh_[p][3]);
                }
            }
        }
    }

    // ---- epilogue ----
    #pragma unroll
    for (int mt_ = 0; mt_ < 4; mt_++) {
        #pragma unroll
        for (int nt = 0; nt < 4; nt++) {
            const int n0 = bn + wn + nt*8 + 2*(lane & 3);
            const float bb0 = bias[n0], bb1 = bias[n0+1];
            #pragma unroll
            for (int half_ = 0; half_ < 2; half_++) {
                const int r = bm + wm + mt_*16 + (lane >> 2) + half_*8;
                float c0 = acc[mt_][nt][half_*2+0] + bb0;
                float c1 = acc[mt_][nt][half_*2+1] + bb1;
                if (MODE == 4) {
                    *(float2*)&Cout[(size_t)r*DMODEL + n0] = make_float2(c0, c1);
                } else {
                    const int b_ = r >> 10, s = r & (SEQ-1);
                    const int h_ = n0 >> 6, d = n0 & 63;
                    const int bh_i = b_ * NHEAD + h_;
                    const size_t o = ((size_t)bh_i*SEQ + s)*HDIM + d;
                    if (z == 0) {          // Q: fp16 2-term, scaled
                        uint32_t Hu, Lu;
                        packsplit_h(c0 * QSC2, c1 * QSC2, Hu, Lu);
                        *(uint32_t*)&g_qh[o] = Hu;
                        *(uint32_t*)&g_ql[o] = Lu;
                    } else if (z == 1) {   // K: fp16 SINGLE, scaled
                        __half2 hv = __floats2half2_rn(c0 * QSC2, c1 * QSC2);
                        *(uint32_t*)&g_kh[o] = *reinterpret_cast<uint32_t*>(&hv);
                    } else {               // V: fp16 2-term
                        uint32_t Hu, Lu;
                        packsplit_h(c0, c1, Hu, Lu);
                        *(uint32_t*)&g_vh[o] = Hu;
                        *(uint32_t*)&g_vl[o] = Lu;
                    }
                }
            }
        }
    }
}

// ------------------------- flash attention v8 --------------------------------
// 128-q tile, 8 warps; warp w owns q rows [w*16, w*16+16) over ALL 64 keys.
// ALL-fp16 tensor path: S = (Qh+Ql)·K (K single fp16, 2 MMAs), softmax via
// h2exp2 -> exact fp16 P, PV = P·(Vh+Vl) (2 MMAs). K/V: 3 tiles/stage.
#define ASTR 72
#define KVTILE (64*ASTR)
#define QTILE (128*ASTR)
#define ATTN_SMEM ((2*QTILE + 6*KVTILE)*2)    // 92,160 B

__global__ void __launch_bounds__(256, 2) attn_bf()
{
    extern __shared__ __align__(16) char smraw[];
    __half* Qh = (__half*)smraw;
    __half* Ql = Qh + QTILE;
    __half* KV = Ql + QTILE;                   // [2 stages][K, Vh, Vl]

    const int t = threadIdx.x, lane = t & 31, w = t >> 5;
    const int qt = blockIdx.x, bh = blockIdx.y;
    const int mt = w * 16;

    const size_t qoff = ((size_t)bh*SEQ + qt*128)*HDIM;
    const size_t koff = (size_t)bh*SEQ*HDIM;

    const int laneA = (lane & 15) * ASTR + (lane >> 4) * 8;
    const int laneB = ((lane & 7) + ((lane >> 4) & 1) * 8) * ASTR + ((lane >> 3) & 1) * 8;
    const int laneV = (lane & 15) * ASTR + (lane >> 4) * 8;   // trans: rows=keys

    // Q load (2 tiles x 128 rows x 8 chunks = 2048)
    #pragma unroll
    for (int i = 0; i < 8; i++) {
        const int c = t + i * 256;
        const int tile = c >> 10, cc = c & 1023;
        const int r = cc >> 3, col = (cc & 7) * 8;
        cp16((tile ? Ql : Qh) + r*ASTR + col,
             (tile ? g_ql : g_qh) + qoff + r*HDIM + col);
    }
    CP_COMMIT();

    auto prefetch = [&](int kt, int st) {
        __half* base = KV + st * 3 * KVTILE;
        #pragma unroll
        for (int i = 0; i < 6; i++) {       // 3 tiles x 512 chunks = 1536
            const int c = t + i * 256;
            const int tile = c >> 9, cc = c & 511;
            const int r = cc >> 3, col = (cc & 7) * 8;
            const __half* g = (tile == 0) ? g_kh : (tile == 1) ? g_vh : g_vl;
            cp16(base + tile*KVTILE + r*ASTR + col,
                 g + koff + (size_t)(kt*64 + r)*HDIM + col);
        }
        CP_COMMIT();
    };

    prefetch(0, 0);

    float m0 = -1e30f, m1 = -1e30f, l0 = 0.f, l1 = 0.f;
    float o[8][4];
    #pragma unroll
    for (int i = 0; i < 8; i++)
        #pragma unroll
        for (int j = 0; j < 4; j++) o[i][j] = 0.f;

    for (int kt = 0; kt < SEQ/64; kt++) {
        const int st = kt & 1;
        CP_WAIT(0);
        __syncthreads();
        if (kt + 1 < SEQ/64) prefetch(kt + 1, st ^ 1);

        const __half* Ks = KV + (st*3 + 0)*KVTILE;
        const __half* Vh = KV + (st*3 + 1)*KVTILE;
        const __half* Vl = KV + (st*3 + 2)*KVTILE;

        // ---- S[16 x 64] = (Qh+Ql) K^T  (log2 units, fp16 MMA) ----
        float sc[8][4];
        #pragma unroll
        for (int i = 0; i < 8; i++)
            #pragma unroll
            for (int j = 0; j < 4; j++) sc[i][j] = 0.f;

        #pragma unroll
        for (int ks4 = 0; ks4 < 4; ks4++) {
            uint32_t qh_[4], ql_[4];
            const int qo = mt*ASTR + ks4*16 + laneA;
            ldsm_x4(qh_[0], qh_[1], qh_[2], qh_[3], sm_addr(Qh + qo));
            ldsm_x4(ql_[0], ql_[1], ql_[2], ql_[3], sm_addr(Ql + qo));
            #pragma unroll
            for (int p = 0; p < 4; p++) {
                uint32_t kk[4];
                const int off = (p*16)*ASTR + ks4*16 + laneB;
                ldsm_x4(kk[0], kk[1], kk[2], kk[3], sm_addr(Ks + off));
                mma16h(sc[2*p],   qh_, kk[0], kk[1]);
                mma16h(sc[2*p],   ql_, kk[0], kk[1]);
                mma16h(sc[2*p+1], qh_, kk[2], kk[3]);
                mma16h(sc[2*p+1], ql_, kk[2], kk[3]);
            }
        }

        // ---- warp-local online softmax (base-2, fp16 P via h2exp2) ----
        float mx0 = sc[0][0], mx1 = sc[0][2];
        #pragma unroll
        for (int nt = 0; nt < 8; nt++) {
            mx0 = fmaxf(mx0, fmaxf(sc[nt][0], sc[nt][1]));
            mx1 = fmaxf(mx1, fmaxf(sc[nt][2], sc[nt][3]));
        }
        mx0 = fmaxf(mx0, __shfl_xor_sync(0xffffffffu, mx0, 1));
        mx0 = fmaxf(mx0, __shfl_xor_sync(0xffffffffu, mx0, 2));
        mx1 = fmaxf(mx1, __shfl_xor_sync(0xffffffffu, mx1, 1));
        mx1 = fmaxf(mx1, __shfl_xor_sync(0xffffffffu, mx1, 2));
        const float mn0 = fmaxf(m0, mx0), mn1 = fmaxf(m1, mx1);
        const float cr0 = ex2(m0 - mn0), cr1 = ex2(m1 - mn1);
        m0 = mn0; m1 = mn1;

        uint32_t pa[8], pb[8];
        float s0 = 0.f, s1 = 0.f;
        #pragma unroll
        for (int nt = 0; nt < 8; nt++) {
            __half2 e0 = h2exp2(__floats2half2_rn(sc[nt][0] - mn0, sc[nt][1] - mn0));
            __half2 e1 = h2exp2(__floats2half2_rn(sc[nt][2] - mn1, sc[nt][3] - mn1));
            pa[nt] = *reinterpret_cast<uint32_t*>(&e0);
            pb[nt] = *reinterpret_cast<uint32_t*>(&e1);
            float2 f0 = __half22float2(e0), f1 = __half22float2(e1);
            s0 += f0.x + f0.y;
            s1 += f1.x + f1.y;
        }
        s0 += __shfl_xor_sync(0xffffffffu, s0, 1);
        s0 += __shfl_xor_sync(0xffffffffu, s0, 2);
        s1 += __shfl_xor_sync(0xffffffffu, s1, 1);
        s1 += __shfl_xor_sync(0xffffffffu, s1, 2);
        l0 = l0*cr0 + s0;
        l1 = l1*cr1 + s1;

        #pragma unroll
        for (int nt = 0; nt < 8; nt++) {
            o[nt][0] *= cr0; o[nt][1] *= cr0;
            o[nt][2] *= cr1; o[nt][3] *= cr1;
        }

        // ---- O += P V (fp16: P exact, V 2-term) ----
        #pragma unroll
        for (int c = 0; c < 4; c++) {
            const uint32_t ph_[4] = { pa[2*c], pb[2*c], pa[2*c+1], pb[2*c+1] };
            #pragma unroll
            for (int p = 0; p < 4; p++) {
                uint32_t vh_[4], vl_[4];
                const int off = (c*16)*ASTR + p*16 + laneV;
                ldsm_x4_t(vh_[0], vh_[1], vh_[2], vh_[3], sm_addr(Vh + off));
                ldsm_x4_t(vl_[0], vl_[1], vl_[2], vl_[3], sm_addr(Vl + off));
                mma16h(o[2*p],   ph_, vh_[0], vh_[1]);
                mma16h(o[2*p],   ph_, vl_[0], vl_[1]);
                mma16h(o[2*p+1], ph_, vh_[2], vh_[3]);
                mma16h(o[2*p+1], ph_, vl_[2], vl_[3]);
            }
        }
    }

    // ---- normalize + write split-bf16 [B,S,D] ----
    const int b_ = bh / NHEAD, h_ = bh % NHEAD;
    const int r0 = mt + (lane >> 2);
    const float inv0 = 1.f / l0, inv1 = 1.f / l1;
    const size_t row0 = (size_t)b_*SEQ + qt*128 + r0;
    #pragma unroll
    for (int nt = 0; nt < 8; nt++) {
        const int cc = nt*8 + 2*(lane & 3);
        uint32_t Hu, Lu;
        packsplit(o[nt][0]*inv0, o[nt][1]*inv0, Hu, Lu);
        *(uint32_t*)&g_ah[row0*DMODEL + h_*HDIM + cc] = Hu;
        *(uint32_t*)&g_al[row0*DMODEL + h_*HDIM + cc] = Lu;
        packsplit(o[nt][2]*inv1, o[nt][3]*inv1, Hu, Lu);
        *(uint32_t*)&g_ah[(row0 + 8)*DMODEL + h_*HDIM + cc] = Hu;
        *(uint32_t*)&g_al[(row0 + 8)*DMODEL + h_*HDIM + cc] = Lu;
    }
}

// ---------------------------------------------------------------------------
extern "C" void kernel_launch(void* const* d_in, const int* in_sizes, int n_in,
                              void* d_out, int out_size)
{
    (void)in_sizes; (void)n_in; (void)out_size;
    const float* x  = (const float*)d_in[0];
    const float* Wq = (const float*)d_in[1];
    const float* bq = (const float*)d_in[2];
    const float* Wk = (const float*)d_in[3];
    const float* bk = (const float*)d_in[4];
    const float* Wv = (const float*)d_in[5];
    const float* bv = (const float*)d_in[6];
    const float* Wo = (const float*)d_in[7];
    const float* bo = (const float*)d_in[8];
    float* out = (float*)d_out;

    prep_x<<<(MROWS*DMODEL/4)/256, 256>>>(x);
    prep_wt<<<dim3(DMODEL/32, DMODEL/32, 4), 256>>>(Wq, Wk, Wv, Wo);

    cudaFuncSetAttribute(gemm_bf<0>, cudaFuncAttributeMaxDynamicSharedMemorySize, GEMM_SMEM);
    cudaFuncSetAttribute(gemm_bf<4>, cudaFuncAttributeMaxDynamicSharedMemorySize, GEMM_SMEM);
    cudaFuncSetAttribute(attn_bf, cudaFuncAttributeMaxDynamicSharedMemorySize, ATTN_SMEM);

    dim3 gq(MROWS/128, DMODEL/128, 3);   // fused QKV
    gemm_bf<0><<<gq, 256, GEMM_SMEM>>>(bq, bk, bv, nullptr);

    attn_bf<<<dim3(SEQ/128, BATCH*NHEAD), 256, ATTN_SMEM>>>();

    dim3 gg(MROWS/128, DMODEL/128);
    gemm_bf<4><<<gg, 256, GEMM_SMEM>>>(bo, nullptr, nullptr, out);
}

// round 14
// speedup vs baseline: 5.2955x; 1.2225x over previous
#include <cuda_runtime.h>
#include <cuda_bf16.h>
#include <cuda_fp16.h>
#include <math.h>
#include <stdint.h>

#define BATCH 8
#define SEQ 1024
#define DMODEL 768
#define NHEAD 12
#define HDIM 64
#define MROWS (BATCH*SEQ)

// sqrt(1/sqrt(64) * log2(e)) — applied to BOTH Q and K so S lands in log2 domain
#define QSC2 0.42466089981329596f

// ------------------------- device scratch (no allocs) -----------------------
__device__ __align__(16) __half g_xh[MROWS*DMODEL];       // x fp16 split [M][K]
__device__ __align__(16) __half g_xl[MROWS*DMODEL];
__device__ __align__(16) __half g_wt[4][DMODEL*DMODEL];   // W^T single fp16 [N][K]
__device__ __align__(16) __half g_qh[MROWS*DMODEL];       // Q*QSC2 fp16 split
__device__ __align__(16) __half g_ql[MROWS*DMODEL];
__device__ __align__(16) __half g_kh[MROWS*DMODEL];       // K*QSC2 fp16 SINGLE
__device__ __align__(16) __half g_vh[MROWS*DMODEL];       // V fp16 split [bh][s][d]
__device__ __align__(16) __half g_vl[MROWS*DMODEL];
__device__ __align__(16) __half g_ah[MROWS*DMODEL];       // attn out fp16 split [M][K]
__device__ __align__(16) __half g_al[MROWS*DMODEL];

// ------------------------- helpers ------------------------------------------
__device__ __forceinline__ void mma16h(float c[4], const uint32_t a[4],
                                       uint32_t b0, uint32_t b1) {
    asm volatile("mma.sync.aligned.m16n8k16.row.col.f32.f16.f16.f32 "
        "{%0,%1,%2,%3}, {%4,%5,%6,%7}, {%8,%9}, {%0,%1,%2,%3};"
        : "+f"(c[0]), "+f"(c[1]), "+f"(c[2]), "+f"(c[3])
        : "r"(a[0]), "r"(a[1]), "r"(a[2]), "r"(a[3]), "r"(b0), "r"(b1));
}
__device__ __forceinline__ uint32_t sm_addr(const void* p) {
    return (uint32_t)__cvta_generic_to_shared(p);
}
__device__ __forceinline__ void ldsm_x4(uint32_t& r0, uint32_t& r1, uint32_t& r2,
                                        uint32_t& r3, uint32_t addr) {
    asm volatile("ldmatrix.sync.aligned.m8n8.x4.shared.b16 {%0,%1,%2,%3}, [%4];"
        : "=r"(r0), "=r"(r1), "=r"(r2), "=r"(r3) : "r"(addr));
}
__device__ __forceinline__ void ldsm_x4_t(uint32_t& r0, uint32_t& r1, uint32_t& r2,
                                          uint32_t& r3, uint32_t addr) {
    asm volatile("ldmatrix.sync.aligned.m8n8.x4.trans.shared.b16 {%0,%1,%2,%3}, [%4];"
        : "=r"(r0), "=r"(r1), "=r"(r2), "=r"(r3) : "r"(addr));
}
__device__ __forceinline__ void cp16(void* dst, const void* src) {
    asm volatile("cp.async.cg.shared.global [%0], [%1], 16;"
        :: "r"(sm_addr(dst)), "l"(src));
}
#define CP_COMMIT() asm volatile("cp.async.commit_group;" ::: "memory")
#define CP_WAIT(n)  asm volatile("cp.async.wait_group %0;" :: "n"(n) : "memory")
__device__ __forceinline__ float ex2(float x) {
    float r; asm("ex2.approx.ftz.f32 %0, %1;" : "=f"(r) : "f"(x)); return r;
}
// fp16 round-split of two floats
__device__ __forceinline__ void packsplit_h(float x, float y, uint32_t& H, uint32_t& L) {
    __half2 h = __floats2half2_rn(x, y);
    float2 hf = __half22float2(h);
    __half2 l = __floats2half2_rn(x - hf.x, y - hf.y);
    H = *reinterpret_cast<uint32_t*>(&h);
    L = *reinterpret_cast<uint32_t*>(&l);
}

// ------------------------- prep kernels -------------------------------------
__global__ void __launch_bounds__(256) prep_x(const float* __restrict__ x)
{
    const int i = blockIdx.x * 256 + threadIdx.x;   // float4 index
    float4 v = ((const float4*)x)[i];
    uint32_t H0, L0, H1, L1;
    packsplit_h(v.x, v.y, H0, L0);
    packsplit_h(v.z, v.w, H1, L1);
    ((uint2*)g_xh)[i] = make_uint2(H0, H1);
    ((uint2*)g_xl)[i] = make_uint2(L0, L1);
}

__global__ void __launch_bounds__(256) prep_wt(const float* __restrict__ Wq,
                                               const float* __restrict__ Wk,
                                               const float* __restrict__ Wv,
                                               const float* __restrict__ Wo)
{
    __shared__ float tile[32][33];
    const int wid = blockIdx.z;
    const float* W = (wid == 0) ? Wq : (wid == 1) ? Wk : (wid == 2) ? Wv : Wo;
    const int n0 = blockIdx.x * 32, k0 = blockIdx.y * 32;
    const int tx = threadIdx.x & 31, ty = threadIdx.x >> 5;
    #pragma unroll
    for (int i = 0; i < 32; i += 8)
        tile[ty + i][tx] = W[(size_t)(k0 + ty + i) * DMODEL + n0 + tx];
    __syncthreads();
    #pragma unroll
    for (int i = 0; i < 32; i += 8)
        g_wt[wid][(size_t)(n0 + ty + i) * DMODEL + k0 + tx] =
            __float2half_rn(tile[tx][ty + i]);
}

// ------------------------- fp16 GEMM: A 2-term x W single --------------------
// MODE 0: fused QKV (blockIdx.z)   MODE 4: O proj -> fp32 out
// C = (Ah + Al) * W^T;  2 MMAs per k16 block.
#define GSTR 40
#define GTILE (128*GSTR)
#define GEMM_SMEM (2*3*GTILE*2)               // 61,440 B

template<int MODE>
__global__ void __launch_bounds__(256, 2) gemm_bf(const float* __restrict__ b0p,
                                                  const float* __restrict__ b1p,
                                                  const float* __restrict__ b2p,
                                                  float* __restrict__ Cout)
{
    extern __shared__ __align__(16) char gsm[];
    __half* Sm = (__half*)gsm;

    const int z = (MODE == 0) ? blockIdx.z : 3;
    const __half* gAh = (MODE == 4) ? g_ah : g_xh;
    const __half* gAl = (MODE == 4) ? g_al : g_xl;
    const __half* gB  = g_wt[z];
    const float* bias = (MODE == 4) ? b0p : (z == 0) ? b0p : (z == 1) ? b1p : b2p;

    const int bm = blockIdx.x * 128, bn = blockIdx.y * 128;
    const int t = threadIdx.x, lane = t & 31, w = t >> 5;
    const int wm = (w >> 2) * 64, wn = (w & 3) * 32;

    float acc[4][4][4];
    #pragma unroll
    for (int i = 0; i < 4; i++)
        #pragma unroll
        for (int j = 0; j < 4; j++)
            #pragma unroll
            for (int q = 0; q < 4; q++) acc[i][j][q] = 0.f;

    auto prefetch = [&](int kt, int stage) {
        const int k0 = kt * 32;
        __half* base = Sm + stage * 3 * GTILE;
        #pragma unroll
        for (int i = 0; i < 6; i++) {       // 3 tiles x 512 chunks = 1536
            const int c = t + i * 256;
            const int tile = c >> 9, cc = c & 511;
            const int row = cc >> 2, col = (cc & 3) * 8;
            const __half* g = (tile == 0) ? gAh : (tile == 1) ? gAl : gB;
            const int gr = ((tile < 2) ? bm : bn) + row;
            cp16(base + tile * GTILE + row * GSTR + col,
                 g + (size_t)gr * DMODEL + k0 + col);
        }
        CP_COMMIT();
    };

    prefetch(0, 0);

    const int laneA = (lane & 15) * GSTR + (lane >> 4) * 8;
    const int laneB = ((lane & 7) + ((lane >> 4) & 1) * 8) * GSTR + ((lane >> 3) & 1) * 8;

    for (int kt = 0; kt < 24; kt++) {
        const int stage = kt & 1;
        CP_WAIT(0);
        __syncthreads();
        if (kt + 1 < 24) prefetch(kt + 1, stage ^ 1);

        const __half* Ah = Sm + (stage * 3 + 0) * GTILE;
        const __half* Al = Sm + (stage * 3 + 1) * GTILE;
        const __half* Bs = Sm + (stage * 3 + 2) * GTILE;

        #pragma unroll
        for (int ks = 0; ks < 32; ks += 16) {
            uint32_t b_[2][4];
            #pragma unroll
            for (int p = 0; p < 2; p++) {
                const int off = (wn + p * 16) * GSTR + ks + laneB;
                ldsm_x4(b_[p][0], b_[p][1], b_[p][2], b_[p][3], sm_addr(Bs + off));
            }
            #pragma unroll
            for (int mt_ = 0; mt_ < 4; mt_++) {
                const int off = (wm + mt_ * 16) * GSTR + ks + laneA;
                uint32_t ah_[4], al_[4];
                ldsm_x4(ah_[0], ah_[1], ah_[2], ah_[3], sm_addr(Ah + off));
                ldsm_x4(al_[0], al_[1], al_[2], al_[3], sm_addr(Al + off));
                #pragma unroll
                for (int p = 0; p < 2; p++) {
                    mma16h(acc[mt_][2*p],   ah_, b_[p][0], b_[p][1]);
                    mma16h(acc[mt_][2*p],   al_, b_[p][0], b_[p][1]);
                    mma16h(acc[mt_][2*p+1], ah_, b_[p][2], b_[p][3]);
                    mma16h(acc[mt_][2*p+1], al_, b_[p][2], b_[p][3]);
                }
            }
        }
    }

    // ---- epilogue ----
    #pragma unroll
    for (int mt_ = 0; mt_ < 4; mt_++) {
        #pragma unroll
        for (int nt = 0; nt < 4; nt++) {
            const int n0 = bn + wn + nt*8 + 2*(lane & 3);
            const float bb0 = bias[n0], bb1 = bias[n0+1];
            #pragma unroll
            for (int half_ = 0; half_ < 2; half_++) {
                const int r = bm + wm + mt_*16 + (lane >> 2) + half_*8;
                float c0 = acc[mt_][nt][half_*2+0] + bb0;
                float c1 = acc[mt_][nt][half_*2+1] + bb1;
                if (MODE == 4) {
                    *(float2*)&Cout[(size_t)r*DMODEL + n0] = make_float2(c0, c1);
                } else {
                    const int b_ = r >> 10, s = r & (SEQ-1);
                    const int h_ = n0 >> 6, d = n0 & 63;
                    const int bh_i = b_ * NHEAD + h_;
                    const size_t o = ((size_t)bh_i*SEQ + s)*HDIM + d;
                    if (z == 0) {          // Q: fp16 2-term, scaled
                        uint32_t Hu, Lu;
                        packsplit_h(c0 * QSC2, c1 * QSC2, Hu, Lu);
                        *(uint32_t*)&g_qh[o] = Hu;
                        *(uint32_t*)&g_ql[o] = Lu;
                    } else if (z == 1) {   // K: fp16 SINGLE, scaled
                        __half2 hv = __floats2half2_rn(c0 * QSC2, c1 * QSC2);
                        *(uint32_t*)&g_kh[o] = *reinterpret_cast<uint32_t*>(&hv);
                    } else {               // V: fp16 2-term
                        uint32_t Hu, Lu;
                        packsplit_h(c0, c1, Hu, Lu);
                        *(uint32_t*)&g_vh[o] = Hu;
                        *(uint32_t*)&g_vl[o] = Lu;
                    }
                }
            }
        }
    }
}

// ------------------------- flash attention v8 (unchanged from R13) -----------
#define ASTR 72
#define KVTILE (64*ASTR)
#define QTILE (128*ASTR)
#define ATTN_SMEM ((2*QTILE + 6*KVTILE)*2)    // 92,160 B

__global__ void __launch_bounds__(256, 2) attn_bf()
{
    extern __shared__ __align__(16) char smraw[];
    __half* Qh = (__half*)smraw;
    __half* Ql = Qh + QTILE;
    __half* KV = Ql + QTILE;                   // [2 stages][K, Vh, Vl]

    const int t = threadIdx.x, lane = t & 31, w = t >> 5;
    const int qt = blockIdx.x, bh = blockIdx.y;
    const int mt = w * 16;

    const size_t qoff = ((size_t)bh*SEQ + qt*128)*HDIM;
    const size_t koff = (size_t)bh*SEQ*HDIM;

    const int laneA = (lane & 15) * ASTR + (lane >> 4) * 8;
    const int laneB = ((lane & 7) + ((lane >> 4) & 1) * 8) * ASTR + ((lane >> 3) & 1) * 8;
    const int laneV = (lane & 15) * ASTR + (lane >> 4) * 8;   // trans: rows=keys

    // Q load
    #pragma unroll
    for (int i = 0; i < 8; i++) {
        const int c = t + i * 256;
        const int tile = c >> 10, cc = c & 1023;
        const int r = cc >> 3, col = (cc & 7) * 8;
        cp16((tile ? Ql : Qh) + r*ASTR + col,
             (tile ? g_ql : g_qh) + qoff + r*HDIM + col);
    }
    CP_COMMIT();

    auto prefetch = [&](int kt, int st) {
        __half* base = KV + st * 3 * KVTILE;
        #pragma unroll
        for (int i = 0; i < 6; i++) {
            const int c = t + i * 256;
            const int tile = c >> 9, cc = c & 511;
            const int r = cc >> 3, col = (cc & 7) * 8;
            const __half* g = (tile == 0) ? g_kh : (tile == 1) ? g_vh : g_vl;
            cp16(base + tile*KVTILE + r*ASTR + col,
                 g + koff + (size_t)(kt*64 + r)*HDIM + col);
        }
        CP_COMMIT();
    };

    prefetch(0, 0);

    float m0 = -1e30f, m1 = -1e30f, l0 = 0.f, l1 = 0.f;
    float o[8][4];
    #pragma unroll
    for (int i = 0; i < 8; i++)
        #pragma unroll
        for (int j = 0; j < 4; j++) o[i][j] = 0.f;

    for (int kt = 0; kt < SEQ/64; kt++) {
        const int st = kt & 1;
        CP_WAIT(0);
        __syncthreads();
        if (kt + 1 < SEQ/64) prefetch(kt + 1, st ^ 1);

        const __half* Ks = KV + (st*3 + 0)*KVTILE;
        const __half* Vh = KV + (st*3 + 1)*KVTILE;
        const __half* Vl = KV + (st*3 + 2)*KVTILE;

        // ---- S[16 x 64] = (Qh+Ql) K^T  (log2 units) ----
        float sc[8][4];
        #pragma unroll
        for (int i = 0; i < 8; i++)
            #pragma unroll
            for (int j = 0; j < 4; j++) sc[i][j] = 0.f;

        #pragma unroll
        for (int ks4 = 0; ks4 < 4; ks4++) {
            uint32_t qh_[4], ql_[4];
            const int qo = mt*ASTR + ks4*16 + laneA;
            ldsm_x4(qh_[0], qh_[1], qh_[2], qh_[3], sm_addr(Qh + qo));
            ldsm_x4(ql_[0], ql_[1], ql_[2], ql_[3], sm_addr(Ql + qo));
            #pragma unroll
            for (int p = 0; p < 4; p++) {
                uint32_t kk[4];
                const int off = (p*16)*ASTR + ks4*16 + laneB;
                ldsm_x4(kk[0], kk[1], kk[2], kk[3], sm_addr(Ks + off));
                mma16h(sc[2*p],   qh_, kk[0], kk[1]);
                mma16h(sc[2*p],   ql_, kk[0], kk[1]);
                mma16h(sc[2*p+1], qh_, kk[2], kk[3]);
                mma16h(sc[2*p+1], ql_, kk[2], kk[3]);
            }
        }

        // ---- warp-local online softmax (base-2, fp16 P via h2exp2) ----
        float mx0 = sc[0][0], mx1 = sc[0][2];
        #pragma unroll
        for (int nt = 0; nt < 8; nt++) {
            mx0 = fmaxf(mx0, fmaxf(sc[nt][0], sc[nt][1]));
            mx1 = fmaxf(mx1, fmaxf(sc[nt][2], sc[nt][3]));
        }
        mx0 = fmaxf(mx0, __shfl_xor_sync(0xffffffffu, mx0, 1));
        mx0 = fmaxf(mx0, __shfl_xor_sync(0xffffffffu, mx0, 2));
        mx1 = fmaxf(mx1, __shfl_xor_sync(0xffffffffu, mx1, 1));
        mx1 = fmaxf(mx1, __shfl_xor_sync(0xffffffffu, mx1, 2));
        const float mn0 = fmaxf(m0, mx0), mn1 = fmaxf(m1, mx1);
        const float cr0 = ex2(m0 - mn0), cr1 = ex2(m1 - mn1);
        m0 = mn0; m1 = mn1;

        uint32_t pa[8], pb[8];
        float s0 = 0.f, s1 = 0.f;
        #pragma unroll
        for (int nt = 0; nt < 8; nt++) {
            __half2 e0 = h2exp2(__floats2half2_rn(sc[nt][0] - mn0, sc[nt][1] - mn0));
            __half2 e1 = h2exp2(__floats2half2_rn(sc[nt][2] - mn1, sc[nt][3] - mn1));
            pa[nt] = *reinterpret_cast<uint32_t*>(&e0);
            pb[nt] = *reinterpret_cast<uint32_t*>(&e1);
            float2 f0 = __half22float2(e0), f1 = __half22float2(e1);
            s0 += f0.x + f0.y;
            s1 += f1.x + f1.y;
        }
        s0 += __shfl_xor_sync(0xffffffffu, s0, 1);
        s0 += __shfl_xor_sync(0xffffffffu, s0, 2);
        s1 += __shfl_xor_sync(0xffffffffu, s1, 1);
        s1 += __shfl_xor_sync(0xffffffffu, s1, 2);
        l0 = l0*cr0 + s0;
        l1 = l1*cr1 + s1;

        #pragma unroll
        for (int nt = 0; nt < 8; nt++) {
            o[nt][0] *= cr0; o[nt][1] *= cr0;
            o[nt][2] *= cr1; o[nt][3] *= cr1;
        }

        // ---- O += P V (fp16: P exact, V 2-term) ----
        #pragma unroll
        for (int c = 0; c < 4; c++) {
            const uint32_t ph_[4] = { pa[2*c], pb[2*c], pa[2*c+1], pb[2*c+1] };
            #pragma unroll
            for (int p = 0; p < 4; p++) {
                uint32_t vh_[4], vl_[4];
                const int off = (c*16)*ASTR + p*16 + laneV;
                ldsm_x4_t(vh_[0], vh_[1], vh_[2], vh_[3], sm_addr(Vh + off));
                ldsm_x4_t(vl_[0], vl_[1], vl_[2], vl_[3], sm_addr(Vl + off));
                mma16h(o[2*p],   ph_, vh_[0], vh_[1]);
                mma16h(o[2*p],   ph_, vl_[0], vl_[1]);
                mma16h(o[2*p+1], ph_, vh_[2], vh_[3]);
                mma16h(o[2*p+1], ph_, vl_[2], vl_[3]);
            }
        }
    }

    // ---- normalize + write fp16-split [B,S,D] for the O GEMM ----
    const int b_ = bh / NHEAD, h_ = bh % NHEAD;
    const int r0 = mt + (lane >> 2);
    const float inv0 = 1.f / l0, inv1 = 1.f / l1;
    const size_t row0 = (size_t)b_*SEQ + qt*128 + r0;
    #pragma unroll
    for (int nt = 0; nt < 8; nt++) {
        const int cc = nt*8 + 2*(lane & 3);
        uint32_t Hu, Lu;
        packsplit_h(o[nt][0]*inv0, o[nt][1]*inv0, Hu, Lu);
        *(uint32_t*)&g_ah[row0*DMODEL + h_*HDIM + cc] = Hu;
        *(uint32_t*)&g_al[row0*DMODEL + h_*HDIM + cc] = Lu;
        packsplit_h(o[nt][2]*inv1, o[nt][3]*inv1, Hu, Lu);
        *(uint32_t*)&g_ah[(row0 + 8)*DMODEL + h_*HDIM + cc] = Hu;
        *(uint32_t*)&g_al[(row0 + 8)*DMODEL + h_*HDIM + cc] = Lu;
    }
}

// ---------------------------------------------------------------------------
extern "C" void kernel_launch(void* const* d_in, const int* in_sizes, int n_in,
                              void* d_out, int out_size)
{
    (void)in_sizes; (void)n_in; (void)out_size;
    const float* x  = (const float*)d_in[0];
    const float* Wq = (const float*)d_in[1];
    const float* bq = (const float*)d_in[2];
    const float* Wk = (const float*)d_in[3];
    const float* bk = (const float*)d_in[4];
    const float* Wv = (const float*)d_in[5];
    const float* bv = (const float*)d_in[6];
    const float* Wo = (const float*)d_in[7];
    const float* bo = (const float*)d_in[8];
    float* out = (float*)d_out;

    prep_x<<<(MROWS*DMODEL/4)/256, 256>>>(x);
    prep_wt<<<dim3(DMODEL/32, DMODEL/32, 4), 256>>>(Wq, Wk, Wv, Wo);

    cudaFuncSetAttribute(gemm_bf<0>, cudaFuncAttributeMaxDynamicSharedMemorySize, GEMM_SMEM);
    cudaFuncSetAttribute(gemm_bf<4>, cudaFuncAttributeMaxDynamicSharedMemorySize, GEMM_SMEM);
    cudaFuncSetAttribute(attn_bf, cudaFuncAttributeMaxDynamicSharedMemorySize, ATTN_SMEM);

    dim3 gq(MROWS/128, DMODEL/128, 3);   // fused QKV
    gemm_bf<0><<<gq, 256, GEMM_SMEM>>>(bq, bk, bv, nullptr);

    attn_bf<<<dim3(SEQ/128, BATCH*NHEAD), 256, ATTN_SMEM>>>();

    dim3 gg(MROWS/128, DMODEL/128);
    gemm_bf<4><<<gg, 256, GEMM_SMEM>>>(bo, nullptr, nullptr, out);
}